// round 6
// baseline (speedup 1.0000x reference)
#include <cuda_runtime.h>

// SAKE GNN fully fused, one CTA per graph (B=512, M=32, H=128, L=2).
// R6: column-split 16 warps (2 col-groups x 8 row/edge-groups): doubles
//     warps/SMSP for latency hiding at UNCHANGED smem W traffic.
//     Edge phase: warp pairs share a slice via 64-thread named barriers.

#define NB 512
#define NT 512
typedef unsigned long long u64;

// ---- shared memory layout (float offsets) ----
#define S_HG    0        // 32x128
#define S_MI    4096
#define S_MJ    8192
#define S_AGG   12288
#define S_W     16384    // 128x128 weight staging
#define S_M1    32768    // 8 pairs x 4 rows x 128 f32 = 4096
#define S_D2    36864    // 32x32
#define S_EDGE  37888    // 1024 ints
#define S_RMASK 38912
#define S_ROFF  38944
#define S_X     38976    // 96
#define S_HT    39072    // 32x16
#define S_RED   39584    // 16
#define S_NE    39600
#define SM_FLOATS 39608

__device__ __forceinline__ float silu_f(float v) {
    return __fdividef(v, 1.0f + __expf(-v));
}
__device__ __forceinline__ u64 pk2(float x) {
    u64 r; asm("mov.b64 %0, {%1, %1};" : "=l"(r) : "f"(x)); return r;
}
__device__ __forceinline__ void ffma2(u64& d, u64 a, u64 b) {
    asm("fma.rn.f32x2 %0, %1, %2, %0;" : "+l"(d) : "l"(a), "l"(b));
}
__device__ __forceinline__ float2 unpk(u64 v) {
    float2 f; asm("mov.b64 {%0, %1}, %2;" : "=f"(f.x), "=f"(f.y) : "l"(v)); return f;
}

__device__ __forceinline__ void cp16(unsigned saddr, const float* g) {
    asm volatile("cp.async.cg.shared.global [%0], [%1], 16;" :: "r"(saddr), "l"(g));
}
#define CP_COMMIT() asm volatile("cp.async.commit_group;")
#define CP_WAIT0()  asm volatile("cp.async.wait_group 0;" ::: "memory")
#define PAIR_BAR(id) asm volatile("bar.sync %0, 64;" :: "r"(id) : "memory")

__device__ __forceinline__ void stage_async(const float* __restrict__ g,
                                            float* s, int nf4) {
    unsigned sa = (unsigned)__cvta_generic_to_shared(s);
    for (int v = threadIdx.x; v < nf4; v += NT)
        cp16(sa + v * 16, g + v * 4);
}

// column-split GEMM: 4 rows, 2 cols/lane (cols k0, k0+1), nh=128.
// W read as LDS.64 (8B/lane), A rows as lane-uniform float4 broadcasts.
__device__ __forceinline__ void gemmC(const float* __restrict__ sX, int ldx,
                                      const float* __restrict__ sW,
                                      int i0, int k0, u64 acc[4]) {
    #pragma unroll 1
    for (int h = 0; h < 128; h += 4) {
        u64 w0 = *(const u64*)&sW[(h + 0) * 128 + k0];
        u64 w1 = *(const u64*)&sW[(h + 1) * 128 + k0];
        u64 w2 = *(const u64*)&sW[(h + 2) * 128 + k0];
        u64 w3 = *(const u64*)&sW[(h + 3) * 128 + k0];
        #pragma unroll
        for (int rr = 0; rr < 4; rr++) {
            float4 a = *(const float4*)&sX[(i0 + rr) * ldx + h];
            ffma2(acc[rr], pk2(a.x), w0);
            ffma2(acc[rr], pk2(a.y), w1);
            ffma2(acc[rr], pk2(a.z), w2);
            ffma2(acc[rr], pk2(a.w), w3);
        }
    }
}

// W_in GEMM (nh = 16, ldx = 16)
__device__ __forceinline__ void gemmC16(const float* __restrict__ sX,
                                        const float* __restrict__ sW,
                                        int i0, int k0, u64 acc[4]) {
    #pragma unroll
    for (int h = 0; h < 16; h += 4) {
        u64 w0 = *(const u64*)&sW[(h + 0) * 128 + k0];
        u64 w1 = *(const u64*)&sW[(h + 1) * 128 + k0];
        u64 w2 = *(const u64*)&sW[(h + 2) * 128 + k0];
        u64 w3 = *(const u64*)&sW[(h + 3) * 128 + k0];
        #pragma unroll
        for (int rr = 0; rr < 4; rr++) {
            float4 a = *(const float4*)&sX[(i0 + rr) * 16 + h];
            ffma2(acc[rr], pk2(a.x), w0);
            ffma2(acc[rr], pk2(a.y), w1);
            ffma2(acc[rr], pk2(a.z), w2);
            ffma2(acc[rr], pk2(a.w), w3);
        }
    }
}

__global__ void __launch_bounds__(NT, 1)
sake_kernel(const float* __restrict__ g_h, const float* __restrict__ g_x,
            const float* __restrict__ W_in, const float* __restrict__ b_in,
            const float* __restrict__ We1, const float* __restrict__ be1,
            const float* __restrict__ We2, const float* __restrict__ be2,
            const float* __restrict__ Wh1, const float* __restrict__ bh1,
            const float* __restrict__ Wh2, const float* __restrict__ bh2,
            const float* __restrict__ W_out, const float* __restrict__ b_out,
            const float* __restrict__ Wn1, const float* __restrict__ bn1,
            const float* __restrict__ Wn2, const float* __restrict__ bn2,
            float* __restrict__ g_out)
{
    extern __shared__ float sm[];
    float*    s_hg  = sm + S_HG;
    float*    s_mi  = sm + S_MI;
    float*    s_mj  = sm + S_MJ;
    float*    s_agg = sm + S_AGG;
    float*    s_W   = sm + S_W;
    float*    s_d2  = sm + S_D2;
    int*      s_edge  = (int*)(sm + S_EDGE);
    unsigned* s_rmask = (unsigned*)(sm + S_RMASK);
    int*      s_roff  = (int*)(sm + S_ROFF);
    float*    s_x   = sm + S_X;
    float*    s_ht  = sm + S_HT;
    float*    s_red = sm + S_RED;
    int*      s_ne  = (int*)(sm + S_NE);

    const int tid  = threadIdx.x;
    const int warp = tid >> 5;        // 0..15
    const int lane = tid & 31;
    const int cg   = warp >> 3;       // column group: 0 -> cols 0..63, 1 -> 64..127
    const int wi   = warp & 7;        // row / edge-slice group
    const int b    = blockIdx.x;
    const int i0   = wi * 4;          // row base (4 rows per warp)
    const int k0   = cg * 64 + lane * 2;  // 2 cols per lane (also h-half index)

    // ---- prologue: stage x, h, W_in ----
    {
        unsigned sx = (unsigned)__cvta_generic_to_shared(s_x);
        if (tid < 24) cp16(sx + tid * 16, g_x + b * 96 + tid * 4);
        unsigned sh = (unsigned)__cvta_generic_to_shared(s_ht);
        if (tid < 128) cp16(sh + tid * 16, g_h + b * 512 + tid * 4);
        stage_async(W_in, s_W, 512);
        CP_COMMIT(); CP_WAIT0();
    }
    __syncthreads();

    // ---- d2 ----
    for (int p = tid; p < 1024; p += NT) {
        int i = p >> 5, j = p & 31;
        float dx = s_x[i * 3 + 0] - s_x[j * 3 + 0];
        float dy = s_x[i * 3 + 1] - s_x[j * 3 + 1];
        float dz = s_x[i * 3 + 2] - s_x[j * 3 + 2];
        s_d2[p] = dx * dx + dy * dy + dz * dz;
    }
    __syncthreads();

    // ---- adjacency masks (warps 0..7) ----
    if (warp < 8) {
        #pragma unroll
        for (int rr = 0; rr < 4; rr++) {
            int i = i0 + rr;
            bool adj = (s_d2[i * 32 + lane] < 1.0f) && (lane != i);
            unsigned m = __ballot_sync(0xffffffffu, adj);
            if (lane == 0) s_rmask[i] = m;
        }
    }
    // ---- hg = h @ W_in + b_in ----
    {
        u64 acc[4] = {};
        gemmC16(s_ht, s_W, i0, k0, acc);
        float2 bb = *(const float2*)&b_in[k0];
        #pragma unroll
        for (int rr = 0; rr < 4; rr++) {
            float2 o = unpk(acc[rr]);
            o.x += bb.x; o.y += bb.y;
            *(float2*)&s_hg[(i0 + rr) * 128 + k0] = o;
        }
    }
    __syncthreads();

    // ---- edge-list scan (layer-invariant, sorted by i) ----
    if (warp == 0) {
        unsigned m = s_rmask[lane];
        int c = __popc(m);
        int inc = c;
        #pragma unroll
        for (int d = 1; d < 32; d <<= 1) {
            int n = __shfl_up_sync(0xffffffffu, inc, d);
            if (lane >= d) inc += n;
        }
        s_roff[lane] = inc - c;
        if (lane == 31) *s_ne = inc;
    }
    __syncthreads();
    if (warp < 8) {
        #pragma unroll
        for (int rr = 0; rr < 4; rr++) {
            int i = i0 + rr;
            unsigned m = s_rmask[i];
            if ((m >> lane) & 1u) {
                int pos = s_roff[i] + __popc(m & ((1u << lane) - 1u));
                s_edge[pos] = (i << 5) | lane;
            }
        }
    }
    __syncthreads();
    const int nE = *s_ne;
    const int nper = (nE + 7) >> 3;

    // ---- layers ----
    #pragma unroll 1
    for (int l = 0; l < 2; l++) {
        const float* We1l = We1 + l * (257 * 128);
        const float* We2l = We2 + l * 16384;
        const float* Wh1l = Wh1 + l * (256 * 128);
        const float* Wh2l = Wh2 + l * 16384;

        // mi = hg @ We1a + be1
        stage_async(We1l, s_W, 4096); CP_COMMIT(); CP_WAIT0();
        __syncthreads();
        {
            u64 acc[4] = {};
            gemmC(s_hg, 128, s_W, i0, k0, acc);
            float2 bb = *(const float2*)&be1[l * 128 + k0];
            #pragma unroll
            for (int rr = 0; rr < 4; rr++) {
                float2 o = unpk(acc[rr]);
                o.x += bb.x; o.y += bb.y;
                *(float2*)&s_mi[(i0 + rr) * 128 + k0] = o;
            }
        }
        __syncthreads();

        // mj = hg @ We1b
        stage_async(We1l + 16384, s_W, 4096); CP_COMMIT(); CP_WAIT0();
        __syncthreads();
        {
            u64 acc[4] = {};
            gemmC(s_hg, 128, s_W, i0, k0, acc);
            #pragma unroll
            for (int rr = 0; rr < 4; rr++)
                *(float2*)&s_mj[(i0 + rr) * 128 + k0] = unpk(acc[rr]);
        }
        __syncthreads();

        // stage We2; zero agg
        stage_async(We2l, s_W, 4096); CP_COMMIT();
        for (int v = tid; v < 4096; v += NT) s_agg[v] = 0.0f;
        CP_WAIT0();
        __syncthreads();

        // ---- pair phase: 8 edge slices, one warp-PAIR (wi, wi+8) each ----
        {
            const float2 wdv  = *(const float2*)&We1l[256 * 128 + k0]; // h-half
            const float2 be2v = *(const float2*)&be2[l * 128 + k0];    // col-half
            float* m1 = sm + S_M1 + wi * 512;   // 4 rows x 128, shared by pair
            const int barid = wi + 1;
            const int e_lo = min(wi * nper, nE);
            const int e_hi = min(e_lo + nper, nE);

            int   cur_i = -1;
            float a0 = 0.f, a1 = 0.f;

            for (int e0 = e_lo; e0 < e_hi; e0 += 4) {
                // build this warp's h-half of 4 rows of m1
                #pragma unroll
                for (int rr = 0; rr < 4; rr++) {
                    int e = e0 + rr;
                    int ij = s_edge[e < e_hi ? e : (e_hi - 1)];
                    int i = ij >> 5, j = ij & 31;
                    float dd = s_d2[ij];
                    float2 miv = *(const float2*)&s_mi[i * 128 + k0];
                    float2 mjv = *(const float2*)&s_mj[j * 128 + k0];
                    float2 v = { silu_f(miv.x + mjv.x + dd * wdv.x),
                                 silu_f(miv.y + mjv.y + dd * wdv.y) };
                    *(float2*)&m1[rr * 128 + k0] = v;
                }
                PAIR_BAR(barid);            // m1 complete (both halves)
                u64 y[4] = {};
                gemmC(m1, 128, s_W, 0, k0, y);
                PAIR_BAR(barid);            // gemm done before next overwrite

                #pragma unroll
                for (int rr = 0; rr < 4; rr++) {
                    int e = e0 + rr;
                    if (e < e_hi) {
                        int i = s_edge[e] >> 5;   // uniform across warp
                        float2 o = unpk(y[rr]);
                        float v0 = silu_f(o.x + be2v.x);
                        float v1 = silu_f(o.y + be2v.y);
                        if (i != cur_i) {
                            if (cur_i >= 0) {
                                atomicAdd(&s_agg[cur_i * 128 + k0 + 0], a0);
                                atomicAdd(&s_agg[cur_i * 128 + k0 + 1], a1);
                            }
                            cur_i = i;
                            a0 = v0; a1 = v1;
                        } else {
                            a0 += v0; a1 += v1;
                        }
                    }
                }
            }
            if (cur_i >= 0) {
                atomicAdd(&s_agg[cur_i * 128 + k0 + 0], a0);
                atomicAdd(&s_agg[cur_i * 128 + k0 + 1], a1);
            }
        }
        __syncthreads();

        // u = silu(hg @ Wh1a + agg @ Wh1b + bh1) -> s_mi
        stage_async(Wh1l, s_W, 4096); CP_COMMIT(); CP_WAIT0();
        __syncthreads();
        u64 acc[4] = {};
        gemmC(s_hg, 128, s_W, i0, k0, acc);
        __syncthreads();
        stage_async(Wh1l + 16384, s_W, 4096); CP_COMMIT(); CP_WAIT0();
        __syncthreads();
        gemmC(s_agg, 128, s_W, i0, k0, acc);
        {
            float2 bb = *(const float2*)&bh1[l * 128 + k0];
            #pragma unroll
            for (int rr = 0; rr < 4; rr++) {
                float2 o = unpk(acc[rr]);
                float2 u2 = { silu_f(o.x + bb.x), silu_f(o.y + bb.y) };
                *(float2*)&s_mi[(i0 + rr) * 128 + k0] = u2;
            }
        }
        __syncthreads();

        // hg += u @ Wh2 + bh2
        stage_async(Wh2l, s_W, 4096); CP_COMMIT(); CP_WAIT0();
        __syncthreads();
        {
            u64 acc2[4] = {};
            gemmC(s_mi, 128, s_W, i0, k0, acc2);
            float2 bb = *(const float2*)&bh2[l * 128 + k0];
            #pragma unroll
            for (int rr = 0; rr < 4; rr++) {
                float2 o = unpk(acc2[rr]);
                float2 cur = *(float2*)&s_hg[(i0 + rr) * 128 + k0];
                cur.x += o.x + bb.x; cur.y += o.y + bb.y;
                *(float2*)&s_hg[(i0 + rr) * 128 + k0] = cur;
            }
        }
        __syncthreads();
    }

    // ---- head: ho = hg @ W_out + b_out -> s_mj ----
    stage_async(W_out, s_W, 4096); CP_COMMIT(); CP_WAIT0();
    __syncthreads();
    {
        u64 acc[4] = {};
        gemmC(s_hg, 128, s_W, i0, k0, acc);
        float2 bb = *(const float2*)&b_out[k0];
        #pragma unroll
        for (int rr = 0; rr < 4; rr++) {
            float2 o = unpk(acc[rr]);
            o.x += bb.x; o.y += bb.y;
            *(float2*)&s_mj[(i0 + rr) * 128 + k0] = o;
        }
    }
    __syncthreads();

    // t1 = silu(ho @ Wn1 + bn1) -> s_mi
    stage_async(Wn1, s_W, 4096); CP_COMMIT(); CP_WAIT0();
    __syncthreads();
    {
        u64 acc[4] = {};
        gemmC(s_mj, 128, s_W, i0, k0, acc);
        float2 bb = *(const float2*)&bn1[k0];
        #pragma unroll
        for (int rr = 0; rr < 4; rr++) {
            float2 o = unpk(acc[rr]);
            float2 t = { silu_f(o.x + bb.x), silu_f(o.y + bb.y) };
            *(float2*)&s_mi[(i0 + rr) * 128 + k0] = t;
        }
    }
    __syncthreads();

    // ---- out[b] = (colsum t1) . Wn2 + 32*bn2 ----
    float part = 0.0f;
    if (tid < 128) {
        float s = 0.0f;
        #pragma unroll
        for (int i = 0; i < 32; i++) s += s_mi[i * 128 + tid];
        part = s * Wn2[tid];
    }
    #pragma unroll
    for (int off = 16; off > 0; off >>= 1)
        part += __shfl_down_sync(0xffffffffu, part, off);
    if (warp < 4 && lane == 0) s_red[warp] = part;
    __syncthreads();
    if (tid == 0)
        g_out[b] = s_red[0] + s_red[1] + s_red[2] + s_red[3] + 32.0f * bn2[0];
}

extern "C" void kernel_launch(void* const* d_in, const int* in_sizes, int n_in,
                              void* d_out, int out_size) {
    const float* g_h   = (const float*)d_in[0];
    const float* g_x   = (const float*)d_in[1];
    const float* W_in  = (const float*)d_in[3];
    const float* b_in  = (const float*)d_in[4];
    const float* We1   = (const float*)d_in[5];
    const float* be1   = (const float*)d_in[6];
    const float* We2   = (const float*)d_in[7];
    const float* be2   = (const float*)d_in[8];
    const float* Wh1   = (const float*)d_in[9];
    const float* bh1   = (const float*)d_in[10];
    const float* Wh2   = (const float*)d_in[11];
    const float* bh2   = (const float*)d_in[12];
    const float* W_out = (const float*)d_in[13];
    const float* b_out = (const float*)d_in[14];
    const float* Wn1   = (const float*)d_in[15];
    const float* bn1   = (const float*)d_in[16];
    const float* Wn2   = (const float*)d_in[17];
    const float* bn2   = (const float*)d_in[18];
    float* out = (float*)d_out;

    const int smem_bytes = SM_FLOATS * 4;
    cudaFuncSetAttribute(sake_kernel, cudaFuncAttributeMaxDynamicSharedMemorySize,
                         smem_bytes);
    sake_kernel<<<NB, NT, smem_bytes>>>(
        g_h, g_x, W_in, b_in, We1, be1, We2, be2, Wh1, bh1, Wh2, bh2,
        W_out, b_out, Wn1, bn1, Wn2, bn2, out);
}

// round 7
// speedup vs baseline: 1.1601x; 1.1601x over previous
#include <cuda_runtime.h>

// SAKE GNN fully fused, one CTA per graph (B=512, M=32, H=128, L=2).
// R7: all GEMMs on tensor cores via bf16 hi/lo split (3-term mma.m16n8k16,
//     fp32 accum -> ~fp32 accuracy). X intermediates stored as split bf16
//     pairs; W staged into per-lane fragment layout at copy time.

#define NB 512
#define NT 256
typedef unsigned int u32;

// ---- shared memory layout (u32 word offsets) ----
#define O_HGH 0        // each X pair array: 32 rows x 68 u32 (136 bf16, pad)
#define O_HGL 2176
#define O_MIH 4352
#define O_MIL 6528
#define O_MJH 8704
#define O_MJL 10880
#define O_AGH 13056
#define O_AGL 15232
#define O_M1H 17408
#define O_M1L 19584
#define O_HTH 21760    // h input pair: 32 x 8 u32
#define O_HTL 22016
#define O_WFH 22272    // W fragments hi: 8 kt x 16 nt x 32 lane x 2 = 8192
#define O_WFL 30464
#define O_M2  38656    // fp32 32 x 132
#define O_AGF 42880    // fp32 32 x 128
#define O_D2  46976    // fp32 32 x 32
#define O_EDGE 48000   // 1024 ints
#define O_WD  49024    // 128 f
#define O_BE2 49152    // 128 f
#define O_RMASK 49280
#define O_ROFF 49312
#define O_X   49344    // 96 f
#define O_RED 49440
#define O_NE  49456
#define SM_WORDS 49472

__device__ __forceinline__ float silu_f(float v) {
    return __fdividef(v, 1.0f + __expf(-v));
}

// pack two f32 -> bf16x2 (x0 in low half, x1 in high half)
__device__ __forceinline__ u32 packbf(float x0, float x1) {
    u32 r;
    asm("cvt.rn.bf16x2.f32 %0, %1, %2;" : "=r"(r) : "f"(x1), "f"(x0));
    return r;
}
// split (x0,x1) into hi/lo bf16x2 pair
__device__ __forceinline__ void split2(float x0, float x1, u32& h, u32& l) {
    h = packbf(x0, x1);
    float r0 = x0 - __uint_as_float(h << 16);
    float r1 = x1 - __uint_as_float(h & 0xffff0000u);
    l = packbf(r0, r1);
}
// reconstruct two f32 from a split pair at (row r, col-pair cpi), stride 68
__device__ __forceinline__ float2 ldpair(const u32* Xh, const u32* Xl, int r, int cpi) {
    u32 h = Xh[r * 68 + cpi], l = Xl[r * 68 + cpi];
    float2 v;
    v.x = __uint_as_float(h << 16) + __uint_as_float(l << 16);
    v.y = __uint_as_float(h & 0xffff0000u) + __uint_as_float(l & 0xffff0000u);
    return v;
}
__device__ __forceinline__ void stpair(u32* Xh, u32* Xl, int r, int cpi,
                                       float v0, float v1) {
    u32 h, l; split2(v0, v1, h, l);
    Xh[r * 68 + cpi] = h; Xl[r * 68 + cpi] = l;
}

__device__ __forceinline__ void mma4(float d[4], const u32 a[4], u32 b0, u32 b1) {
    asm volatile("mma.sync.aligned.m16n8k16.row.col.f32.bf16.bf16.f32 "
        "{%0,%1,%2,%3}, {%4,%5,%6,%7}, {%8,%9}, {%0,%1,%2,%3};"
        : "+f"(d[0]), "+f"(d[1]), "+f"(d[2]), "+f"(d[3])
        : "r"(a[0]), "r"(a[1]), "r"(a[2]), "r"(a[3]), "r"(b0), "r"(b1));
}

// A fragment (m16k16) from a split-X array with row stride rs (u32 units)
__device__ __forceinline__ void ldAf(const u32* X, int rs, int r0, int kt,
                                     int lane, u32 a[4]) {
    int gid = lane >> 2, tig = lane & 3;
    const u32* p = X + (r0 + gid) * rs + kt * 8 + tig;
    a[0] = p[0];
    a[2] = p[4];
    a[1] = p[8 * rs];
    a[3] = p[8 * rs + 4];
}

// full 3-term GEMM: D[4 ntiles][4] += Xpair(rows r0..r0+15) @ Wfrag
__device__ __forceinline__ void gemm_mma(const u32* Xh, const u32* Xl, int rs,
                                         const u32* Wfh, const u32* Wfl,
                                         int r0, int ntb, int lane, int nkt,
                                         float D[4][4]) {
    #pragma unroll 1
    for (int kt = 0; kt < nkt; kt++) {
        u32 ah[4], al[4];
        ldAf(Xh, rs, r0, kt, lane, ah);
        ldAf(Xl, rs, r0, kt, lane, al);
        #pragma unroll
        for (int t = 0; t < 4; t++) {
            int nt = ntb + t;
            const u32* bp = Wfh + ((kt * 16 + nt) * 32 + lane) * 2;
            const u32* bq = Wfl + ((kt * 16 + nt) * 32 + lane) * 2;
            u32 bh0 = bp[0], bh1 = bp[1];
            u32 bl0 = bq[0], bl1 = bq[1];
            mma4(D[t], ah, bh0, bh1);
            mma4(D[t], ah, bl0, bl1);
            mma4(D[t], al, bh0, bh1);
        }
    }
}

// stage W (nrows x 128 f32, row-major global) into hi/lo fragment layout
__device__ __forceinline__ void stage_frag(const float* __restrict__ gW, int nrows,
                                           u32* Wfh, u32* Wfl, int tid) {
    int nunits = (nrows >> 1) * 128;
    for (int u = tid; u < nunits; u += NT) {
        int c = u & 127, p = u >> 7;
        float w0 = gW[(2 * p) * 128 + c];
        float w1 = gW[(2 * p + 1) * 128 + c];
        int kt = p >> 3;
        int pr = p & 7;
        int cp = pr & 3;
        int reg = pr >> 2;
        int lane = (c & 7) * 4 + cp;
        int nt = c >> 3;
        int idx = ((kt * 16 + nt) * 32 + lane) * 2 + reg;
        u32 h, l; split2(w0, w1, h, l);
        Wfh[idx] = h; Wfl[idx] = l;
    }
}

__global__ void __launch_bounds__(NT, 1)
sake_kernel(const float* __restrict__ g_h, const float* __restrict__ g_x,
            const float* __restrict__ W_in, const float* __restrict__ b_in,
            const float* __restrict__ We1, const float* __restrict__ be1,
            const float* __restrict__ We2, const float* __restrict__ be2,
            const float* __restrict__ Wh1, const float* __restrict__ bh1,
            const float* __restrict__ Wh2, const float* __restrict__ bh2,
            const float* __restrict__ W_out, const float* __restrict__ b_out,
            const float* __restrict__ Wn1, const float* __restrict__ bn1,
            const float* __restrict__ Wn2, const float* __restrict__ bn2,
            float* __restrict__ g_out)
{
    extern __shared__ u32 smu[];
    u32* HGH = smu + O_HGH;  u32* HGL = smu + O_HGL;
    u32* MIH = smu + O_MIH;  u32* MIL = smu + O_MIL;
    u32* MJH = smu + O_MJH;  u32* MJL = smu + O_MJL;
    u32* AGH = smu + O_AGH;  u32* AGL = smu + O_AGL;
    u32* M1H = smu + O_M1H;  u32* M1L = smu + O_M1L;
    u32* HTH = smu + O_HTH;  u32* HTL = smu + O_HTL;
    u32* WFH = smu + O_WFH;  u32* WFL = smu + O_WFL;
    float* s_m2   = (float*)(smu + O_M2);
    float* s_aggF = (float*)(smu + O_AGF);
    float* s_d2   = (float*)(smu + O_D2);
    int*   s_edge = (int*)(smu + O_EDGE);
    float* s_wd   = (float*)(smu + O_WD);
    float* s_be2  = (float*)(smu + O_BE2);
    u32*   s_rmask = smu + O_RMASK;
    int*   s_roff  = (int*)(smu + O_ROFF);
    float* s_x    = (float*)(smu + O_X);
    float* s_red  = (float*)(smu + O_RED);
    int*   s_ne   = (int*)(smu + O_NE);

    const int tid  = threadIdx.x;
    const int warp = tid >> 5;          // 0..7
    const int lane = tid & 31;
    const int gid  = lane >> 2;
    const int tig  = lane & 3;
    const int b    = blockIdx.x;
    const int rt   = warp & 1;          // row tile (16 rows)
    const int ntb  = (warp >> 1) * 4;   // 4 n-tiles of 8 cols
    const int i0   = warp * 4;          // adjacency rows

    // ---- prologue: x, split h, W_in frags ----
    if (tid < 96) s_x[tid] = g_x[b * 96 + tid];
    {
        int r = tid >> 3, cp = tid & 7;
        float2 hv = *(const float2*)&g_h[b * 512 + r * 16 + cp * 2];
        u32 h, l; split2(hv.x, hv.y, h, l);
        HTH[r * 8 + cp] = h; HTL[r * 8 + cp] = l;
    }
    stage_frag(W_in, 16, WFH, WFL, tid);
    __syncthreads();

    // ---- d2 ----
    for (int p = tid; p < 1024; p += NT) {
        int i = p >> 5, j = p & 31;
        float dx = s_x[i * 3 + 0] - s_x[j * 3 + 0];
        float dy = s_x[i * 3 + 1] - s_x[j * 3 + 1];
        float dz = s_x[i * 3 + 2] - s_x[j * 3 + 2];
        s_d2[p] = dx * dx + dy * dy + dz * dz;
    }
    __syncthreads();

    // ---- adjacency masks ----
    #pragma unroll
    for (int rr = 0; rr < 4; rr++) {
        int i = i0 + rr;
        bool adj = (s_d2[i * 32 + lane] < 1.0f) && (lane != i);
        unsigned m = __ballot_sync(0xffffffffu, adj);
        if (lane == 0) s_rmask[i] = m;
    }

    // ---- hg = h @ W_in + b_in ----
    {
        float D[4][4] = {};
        gemm_mma(HTH, HTL, 8, WFH, WFL, rt * 16, ntb, lane, 1, D);
        #pragma unroll
        for (int t = 0; t < 4; t++) {
            int c0 = (ntb + t) * 8 + 2 * tig;
            float b0 = b_in[c0], b1 = b_in[c0 + 1];
            int cpi = c0 >> 1;
            stpair(HGH, HGL, rt * 16 + gid,     cpi, D[t][0] + b0, D[t][1] + b1);
            stpair(HGH, HGL, rt * 16 + gid + 8, cpi, D[t][2] + b0, D[t][3] + b1);
        }
    }
    __syncthreads();

    // ---- edge-list scan (layer-invariant, sorted by i) ----
    if (warp == 0) {
        unsigned m = s_rmask[lane];
        int c = __popc(m);
        int inc = c;
        #pragma unroll
        for (int d = 1; d < 32; d <<= 1) {
            int n = __shfl_up_sync(0xffffffffu, inc, d);
            if (lane >= d) inc += n;
        }
        s_roff[lane] = inc - c;
        if (lane == 31) *s_ne = inc;
    }
    __syncthreads();
    #pragma unroll
    for (int rr = 0; rr < 4; rr++) {
        int i = i0 + rr;
        unsigned m = s_rmask[i];
        if ((m >> lane) & 1u) {
            int pos = s_roff[i] + __popc(m & ((1u << lane) - 1u));
            s_edge[pos] = (i << 5) | lane;
        }
    }
    __syncthreads();
    const int nE = *s_ne;

    // ---- layers ----
    #pragma unroll 1
    for (int l = 0; l < 2; l++) {
        const float* We1l = We1 + l * (257 * 128);
        const float* We2l = We2 + l * 16384;
        const float* Wh1l = Wh1 + l * (256 * 128);
        const float* Wh2l = Wh2 + l * 16384;

        // mi = hg @ We1a + be1
        stage_frag(We1l, 128, WFH, WFL, tid);
        __syncthreads();
        {
            float D[4][4] = {};
            gemm_mma(HGH, HGL, 68, WFH, WFL, rt * 16, ntb, lane, 8, D);
            #pragma unroll
            for (int t = 0; t < 4; t++) {
                int c0 = (ntb + t) * 8 + 2 * tig;
                float b0 = be1[l * 128 + c0], b1 = be1[l * 128 + c0 + 1];
                int cpi = c0 >> 1;
                stpair(MIH, MIL, rt * 16 + gid,     cpi, D[t][0] + b0, D[t][1] + b1);
                stpair(MIH, MIL, rt * 16 + gid + 8, cpi, D[t][2] + b0, D[t][3] + b1);
            }
        }
        __syncthreads();

        // mj = hg @ We1b
        stage_frag(We1l + 16384, 128, WFH, WFL, tid);
        __syncthreads();
        {
            float D[4][4] = {};
            gemm_mma(HGH, HGL, 68, WFH, WFL, rt * 16, ntb, lane, 8, D);
            #pragma unroll
            for (int t = 0; t < 4; t++) {
                int cpi = ((ntb + t) * 8 + 2 * tig) >> 1;
                stpair(MJH, MJL, rt * 16 + gid,     cpi, D[t][0], D[t][1]);
                stpair(MJH, MJL, rt * 16 + gid + 8, cpi, D[t][2], D[t][3]);
            }
        }
        __syncthreads();

        // stage We2 frags; wd, be2; zero agg
        stage_frag(We2l, 128, WFH, WFL, tid);
        if (tid < 128) {
            s_wd[tid]  = We1l[256 * 128 + tid];
            s_be2[tid] = be2[l * 128 + tid];
        }
        for (int v = tid; v < 4096; v += NT) s_aggF[v] = 0.0f;
        __syncthreads();

        // ---- pair phase: CTA-wide 32-edge chunks ----
        for (int e0 = 0; e0 < nE; e0 += 32) {
            // build m1 (split): thread -> (edge row, 16-col group)
            {
                int e = tid >> 3, cg8 = tid & 7;
                int ee = e0 + e;
                int ij = s_edge[ee < nE ? ee : nE - 1];
                int i = ij >> 5, j = ij & 31;
                float dd = s_d2[ij];
                int cp0 = cg8 * 8;
                #pragma unroll
                for (int cp = 0; cp < 8; cp++) {
                    int cpi = cp0 + cp;
                    float2 miv = ldpair(MIH, MIL, i, cpi);
                    float2 mjv = ldpair(MJH, MJL, j, cpi);
                    int c = cpi * 2;
                    float v0 = silu_f(miv.x + mjv.x + dd * s_wd[c]);
                    float v1 = silu_f(miv.y + mjv.y + dd * s_wd[c + 1]);
                    stpair(M1H, M1L, e, cpi, v0, v1);
                }
            }
            __syncthreads();
            // GEMM + silu epilogue -> m2 (fp32)
            {
                float D[4][4] = {};
                gemm_mma(M1H, M1L, 68, WFH, WFL, rt * 16, ntb, lane, 8, D);
                #pragma unroll
                for (int t = 0; t < 4; t++) {
                    int c0 = (ntb + t) * 8 + 2 * tig;
                    float b0 = s_be2[c0], b1 = s_be2[c0 + 1];
                    int r0 = rt * 16 + gid;
                    float2 y0 = { silu_f(D[t][0] + b0), silu_f(D[t][1] + b1) };
                    float2 y1 = { silu_f(D[t][2] + b0), silu_f(D[t][3] + b1) };
                    *(float2*)&s_m2[r0 * 132 + c0]       = y0;
                    *(float2*)&s_m2[(r0 + 8) * 132 + c0] = y1;
                }
            }
            __syncthreads();
            // segmented column sweep -> aggF (no atomics)
            if (tid < 128) {
                int c = tid;
                float run = 0.0f; int curi = -1;
                int lim = nE - e0; if (lim > 32) lim = 32;
                for (int r = 0; r < lim; r++) {
                    int i = s_edge[e0 + r] >> 5;
                    if (i != curi) {
                        if (curi >= 0) s_aggF[curi * 128 + c] += run;
                        curi = i; run = 0.0f;
                    }
                    run += s_m2[r * 132 + c];
                }
                if (curi >= 0) s_aggF[curi * 128 + c] += run;
            }
            __syncthreads();
        }

        // split aggF -> AG pair; stage Wh1a
        for (int u = tid; u < 2048; u += NT) {
            int r = u >> 6, cpi = u & 63;
            float v0 = s_aggF[r * 128 + cpi * 2];
            float v1 = s_aggF[r * 128 + cpi * 2 + 1];
            u32 h, l2; split2(v0, v1, h, l2);
            AGH[r * 68 + cpi] = h; AGL[r * 68 + cpi] = l2;
        }
        stage_frag(Wh1l, 128, WFH, WFL, tid);
        __syncthreads();

        // u = silu(hg @ Wh1a + agg @ Wh1b + bh1) -> MI
        {
            float D[4][4] = {};
            gemm_mma(HGH, HGL, 68, WFH, WFL, rt * 16, ntb, lane, 8, D);
            __syncthreads();
            stage_frag(Wh1l + 16384, 128, WFH, WFL, tid);
            __syncthreads();
            gemm_mma(AGH, AGL, 68, WFH, WFL, rt * 16, ntb, lane, 8, D);
            #pragma unroll
            for (int t = 0; t < 4; t++) {
                int c0 = (ntb + t) * 8 + 2 * tig;
                float b0 = bh1[l * 128 + c0], b1 = bh1[l * 128 + c0 + 1];
                int cpi = c0 >> 1;
                stpair(MIH, MIL, rt * 16 + gid, cpi,
                       silu_f(D[t][0] + b0), silu_f(D[t][1] + b1));
                stpair(MIH, MIL, rt * 16 + gid + 8, cpi,
                       silu_f(D[t][2] + b0), silu_f(D[t][3] + b1));
            }
        }
        __syncthreads();

        // hg += u @ Wh2 + bh2
        stage_frag(Wh2l, 128, WFH, WFL, tid);
        __syncthreads();
        {
            float D[4][4] = {};
            gemm_mma(MIH, MIL, 68, WFH, WFL, rt * 16, ntb, lane, 8, D);
            #pragma unroll
            for (int t = 0; t < 4; t++) {
                int c0 = (ntb + t) * 8 + 2 * tig;
                float b0 = bh2[l * 128 + c0], b1 = bh2[l * 128 + c0 + 1];
                int cpi = c0 >> 1;
                int r0 = rt * 16 + gid;
                float2 h0 = ldpair(HGH, HGL, r0, cpi);
                stpair(HGH, HGL, r0, cpi, h0.x + D[t][0] + b0, h0.y + D[t][1] + b1);
                float2 h1 = ldpair(HGH, HGL, r0 + 8, cpi);
                stpair(HGH, HGL, r0 + 8, cpi, h1.x + D[t][2] + b0, h1.y + D[t][3] + b1);
            }
        }
        __syncthreads();
    }

    // ---- head: ho = hg @ W_out + b_out -> MJ ----
    stage_frag(W_out, 128, WFH, WFL, tid);
    __syncthreads();
    {
        float D[4][4] = {};
        gemm_mma(HGH, HGL, 68, WFH, WFL, rt * 16, ntb, lane, 8, D);
        #pragma unroll
        for (int t = 0; t < 4; t++) {
            int c0 = (ntb + t) * 8 + 2 * tig;
            float b0 = b_out[c0], b1 = b_out[c0 + 1];
            int cpi = c0 >> 1;
            stpair(MJH, MJL, rt * 16 + gid,     cpi, D[t][0] + b0, D[t][1] + b1);
            stpair(MJH, MJL, rt * 16 + gid + 8, cpi, D[t][2] + b0, D[t][3] + b1);
        }
    }
    __syncthreads();

    // t1 = silu(ho @ Wn1 + bn1) -> MI
    stage_frag(Wn1, 128, WFH, WFL, tid);
    __syncthreads();
    {
        float D[4][4] = {};
        gemm_mma(MJH, MJL, 68, WFH, WFL, rt * 16, ntb, lane, 8, D);
        #pragma unroll
        for (int t = 0; t < 4; t++) {
            int c0 = (ntb + t) * 8 + 2 * tig;
            float b0 = bn1[c0], b1 = bn1[c0 + 1];
            int cpi = c0 >> 1;
            stpair(MIH, MIL, rt * 16 + gid, cpi,
                   silu_f(D[t][0] + b0), silu_f(D[t][1] + b1));
            stpair(MIH, MIL, rt * 16 + gid + 8, cpi,
                   silu_f(D[t][2] + b0), silu_f(D[t][3] + b1));
        }
    }
    __syncthreads();

    // ---- out[b] = (colsum t1) . Wn2 + 32*bn2 ----
    float part = 0.0f;
    if (tid < 128) {
        int c = tid, cpi = c >> 1;
        float s = 0.0f;
        #pragma unroll 1
        for (int i = 0; i < 32; i++) {
            u32 h = MIH[i * 68 + cpi], l2 = MIL[i * 68 + cpi];
            float v = (c & 1)
                ? (__uint_as_float(h & 0xffff0000u) + __uint_as_float(l2 & 0xffff0000u))
                : (__uint_as_float(h << 16) + __uint_as_float(l2 << 16));
            s += v;
        }
        part = s * Wn2[c];
    }
    #pragma unroll
    for (int off = 16; off > 0; off >>= 1)
        part += __shfl_down_sync(0xffffffffu, part, off);
    if (warp < 4 && lane == 0) s_red[warp] = part;
    __syncthreads();
    if (tid == 0)
        g_out[b] = s_red[0] + s_red[1] + s_red[2] + s_red[3] + 32.0f * bn2[0];
}

extern "C" void kernel_launch(void* const* d_in, const int* in_sizes, int n_in,
                              void* d_out, int out_size) {
    const float* g_h   = (const float*)d_in[0];
    const float* g_x   = (const float*)d_in[1];
    const float* W_in  = (const float*)d_in[3];
    const float* b_in  = (const float*)d_in[4];
    const float* We1   = (const float*)d_in[5];
    const float* be1   = (const float*)d_in[6];
    const float* We2   = (const float*)d_in[7];
    const float* be2   = (const float*)d_in[8];
    const float* Wh1   = (const float*)d_in[9];
    const float* bh1   = (const float*)d_in[10];
    const float* Wh2   = (const float*)d_in[11];
    const float* bh2   = (const float*)d_in[12];
    const float* W_out = (const float*)d_in[13];
    const float* b_out = (const float*)d_in[14];
    const float* Wn1   = (const float*)d_in[15];
    const float* bn1   = (const float*)d_in[16];
    const float* Wn2   = (const float*)d_in[17];
    const float* bn2   = (const float*)d_in[18];
    float* out = (float*)d_out;

    const int smem_bytes = SM_WORDS * 4;
    cudaFuncSetAttribute(sake_kernel, cudaFuncAttributeMaxDynamicSharedMemorySize,
                         smem_bytes);
    sake_kernel<<<NB, NT, smem_bytes>>>(
        g_h, g_x, W_in, b_in, We1, be1, We2, be2, Wh1, bh1, Wh2, bh2,
        W_out, b_out, Wn1, bn1, Wn2, bn2, out);
}

// round 8
// speedup vs baseline: 1.6462x; 1.4189x over previous
#include <cuda_runtime.h>

// SAKE GNN fully fused, one CTA per graph (B=512, M=32, H=128, L=2).
// R8: weights pre-converted once to bf16 hi/lo MMA-fragment layout in global
//     (prep kernel); CTA staging is pure cp.async memcpy. mi/mj kept in f32
//     (not split) since they never feed an MMA. u/ho reuse M1 split buffers.

#define NB 512
#define NT 256
typedef unsigned int u32;

// global fragment buffer: 14 big Ws (16384 u32 each) + W_in (2048)
__device__ u32 g_wfrag[14 * 16384 + 2048];
#define WIN_BASE (14 * 16384)

// ---- shared memory layout (u32 word offsets) ----
#define O_HGH 0        // hg split: 32 x 68
#define O_HGL 2176
#define O_MIF 4352     // mi f32: 32 x 132
#define O_MJF 8576     // mj f32: 32 x 132
#define O_AGH 12800    // agg split: 32 x 68
#define O_AGL 14976
#define O_M1H 17152    // m1 / u / ho split: 32 x 68
#define O_M1L 19328
#define O_HTH 21504    // h input split: 32 x 8
#define O_HTL 21760
#define O_WF  22016    // W fragments: hi 8192 + lo 8192
#define O_M2  38400    // f32 32 x 132
#define O_AGF 42624    // f32 32 x 128
#define O_D2  46720
#define O_EDGE 47744
#define O_WD  48768
#define O_BE2 48896
#define O_RMASK 49024
#define O_ROFF 49056
#define O_X   49088
#define O_RED 49184
#define O_NE  49200
#define SM_WORDS 49208

__device__ __forceinline__ float silu_f(float v) {
    return __fdividef(v, 1.0f + __expf(-v));
}
__device__ __forceinline__ u32 packbf(float x0, float x1) {
    u32 r;
    asm("cvt.rn.bf16x2.f32 %0, %1, %2;" : "=r"(r) : "f"(x1), "f"(x0));
    return r;
}
__device__ __forceinline__ void split2(float x0, float x1, u32& h, u32& l) {
    h = packbf(x0, x1);
    float r0 = x0 - __uint_as_float(h << 16);
    float r1 = x1 - __uint_as_float(h & 0xffff0000u);
    l = packbf(r0, r1);
}
__device__ __forceinline__ float2 ldpair(const u32* Xh, const u32* Xl, int idx) {
    u32 h = Xh[idx], l = Xl[idx];
    float2 v;
    v.x = __uint_as_float(h << 16) + __uint_as_float(l << 16);
    v.y = __uint_as_float(h & 0xffff0000u) + __uint_as_float(l & 0xffff0000u);
    return v;
}
__device__ __forceinline__ void stpair(u32* Xh, u32* Xl, int idx, float v0, float v1) {
    u32 h, l; split2(v0, v1, h, l);
    Xh[idx] = h; Xl[idx] = l;
}

__device__ __forceinline__ void mma4(float d[4], const u32 a[4], u32 b0, u32 b1) {
    asm volatile("mma.sync.aligned.m16n8k16.row.col.f32.bf16.bf16.f32 "
        "{%0,%1,%2,%3}, {%4,%5,%6,%7}, {%8,%9}, {%0,%1,%2,%3};"
        : "+f"(d[0]), "+f"(d[1]), "+f"(d[2]), "+f"(d[3])
        : "r"(a[0]), "r"(a[1]), "r"(a[2]), "r"(a[3]), "r"(b0), "r"(b1));
}

__device__ __forceinline__ void ldAf(const u32* X, int rs, int r0, int kt,
                                     int lane, u32 a[4]) {
    int gid = lane >> 2, tig = lane & 3;
    const u32* p = X + (r0 + gid) * rs + kt * 8 + tig;
    a[0] = p[0];
    a[2] = p[4];
    a[1] = p[8 * rs];
    a[3] = p[8 * rs + 4];
}

// 3-term GEMM over kt range [kt0, kt1) reading W frags from sWF
__device__ __forceinline__ void gemm_mma(const u32* Xh, const u32* Xl, int rs,
                                         const u32* sWF, int r0, int ntb,
                                         int lane, int kt0, int kt1,
                                         float D[4][4]) {
    #pragma unroll 1
    for (int kt = kt0; kt < kt1; kt++) {
        u32 ah[4], al[4];
        ldAf(Xh, rs, r0, kt, lane, ah);
        ldAf(Xl, rs, r0, kt, lane, al);
        #pragma unroll
        for (int t = 0; t < 4; t++) {
            const u32* bp = sWF + ((kt * 16 + ntb + t) * 32 + lane) * 2;
            u32 bh0 = bp[0], bh1 = bp[1];
            u32 bl0 = bp[8192], bl1 = bp[8193];
            mma4(D[t], ah, bh0, bh1);
            mma4(D[t], ah, bl0, bl1);
            mma4(D[t], al, bh0, bh1);
        }
    }
}

__device__ __forceinline__ void cp16(unsigned saddr, const void* g) {
    asm volatile("cp.async.cg.shared.global [%0], [%1], 16;" :: "r"(saddr), "l"(g));
}
#define CP_COMMIT() asm volatile("cp.async.commit_group;")
#define CP_WAIT0()  asm volatile("cp.async.wait_group 0;" ::: "memory")

// copy nf4 16-byte units global->shared
__device__ __forceinline__ void stage_cp(const u32* __restrict__ g, u32* s,
                                         int nf4, int tid) {
    unsigned sa = (unsigned)__cvta_generic_to_shared(s);
    for (int v = tid; v < nf4; v += NT)
        cp16(sa + v * 16, g + v * 4);
}

// ================= prep kernel: weights -> fragment hi/lo layout =============
__global__ void prep_kernel(const float* __restrict__ We1,
                            const float* __restrict__ We2,
                            const float* __restrict__ Wh1,
                            const float* __restrict__ Wh2,
                            const float* __restrict__ W_out,
                            const float* __restrict__ Wn1,
                            const float* __restrict__ W_in) {
    int y = blockIdx.y;
    int u = blockIdx.x * 256 + threadIdx.x;
    if (y < 14) {
        const float* src;
        if (y < 12) {
            int l = y / 6, w = y % 6;
            switch (w) {
                case 0: src = We1 + l * 257 * 128; break;
                case 1: src = We1 + l * 257 * 128 + 16384; break;
                case 2: src = We2 + l * 16384; break;
                case 3: src = Wh1 + l * 32768; break;
                case 4: src = Wh1 + l * 32768 + 16384; break;
                default: src = Wh2 + l * 16384; break;
            }
        } else {
            src = (y == 12) ? W_out : Wn1;
        }
        int p = u >> 7, c = u & 127;
        float w0 = src[(2 * p) * 128 + c];
        float w1 = src[(2 * p + 1) * 128 + c];
        int kt = p >> 3, pr = p & 7;
        int cpp = pr & 3, reg = pr >> 2;
        int lane = (c & 7) * 4 + cpp;
        int nt = c >> 3;
        int dst = y * 16384 + ((kt * 16 + nt) * 32 + lane) * 2 + reg;
        u32 h, l2; split2(w0, w1, h, l2);
        g_wfrag[dst] = h;
        g_wfrag[dst + 8192] = l2;
    } else {
        if (u >= 1024) return;
        int p = u >> 7, c = u & 127;
        float w0 = W_in[(2 * p) * 128 + c];
        float w1 = W_in[(2 * p + 1) * 128 + c];
        int cpp = p & 3, reg = p >> 2;
        int lane = (c & 7) * 4 + cpp;
        int nt = c >> 3;
        int dst = WIN_BASE + ((nt * 32 + lane) * 2 + reg);
        u32 h, l2; split2(w0, w1, h, l2);
        g_wfrag[dst] = h;
        g_wfrag[dst + 1024] = l2;
    }
}

// ================================ main kernel ================================
__global__ void __launch_bounds__(NT, 1)
sake_kernel(const float* __restrict__ g_h, const float* __restrict__ g_x,
            const float* __restrict__ b_in,
            const float* __restrict__ We1, const float* __restrict__ be1,
            const float* __restrict__ be2,
            const float* __restrict__ bh1, const float* __restrict__ bh2,
            const float* __restrict__ b_out,
            const float* __restrict__ bn1,
            const float* __restrict__ Wn2, const float* __restrict__ bn2,
            float* __restrict__ g_out)
{
    extern __shared__ u32 smu[];
    u32* HGH = smu + O_HGH;  u32* HGL = smu + O_HGL;
    float* miF = (float*)(smu + O_MIF);
    float* mjF = (float*)(smu + O_MJF);
    u32* AGH = smu + O_AGH;  u32* AGL = smu + O_AGL;
    u32* M1H = smu + O_M1H;  u32* M1L = smu + O_M1L;
    u32* HTH = smu + O_HTH;  u32* HTL = smu + O_HTL;
    u32* WF  = smu + O_WF;
    float* s_m2   = (float*)(smu + O_M2);
    float* s_aggF = (float*)(smu + O_AGF);
    float* s_d2   = (float*)(smu + O_D2);
    int*   s_edge = (int*)(smu + O_EDGE);
    float* s_wd   = (float*)(smu + O_WD);
    float* s_be2  = (float*)(smu + O_BE2);
    u32*   s_rmask = smu + O_RMASK;
    int*   s_roff  = (int*)(smu + O_ROFF);
    float* s_x    = (float*)(smu + O_X);
    float* s_red  = (float*)(smu + O_RED);
    int*   s_ne   = (int*)(smu + O_NE);

    const int tid  = threadIdx.x;
    const int warp = tid >> 5;
    const int lane = tid & 31;
    const int gid  = lane >> 2;
    const int tig  = lane & 3;
    const int b    = blockIdx.x;
    const int rt   = warp & 1;
    const int ntb  = (warp >> 1) * 4;
    const int i0   = warp * 4;

    // ---- prologue: x, split h, stage W_in frags (pure memcpy) ----
    if (tid < 96) s_x[tid] = g_x[b * 96 + tid];
    {
        int r = tid >> 3, cp = tid & 7;
        float2 hv = *(const float2*)&g_h[b * 512 + r * 16 + cp * 2];
        u32 h, l; split2(hv.x, hv.y, h, l);
        HTH[r * 8 + cp] = h; HTL[r * 8 + cp] = l;
    }
    stage_cp(g_wfrag + WIN_BASE, WF, 256, tid);              // hi
    stage_cp(g_wfrag + WIN_BASE + 1024, WF + 8192, 256, tid); // lo
    CP_COMMIT();
    __syncthreads();

    // ---- d2 ----
    for (int p = tid; p < 1024; p += NT) {
        int i = p >> 5, j = p & 31;
        float dx = s_x[i * 3 + 0] - s_x[j * 3 + 0];
        float dy = s_x[i * 3 + 1] - s_x[j * 3 + 1];
        float dz = s_x[i * 3 + 2] - s_x[j * 3 + 2];
        s_d2[p] = dx * dx + dy * dy + dz * dz;
    }
    __syncthreads();

    // ---- adjacency masks ----
    #pragma unroll
    for (int rr = 0; rr < 4; rr++) {
        int i = i0 + rr;
        bool adj = (s_d2[i * 32 + lane] < 1.0f) && (lane != i);
        unsigned m = __ballot_sync(0xffffffffu, adj);
        if (lane == 0) s_rmask[i] = m;
    }
    CP_WAIT0();
    __syncthreads();

    // ---- hg = h @ W_in + b_in (kt 0 only; lo frags at +1024 staged to +8192)
    {
        float D[4][4] = {};
        gemm_mma(HTH, HTL, 8, WF, rt * 16, ntb, lane, 0, 1, D);
        #pragma unroll
        for (int t = 0; t < 4; t++) {
            int c0 = (ntb + t) * 8 + 2 * tig;
            float b0 = b_in[c0], b1 = b_in[c0 + 1];
            int cpi = c0 >> 1;
            stpair(HGH, HGL, (rt * 16 + gid) * 68 + cpi,     D[t][0] + b0, D[t][1] + b1);
            stpair(HGH, HGL, (rt * 16 + gid + 8) * 68 + cpi, D[t][2] + b0, D[t][3] + b1);
        }
    }

    // ---- edge-list scan ----
    __syncthreads();
    if (warp == 0) {
        unsigned m = s_rmask[lane];
        int c = __popc(m);
        int inc = c;
        #pragma unroll
        for (int d = 1; d < 32; d <<= 1) {
            int n = __shfl_up_sync(0xffffffffu, inc, d);
            if (lane >= d) inc += n;
        }
        s_roff[lane] = inc - c;
        if (lane == 31) *s_ne = inc;
    }
    __syncthreads();
    #pragma unroll
    for (int rr = 0; rr < 4; rr++) {
        int i = i0 + rr;
        unsigned m = s_rmask[i];
        if ((m >> lane) & 1u) {
            int pos = s_roff[i] + __popc(m & ((1u << lane) - 1u));
            s_edge[pos] = (i << 5) | lane;
        }
    }
    __syncthreads();
    const int nE = *s_ne;

    // ---- layers ----
    #pragma unroll 1
    for (int l = 0; l < 2; l++) {
        const u32* F_e1a = g_wfrag + (l * 6 + 0) * 16384;
        const u32* F_e1b = g_wfrag + (l * 6 + 1) * 16384;
        const u32* F_e2  = g_wfrag + (l * 6 + 2) * 16384;
        const u32* F_h1a = g_wfrag + (l * 6 + 3) * 16384;
        const u32* F_h1b = g_wfrag + (l * 6 + 4) * 16384;
        const u32* F_h2  = g_wfrag + (l * 6 + 5) * 16384;
        const float* We1l = We1 + l * (257 * 128);

        // mi = hg @ We1a + be1 -> miF (f32)
        stage_cp(F_e1a, WF, 4096, tid); CP_COMMIT(); CP_WAIT0();
        __syncthreads();
        {
            float D[4][4] = {};
            gemm_mma(HGH, HGL, 68, WF, rt * 16, ntb, lane, 0, 8, D);
            #pragma unroll
            for (int t = 0; t < 4; t++) {
                int c0 = (ntb + t) * 8 + 2 * tig;
                float b0 = be1[l * 128 + c0], b1 = be1[l * 128 + c0 + 1];
                int r0 = rt * 16 + gid;
                *(float2*)&miF[r0 * 132 + c0]       = make_float2(D[t][0] + b0, D[t][1] + b1);
                *(float2*)&miF[(r0 + 8) * 132 + c0] = make_float2(D[t][2] + b0, D[t][3] + b1);
            }
        }
        __syncthreads();

        // mj = hg @ We1b -> mjF (f32)
        stage_cp(F_e1b, WF, 4096, tid); CP_COMMIT(); CP_WAIT0();
        __syncthreads();
        {
            float D[4][4] = {};
            gemm_mma(HGH, HGL, 68, WF, rt * 16, ntb, lane, 0, 8, D);
            #pragma unroll
            for (int t = 0; t < 4; t++) {
                int c0 = (ntb + t) * 8 + 2 * tig;
                int r0 = rt * 16 + gid;
                *(float2*)&mjF[r0 * 132 + c0]       = make_float2(D[t][0], D[t][1]);
                *(float2*)&mjF[(r0 + 8) * 132 + c0] = make_float2(D[t][2], D[t][3]);
            }
        }
        __syncthreads();

        // stage We2; wd, be2; zero agg
        stage_cp(F_e2, WF, 4096, tid); CP_COMMIT();
        if (tid < 128) {
            s_wd[tid]  = We1l[256 * 128 + tid];
            s_be2[tid] = be2[l * 128 + tid];
        }
        for (int v = tid; v < 4096; v += NT) s_aggF[v] = 0.0f;
        CP_WAIT0();
        __syncthreads();

        // ---- pair phase: CTA-wide 32-edge chunks ----
        for (int e0 = 0; e0 < nE; e0 += 32) {
            {   // build m1 (split) from f32 mi/mj
                int e = tid >> 3, cg8 = tid & 7;
                int ee = e0 + e;
                int ij = s_edge[ee < nE ? ee : nE - 1];
                int i = ij >> 5, j = ij & 31;
                float dd = s_d2[ij];
                int c0 = cg8 * 16;
                u32 hbuf[8], lbuf[8];
                #pragma unroll
                for (int q = 0; q < 4; q++) {
                    float4 a = *(const float4*)&miF[i * 132 + c0 + 4 * q];
                    float4 bb = *(const float4*)&mjF[j * 132 + c0 + 4 * q];
                    float4 w = *(const float4*)&s_wd[c0 + 4 * q];
                    float v0 = silu_f(a.x + bb.x + dd * w.x);
                    float v1 = silu_f(a.y + bb.y + dd * w.y);
                    float v2 = silu_f(a.z + bb.z + dd * w.z);
                    float v3 = silu_f(a.w + bb.w + dd * w.w);
                    split2(v0, v1, hbuf[2 * q], lbuf[2 * q]);
                    split2(v2, v3, hbuf[2 * q + 1], lbuf[2 * q + 1]);
                }
                u32* ph = &M1H[e * 68 + cg8 * 8];
                u32* pl = &M1L[e * 68 + cg8 * 8];
                *(uint4*)&ph[0] = make_uint4(hbuf[0], hbuf[1], hbuf[2], hbuf[3]);
                *(uint4*)&ph[4] = make_uint4(hbuf[4], hbuf[5], hbuf[6], hbuf[7]);
                *(uint4*)&pl[0] = make_uint4(lbuf[0], lbuf[1], lbuf[2], lbuf[3]);
                *(uint4*)&pl[4] = make_uint4(lbuf[4], lbuf[5], lbuf[6], lbuf[7]);
            }
            __syncthreads();
            {   // GEMM + silu -> m2 (f32)
                float D[4][4] = {};
                gemm_mma(M1H, M1L, 68, WF, rt * 16, ntb, lane, 0, 8, D);
                #pragma unroll
                for (int t = 0; t < 4; t++) {
                    int c0 = (ntb + t) * 8 + 2 * tig;
                    float b0 = s_be2[c0], b1 = s_be2[c0 + 1];
                    int r0 = rt * 16 + gid;
                    *(float2*)&s_m2[r0 * 132 + c0] =
                        make_float2(silu_f(D[t][0] + b0), silu_f(D[t][1] + b1));
                    *(float2*)&s_m2[(r0 + 8) * 132 + c0] =
                        make_float2(silu_f(D[t][2] + b0), silu_f(D[t][3] + b1));
                }
            }
            __syncthreads();
            if (tid < 128) {   // segmented column sweep
                int c = tid;
                float run = 0.0f; int curi = -1;
                int lim = nE - e0; if (lim > 32) lim = 32;
                for (int r = 0; r < lim; r++) {
                    int i = s_edge[e0 + r] >> 5;
                    if (i != curi) {
                        if (curi >= 0) s_aggF[curi * 128 + c] += run;
                        curi = i; run = 0.0f;
                    }
                    run += s_m2[r * 132 + c];
                }
                if (curi >= 0) s_aggF[curi * 128 + c] += run;
            }
            __syncthreads();
        }

        // split aggF -> AG; stage Wh1a
        stage_cp(F_h1a, WF, 4096, tid); CP_COMMIT();
        for (int u = tid; u < 2048; u += NT) {
            int r = u >> 6, cpi = u & 63;
            stpair(AGH, AGL, r * 68 + cpi,
                   s_aggF[r * 128 + cpi * 2], s_aggF[r * 128 + cpi * 2 + 1]);
        }
        CP_WAIT0();
        __syncthreads();

        // u = silu(hg @ Wh1a + agg @ Wh1b + bh1) -> M1 (split)
        float D[4][4] = {};
        gemm_mma(HGH, HGL, 68, WF, rt * 16, ntb, lane, 0, 8, D);
        __syncthreads();
        stage_cp(F_h1b, WF, 4096, tid); CP_COMMIT(); CP_WAIT0();
        __syncthreads();
        gemm_mma(AGH, AGL, 68, WF, rt * 16, ntb, lane, 0, 8, D);
        #pragma unroll
        for (int t = 0; t < 4; t++) {
            int c0 = (ntb + t) * 8 + 2 * tig;
            float b0 = bh1[l * 128 + c0], b1 = bh1[l * 128 + c0 + 1];
            int cpi = c0 >> 1;
            stpair(M1H, M1L, (rt * 16 + gid) * 68 + cpi,
                   silu_f(D[t][0] + b0), silu_f(D[t][1] + b1));
            stpair(M1H, M1L, (rt * 16 + gid + 8) * 68 + cpi,
                   silu_f(D[t][2] + b0), silu_f(D[t][3] + b1));
        }
        __syncthreads();

        // hg += u @ Wh2 + bh2
        stage_cp(F_h2, WF, 4096, tid); CP_COMMIT(); CP_WAIT0();
        __syncthreads();
        {
            float D2[4][4] = {};
            gemm_mma(M1H, M1L, 68, WF, rt * 16, ntb, lane, 0, 8, D2);
            #pragma unroll
            for (int t = 0; t < 4; t++) {
                int c0 = (ntb + t) * 8 + 2 * tig;
                float b0 = bh2[l * 128 + c0], b1 = bh2[l * 128 + c0 + 1];
                int cpi = c0 >> 1;
                int r0 = rt * 16 + gid;
                float2 h0 = ldpair(HGH, HGL, r0 * 68 + cpi);
                stpair(HGH, HGL, r0 * 68 + cpi,
                       h0.x + D2[t][0] + b0, h0.y + D2[t][1] + b1);
                float2 h1 = ldpair(HGH, HGL, (r0 + 8) * 68 + cpi);
                stpair(HGH, HGL, (r0 + 8) * 68 + cpi,
                       h1.x + D2[t][2] + b0, h1.y + D2[t][3] + b1);
            }
        }
        __syncthreads();
    }

    // ---- head: ho = hg @ W_out + b_out -> M1 (split) ----
    stage_cp(g_wfrag + 12 * 16384, WF, 4096, tid); CP_COMMIT(); CP_WAIT0();
    __syncthreads();
    {
        float D[4][4] = {};
        gemm_mma(HGH, HGL, 68, WF, rt * 16, ntb, lane, 0, 8, D);
        #pragma unroll
        for (int t = 0; t < 4; t++) {
            int c0 = (ntb + t) * 8 + 2 * tig;
            float b0 = b_out[c0], b1 = b_out[c0 + 1];
            int cpi = c0 >> 1;
            stpair(M1H, M1L, (rt * 16 + gid) * 68 + cpi,     D[t][0] + b0, D[t][1] + b1);
            stpair(M1H, M1L, (rt * 16 + gid + 8) * 68 + cpi, D[t][2] + b0, D[t][3] + b1);
        }
    }
    __syncthreads();

    // t1 = silu(ho @ Wn1 + bn1) -> s_m2 (f32)
    stage_cp(g_wfrag + 13 * 16384, WF, 4096, tid); CP_COMMIT(); CP_WAIT0();
    __syncthreads();
    {
        float D[4][4] = {};
        gemm_mma(M1H, M1L, 68, WF, rt * 16, ntb, lane, 0, 8, D);
        #pragma unroll
        for (int t = 0; t < 4; t++) {
            int c0 = (ntb + t) * 8 + 2 * tig;
            float b0 = bn1[c0], b1 = bn1[c0 + 1];
            int r0 = rt * 16 + gid;
            *(float2*)&s_m2[r0 * 132 + c0] =
                make_float2(silu_f(D[t][0] + b0), silu_f(D[t][1] + b1));
            *(float2*)&s_m2[(r0 + 8) * 132 + c0] =
                make_float2(silu_f(D[t][2] + b0), silu_f(D[t][3] + b1));
        }
    }
    __syncthreads();

    // ---- out[b] = (colsum t1) . Wn2 + 32*bn2 ----
    float part = 0.0f;
    if (tid < 128) {
        int c = tid;
        float s = 0.0f;
        #pragma unroll 1
        for (int i = 0; i < 32; i++) s += s_m2[i * 132 + c];
        part = s * Wn2[c];
    }
    #pragma unroll
    for (int off = 16; off > 0; off >>= 1)
        part += __shfl_down_sync(0xffffffffu, part, off);
    if (warp < 4 && lane == 0) s_red[warp] = part;
    __syncthreads();
    if (tid == 0)
        g_out[b] = s_red[0] + s_red[1] + s_red[2] + s_red[3] + 32.0f * bn2[0];
}

extern "C" void kernel_launch(void* const* d_in, const int* in_sizes, int n_in,
                              void* d_out, int out_size) {
    const float* g_h   = (const float*)d_in[0];
    const float* g_x   = (const float*)d_in[1];
    const float* W_in  = (const float*)d_in[3];
    const float* b_in  = (const float*)d_in[4];
    const float* We1   = (const float*)d_in[5];
    const float* be1   = (const float*)d_in[6];
    const float* We2   = (const float*)d_in[7];
    const float* be2   = (const float*)d_in[8];
    const float* Wh1   = (const float*)d_in[9];
    const float* bh1   = (const float*)d_in[10];
    const float* Wh2   = (const float*)d_in[11];
    const float* bh2   = (const float*)d_in[12];
    const float* W_out = (const float*)d_in[13];
    const float* b_out = (const float*)d_in[14];
    const float* Wn1   = (const float*)d_in[15];
    const float* bn1   = (const float*)d_in[16];
    const float* Wn2   = (const float*)d_in[17];
    const float* bn2   = (const float*)d_in[18];
    float* out = (float*)d_out;

    prep_kernel<<<dim3(32, 15), 256>>>(We1, We2, Wh1, Wh2, W_out, Wn1, W_in);

    const int smem_bytes = SM_WORDS * 4;
    cudaFuncSetAttribute(sake_kernel, cudaFuncAttributeMaxDynamicSharedMemorySize,
                         smem_bytes);
    sake_kernel<<<NB, NT, smem_bytes>>>(
        g_h, g_x, b_in, We1, be1, be2, bh1, bh2, b_out, bn1, Wn2, bn2, out);
}

// round 9
// speedup vs baseline: 1.7190x; 1.0443x over previous
#include <cuda_runtime.h>

// SAKE GNN fully fused, one CTA per graph (B=512, M=32, H=128, L=2).
// R9: 16 warps (512 thr) — n-tile split keeps smem traffic constant while
//     doubling warps/SMSP; W staging half-pipelined via cp.async groups.

#define NB 512
#define NT 512
typedef unsigned int u32;

// global fragment buffer: 14 big Ws (16384 u32 each) + W_in (2048)
__device__ u32 g_wfrag[14 * 16384 + 2048];
#define WIN_BASE (14 * 16384)

// ---- shared memory layout (u32 word offsets) ----
#define O_HGH 0        // hg split: 32 x 68
#define O_HGL 2176
#define O_MIF 4352     // mi f32: 32 x 132
#define O_MJF 8576     // mj f32: 32 x 132
#define O_AGH 12800    // agg split: 32 x 68
#define O_AGL 14976
#define O_M1H 17152    // m1 / u / ho split: 32 x 68
#define O_M1L 19328
#define O_HTH 21504    // h input split: 32 x 8
#define O_HTL 21760
#define O_WF  22016    // W fragments: hi 8192 + lo 8192
#define O_M2  38400    // f32 32 x 132
#define O_AGF 42624    // f32 32 x 128
#define O_D2  46720
#define O_EDGE 47744
#define O_WD  48768
#define O_BE2 48896
#define O_RMASK 49024
#define O_ROFF 49056
#define O_X   49088
#define O_RED 49184
#define O_NE  49200
#define SM_WORDS 49208

__device__ __forceinline__ float silu_f(float v) {
    return __fdividef(v, 1.0f + __expf(-v));
}
__device__ __forceinline__ u32 packbf(float x0, float x1) {
    u32 r;
    asm("cvt.rn.bf16x2.f32 %0, %1, %2;" : "=r"(r) : "f"(x1), "f"(x0));
    return r;
}
__device__ __forceinline__ void split2(float x0, float x1, u32& h, u32& l) {
    h = packbf(x0, x1);
    float r0 = x0 - __uint_as_float(h << 16);
    float r1 = x1 - __uint_as_float(h & 0xffff0000u);
    l = packbf(r0, r1);
}
__device__ __forceinline__ float2 ldpair(const u32* Xh, const u32* Xl, int idx) {
    u32 h = Xh[idx], l = Xl[idx];
    float2 v;
    v.x = __uint_as_float(h << 16) + __uint_as_float(l << 16);
    v.y = __uint_as_float(h & 0xffff0000u) + __uint_as_float(l & 0xffff0000u);
    return v;
}
__device__ __forceinline__ void stpair(u32* Xh, u32* Xl, int idx, float v0, float v1) {
    u32 h, l; split2(v0, v1, h, l);
    Xh[idx] = h; Xl[idx] = l;
}

__device__ __forceinline__ void mma4(float d[4], const u32 a[4], u32 b0, u32 b1) {
    asm volatile("mma.sync.aligned.m16n8k16.row.col.f32.bf16.bf16.f32 "
        "{%0,%1,%2,%3}, {%4,%5,%6,%7}, {%8,%9}, {%0,%1,%2,%3};"
        : "+f"(d[0]), "+f"(d[1]), "+f"(d[2]), "+f"(d[3])
        : "r"(a[0]), "r"(a[1]), "r"(a[2]), "r"(a[3]), "r"(b0), "r"(b1));
}

__device__ __forceinline__ void ldAf(const u32* X, int rs, int r0, int kt,
                                     int lane, u32 a[4]) {
    int gid = lane >> 2, tig = lane & 3;
    const u32* p = X + (r0 + gid) * rs + kt * 8 + tig;
    a[0] = p[0];
    a[2] = p[4];
    a[1] = p[8 * rs];
    a[3] = p[8 * rs + 4];
}

// 3-term GEMM, 2 n-tiles per warp, kt range [kt0, kt1)
__device__ __forceinline__ void gemm_mma(const u32* Xh, const u32* Xl, int rs,
                                         const u32* sWF, int r0, int ntb,
                                         int lane, int kt0, int kt1,
                                         float D[2][4]) {
    #pragma unroll 1
    for (int kt = kt0; kt < kt1; kt++) {
        u32 ah[4], al[4];
        ldAf(Xh, rs, r0, kt, lane, ah);
        ldAf(Xl, rs, r0, kt, lane, al);
        #pragma unroll
        for (int t = 0; t < 2; t++) {
            const u32* bp = sWF + ((kt * 16 + ntb + t) * 32 + lane) * 2;
            u32 bh0 = bp[0], bh1 = bp[1];
            u32 bl0 = bp[8192], bl1 = bp[8193];
            mma4(D[t], ah, bh0, bh1);
            mma4(D[t], ah, bl0, bl1);
            mma4(D[t], al, bh0, bh1);
        }
    }
}

__device__ __forceinline__ void cp16(unsigned saddr, const void* g) {
    asm volatile("cp.async.cg.shared.global [%0], [%1], 16;" :: "r"(saddr), "l"(g));
}
#define CP_COMMIT() asm volatile("cp.async.commit_group;")
#define CP_WAIT0()  asm volatile("cp.async.wait_group 0;" ::: "memory")
#define CP_WAIT1()  asm volatile("cp.async.wait_group 1;" ::: "memory")

__device__ __forceinline__ void stage_cp(const u32* __restrict__ g, u32* s,
                                         int nf4, int tid) {
    unsigned sa = (unsigned)__cvta_generic_to_shared(s);
    for (int v = tid; v < nf4; v += NT)
        cp16(sa + v * 16, g + v * 4);
}

// issue both kt-half stages of one weight as two cp.async groups
__device__ __forceinline__ void stage_W_halves(const u32* __restrict__ F,
                                               u32* WF, int tid) {
    stage_cp(F, WF, 1024, tid);                    // hi kt 0..3
    stage_cp(F + 8192, WF + 8192, 1024, tid);      // lo kt 0..3
    CP_COMMIT();
    stage_cp(F + 4096, WF + 4096, 1024, tid);      // hi kt 4..7
    stage_cp(F + 12288, WF + 12288, 1024, tid);    // lo kt 4..7
    CP_COMMIT();
}

// ================= prep kernel: weights -> fragment hi/lo layout =============
__global__ void prep_kernel(const float* __restrict__ We1,
                            const float* __restrict__ We2,
                            const float* __restrict__ Wh1,
                            const float* __restrict__ Wh2,
                            const float* __restrict__ W_out,
                            const float* __restrict__ Wn1,
                            const float* __restrict__ W_in) {
    int y = blockIdx.y;
    int u = blockIdx.x * 256 + threadIdx.x;
    if (y < 14) {
        const float* src;
        if (y < 12) {
            int l = y / 6, w = y % 6;
            switch (w) {
                case 0: src = We1 + l * 257 * 128; break;
                case 1: src = We1 + l * 257 * 128 + 16384; break;
                case 2: src = We2 + l * 16384; break;
                case 3: src = Wh1 + l * 32768; break;
                case 4: src = Wh1 + l * 32768 + 16384; break;
                default: src = Wh2 + l * 16384; break;
            }
        } else {
            src = (y == 12) ? W_out : Wn1;
        }
        int p = u >> 7, c = u & 127;
        float w0 = src[(2 * p) * 128 + c];
        float w1 = src[(2 * p + 1) * 128 + c];
        int kt = p >> 3, pr = p & 7;
        int cpp = pr & 3, reg = pr >> 2;
        int lane = (c & 7) * 4 + cpp;
        int nt = c >> 3;
        int dst = y * 16384 + ((kt * 16 + nt) * 32 + lane) * 2 + reg;
        u32 h, l2; split2(w0, w1, h, l2);
        g_wfrag[dst] = h;
        g_wfrag[dst + 8192] = l2;
    } else {
        if (u >= 1024) return;
        int p = u >> 7, c = u & 127;
        float w0 = W_in[(2 * p) * 128 + c];
        float w1 = W_in[(2 * p + 1) * 128 + c];
        int cpp = p & 3, reg = p >> 2;
        int lane = (c & 7) * 4 + cpp;
        int nt = c >> 3;
        int dst = WIN_BASE + ((nt * 32 + lane) * 2 + reg);
        u32 h, l2; split2(w0, w1, h, l2);
        g_wfrag[dst] = h;
        g_wfrag[dst + 1024] = l2;
    }
}

// ================================ main kernel ================================
__global__ void __launch_bounds__(NT, 1)
sake_kernel(const float* __restrict__ g_h, const float* __restrict__ g_x,
            const float* __restrict__ b_in,
            const float* __restrict__ We1, const float* __restrict__ be1,
            const float* __restrict__ be2,
            const float* __restrict__ bh1, const float* __restrict__ bh2,
            const float* __restrict__ b_out,
            const float* __restrict__ bn1,
            const float* __restrict__ Wn2, const float* __restrict__ bn2,
            float* __restrict__ g_out)
{
    extern __shared__ u32 smu[];
    u32* HGH = smu + O_HGH;  u32* HGL = smu + O_HGL;
    float* miF = (float*)(smu + O_MIF);
    float* mjF = (float*)(smu + O_MJF);
    u32* AGH = smu + O_AGH;  u32* AGL = smu + O_AGL;
    u32* M1H = smu + O_M1H;  u32* M1L = smu + O_M1L;
    u32* HTH = smu + O_HTH;  u32* HTL = smu + O_HTL;
    u32* WF  = smu + O_WF;
    float* s_m2   = (float*)(smu + O_M2);
    float* s_aggF = (float*)(smu + O_AGF);
    float* s_d2   = (float*)(smu + O_D2);
    int*   s_edge = (int*)(smu + O_EDGE);
    float* s_wd   = (float*)(smu + O_WD);
    float* s_be2  = (float*)(smu + O_BE2);
    u32*   s_rmask = smu + O_RMASK;
    int*   s_roff  = (int*)(smu + O_ROFF);
    float* s_x    = (float*)(smu + O_X);
    float* s_red  = (float*)(smu + O_RED);
    int*   s_ne   = (int*)(smu + O_NE);

    const int tid  = threadIdx.x;
    const int warp = tid >> 5;          // 0..15
    const int lane = tid & 31;
    const int gid  = lane >> 2;
    const int tig  = lane & 3;
    const int b    = blockIdx.x;
    const int rt   = warp & 1;          // row tile
    const int ntb  = (warp >> 1) * 2;   // 2 n-tiles per warp
    const int i0   = warp * 2;          // adjacency rows

    // ---- prologue: x, split h, stage W_in frags ----
    if (tid < 96) s_x[tid] = g_x[b * 96 + tid];
    if (tid < 256) {
        int r = tid >> 3, cp = tid & 7;
        float2 hv = *(const float2*)&g_h[b * 512 + r * 16 + cp * 2];
        u32 h, l; split2(hv.x, hv.y, h, l);
        HTH[r * 8 + cp] = h; HTL[r * 8 + cp] = l;
    }
    stage_cp(g_wfrag + WIN_BASE, WF, 256, tid);
    stage_cp(g_wfrag + WIN_BASE + 1024, WF + 8192, 256, tid);
    CP_COMMIT();
    __syncthreads();

    // ---- d2 ----
    for (int p = tid; p < 1024; p += NT) {
        int i = p >> 5, j = p & 31;
        float dx = s_x[i * 3 + 0] - s_x[j * 3 + 0];
        float dy = s_x[i * 3 + 1] - s_x[j * 3 + 1];
        float dz = s_x[i * 3 + 2] - s_x[j * 3 + 2];
        s_d2[p] = dx * dx + dy * dy + dz * dz;
    }
    __syncthreads();

    // ---- adjacency masks ----
    #pragma unroll
    for (int rr = 0; rr < 2; rr++) {
        int i = i0 + rr;
        bool adj = (s_d2[i * 32 + lane] < 1.0f) && (lane != i);
        unsigned m = __ballot_sync(0xffffffffu, adj);
        if (lane == 0) s_rmask[i] = m;
    }
    CP_WAIT0();
    __syncthreads();

    // ---- hg = h @ W_in + b_in ----
    {
        float D[2][4] = {};
        gemm_mma(HTH, HTL, 8, WF, rt * 16, ntb, lane, 0, 1, D);
        #pragma unroll
        for (int t = 0; t < 2; t++) {
            int c0 = (ntb + t) * 8 + 2 * tig;
            float b0 = b_in[c0], b1 = b_in[c0 + 1];
            int cpi = c0 >> 1;
            stpair(HGH, HGL, (rt * 16 + gid) * 68 + cpi,     D[t][0] + b0, D[t][1] + b1);
            stpair(HGH, HGL, (rt * 16 + gid + 8) * 68 + cpi, D[t][2] + b0, D[t][3] + b1);
        }
    }

    // ---- edge-list scan ----
    __syncthreads();
    if (warp == 0) {
        unsigned m = s_rmask[lane];
        int c = __popc(m);
        int inc = c;
        #pragma unroll
        for (int d = 1; d < 32; d <<= 1) {
            int n = __shfl_up_sync(0xffffffffu, inc, d);
            if (lane >= d) inc += n;
        }
        s_roff[lane] = inc - c;
        if (lane == 31) *s_ne = inc;
    }
    __syncthreads();
    #pragma unroll
    for (int rr = 0; rr < 2; rr++) {
        int i = i0 + rr;
        unsigned m = s_rmask[i];
        if ((m >> lane) & 1u) {
            int pos = s_roff[i] + __popc(m & ((1u << lane) - 1u));
            s_edge[pos] = (i << 5) | lane;
        }
    }
    __syncthreads();
    const int nE = *s_ne;

    // ---- layers ----
    #pragma unroll 1
    for (int l = 0; l < 2; l++) {
        const u32* F_e1a = g_wfrag + (l * 6 + 0) * 16384;
        const u32* F_e1b = g_wfrag + (l * 6 + 1) * 16384;
        const u32* F_e2  = g_wfrag + (l * 6 + 2) * 16384;
        const u32* F_h1a = g_wfrag + (l * 6 + 3) * 16384;
        const u32* F_h1b = g_wfrag + (l * 6 + 4) * 16384;
        const u32* F_h2  = g_wfrag + (l * 6 + 5) * 16384;
        const float* We1l = We1 + l * (257 * 128);

        // mi = hg @ We1a + be1 -> miF
        stage_W_halves(F_e1a, WF, tid);
        CP_WAIT1(); __syncthreads();
        {
            float D[2][4] = {};
            gemm_mma(HGH, HGL, 68, WF, rt * 16, ntb, lane, 0, 4, D);
            CP_WAIT0(); __syncthreads();
            gemm_mma(HGH, HGL, 68, WF, rt * 16, ntb, lane, 4, 8, D);
            #pragma unroll
            for (int t = 0; t < 2; t++) {
                int c0 = (ntb + t) * 8 + 2 * tig;
                float b0 = be1[l * 128 + c0], b1 = be1[l * 128 + c0 + 1];
                int r0 = rt * 16 + gid;
                *(float2*)&miF[r0 * 132 + c0]       = make_float2(D[t][0] + b0, D[t][1] + b1);
                *(float2*)&miF[(r0 + 8) * 132 + c0] = make_float2(D[t][2] + b0, D[t][3] + b1);
            }
        }
        __syncthreads();

        // mj = hg @ We1b -> mjF
        stage_W_halves(F_e1b, WF, tid);
        CP_WAIT1(); __syncthreads();
        {
            float D[2][4] = {};
            gemm_mma(HGH, HGL, 68, WF, rt * 16, ntb, lane, 0, 4, D);
            CP_WAIT0(); __syncthreads();
            gemm_mma(HGH, HGL, 68, WF, rt * 16, ntb, lane, 4, 8, D);
            #pragma unroll
            for (int t = 0; t < 2; t++) {
                int c0 = (ntb + t) * 8 + 2 * tig;
                int r0 = rt * 16 + gid;
                *(float2*)&mjF[r0 * 132 + c0]       = make_float2(D[t][0], D[t][1]);
                *(float2*)&mjF[(r0 + 8) * 132 + c0] = make_float2(D[t][2], D[t][3]);
            }
        }
        __syncthreads();

        // stage We2; wd, be2; zero agg
        stage_W_halves(F_e2, WF, tid);
        if (tid < 128) {
            s_wd[tid]  = We1l[256 * 128 + tid];
            s_be2[tid] = be2[l * 128 + tid];
        }
        for (int v = tid; v < 4096; v += NT) s_aggF[v] = 0.0f;
        CP_WAIT0();
        __syncthreads();

        // ---- pair phase: CTA-wide 32-edge chunks ----
        for (int e0 = 0; e0 < nE; e0 += 32) {
            {   // build m1 (split): 16 threads per edge, 8 cols each
                int e = tid >> 4, cg16 = tid & 15;
                int ee = e0 + e;
                int ij = s_edge[ee < nE ? ee : nE - 1];
                int i = ij >> 5, j = ij & 31;
                float dd = s_d2[ij];
                int c0 = cg16 * 8;
                u32 hbuf[4], lbuf[4];
                #pragma unroll
                for (int q = 0; q < 2; q++) {
                    float4 a = *(const float4*)&miF[i * 132 + c0 + 4 * q];
                    float4 bb = *(const float4*)&mjF[j * 132 + c0 + 4 * q];
                    float4 w = *(const float4*)&s_wd[c0 + 4 * q];
                    float v0 = silu_f(a.x + bb.x + dd * w.x);
                    float v1 = silu_f(a.y + bb.y + dd * w.y);
                    float v2 = silu_f(a.z + bb.z + dd * w.z);
                    float v3 = silu_f(a.w + bb.w + dd * w.w);
                    split2(v0, v1, hbuf[2 * q], lbuf[2 * q]);
                    split2(v2, v3, hbuf[2 * q + 1], lbuf[2 * q + 1]);
                }
                *(uint4*)&M1H[e * 68 + cg16 * 4] = make_uint4(hbuf[0], hbuf[1], hbuf[2], hbuf[3]);
                *(uint4*)&M1L[e * 68 + cg16 * 4] = make_uint4(lbuf[0], lbuf[1], lbuf[2], lbuf[3]);
            }
            __syncthreads();
            {   // GEMM + silu -> m2
                float D[2][4] = {};
                gemm_mma(M1H, M1L, 68, WF, rt * 16, ntb, lane, 0, 8, D);
                #pragma unroll
                for (int t = 0; t < 2; t++) {
                    int c0 = (ntb + t) * 8 + 2 * tig;
                    float b0 = s_be2[c0], b1 = s_be2[c0 + 1];
                    int r0 = rt * 16 + gid;
                    *(float2*)&s_m2[r0 * 132 + c0] =
                        make_float2(silu_f(D[t][0] + b0), silu_f(D[t][1] + b1));
                    *(float2*)&s_m2[(r0 + 8) * 132 + c0] =
                        make_float2(silu_f(D[t][2] + b0), silu_f(D[t][3] + b1));
                }
            }
            __syncthreads();
            if (tid < 128) {   // segmented column sweep
                int c = tid;
                float run = 0.0f; int curi = -1;
                int lim = nE - e0; if (lim > 32) lim = 32;
                for (int r = 0; r < lim; r++) {
                    int i = s_edge[e0 + r] >> 5;
                    if (i != curi) {
                        if (curi >= 0) s_aggF[curi * 128 + c] += run;
                        curi = i; run = 0.0f;
                    }
                    run += s_m2[r * 132 + c];
                }
                if (curi >= 0) s_aggF[curi * 128 + c] += run;
            }
            __syncthreads();
        }

        // split aggF -> AG; stage Wh1a
        stage_W_halves(F_h1a, WF, tid);
        for (int u = tid; u < 2048; u += NT) {
            int r = u >> 6, cpi = u & 63;
            stpair(AGH, AGL, r * 68 + cpi,
                   s_aggF[r * 128 + cpi * 2], s_aggF[r * 128 + cpi * 2 + 1]);
        }
        CP_WAIT0();
        __syncthreads();

        // u = silu(hg @ Wh1a + agg @ Wh1b + bh1) -> M1 (split)
        float D[2][4] = {};
        gemm_mma(HGH, HGL, 68, WF, rt * 16, ntb, lane, 0, 8, D);
        __syncthreads();
        stage_W_halves(F_h1b, WF, tid);
        CP_WAIT0();
        __syncthreads();
        gemm_mma(AGH, AGL, 68, WF, rt * 16, ntb, lane, 0, 8, D);
        #pragma unroll
        for (int t = 0; t < 2; t++) {
            int c0 = (ntb + t) * 8 + 2 * tig;
            float b0 = bh1[l * 128 + c0], b1 = bh1[l * 128 + c0 + 1];
            int cpi = c0 >> 1;
            stpair(M1H, M1L, (rt * 16 + gid) * 68 + cpi,
                   silu_f(D[t][0] + b0), silu_f(D[t][1] + b1));
            stpair(M1H, M1L, (rt * 16 + gid + 8) * 68 + cpi,
                   silu_f(D[t][2] + b0), silu_f(D[t][3] + b1));
        }
        __syncthreads();

        // hg += u @ Wh2 + bh2
        stage_W_halves(F_h2, WF, tid);
        CP_WAIT1(); __syncthreads();
        {
            float D2[2][4] = {};
            gemm_mma(M1H, M1L, 68, WF, rt * 16, ntb, lane, 0, 4, D2);
            CP_WAIT0(); __syncthreads();
            gemm_mma(M1H, M1L, 68, WF, rt * 16, ntb, lane, 4, 8, D2);
            #pragma unroll
            for (int t = 0; t < 2; t++) {
                int c0 = (ntb + t) * 8 + 2 * tig;
                float b0 = bh2[l * 128 + c0], b1 = bh2[l * 128 + c0 + 1];
                int cpi = c0 >> 1;
                int r0 = rt * 16 + gid;
                float2 h0 = ldpair(HGH, HGL, r0 * 68 + cpi);
                stpair(HGH, HGL, r0 * 68 + cpi,
                       h0.x + D2[t][0] + b0, h0.y + D2[t][1] + b1);
                float2 h1 = ldpair(HGH, HGL, (r0 + 8) * 68 + cpi);
                stpair(HGH, HGL, (r0 + 8) * 68 + cpi,
                       h1.x + D2[t][2] + b0, h1.y + D2[t][3] + b1);
            }
        }
        __syncthreads();
    }

    // ---- head: ho = hg @ W_out + b_out -> M1 (split) ----
    stage_W_halves(g_wfrag + 12 * 16384, WF, tid);
    CP_WAIT1(); __syncthreads();
    {
        float D[2][4] = {};
        gemm_mma(HGH, HGL, 68, WF, rt * 16, ntb, lane, 0, 4, D);
        CP_WAIT0(); __syncthreads();
        gemm_mma(HGH, HGL, 68, WF, rt * 16, ntb, lane, 4, 8, D);
        #pragma unroll
        for (int t = 0; t < 2; t++) {
            int c0 = (ntb + t) * 8 + 2 * tig;
            float b0 = b_out[c0], b1 = b_out[c0 + 1];
            int cpi = c0 >> 1;
            stpair(M1H, M1L, (rt * 16 + gid) * 68 + cpi,     D[t][0] + b0, D[t][1] + b1);
            stpair(M1H, M1L, (rt * 16 + gid + 8) * 68 + cpi, D[t][2] + b0, D[t][3] + b1);
        }
    }
    __syncthreads();

    // t1 = silu(ho @ Wn1 + bn1) -> s_m2 (f32)
    stage_W_halves(g_wfrag + 13 * 16384, WF, tid);
    CP_WAIT1(); __syncthreads();
    {
        float D[2][4] = {};
        gemm_mma(M1H, M1L, 68, WF, rt * 16, ntb, lane, 0, 4, D);
        CP_WAIT0(); __syncthreads();
        gemm_mma(M1H, M1L, 68, WF, rt * 16, ntb, lane, 4, 8, D);
        #pragma unroll
        for (int t = 0; t < 2; t++) {
            int c0 = (ntb + t) * 8 + 2 * tig;
            float b0 = bn1[c0], b1 = bn1[c0 + 1];
            int r0 = rt * 16 + gid;
            *(float2*)&s_m2[r0 * 132 + c0] =
                make_float2(silu_f(D[t][0] + b0), silu_f(D[t][1] + b1));
            *(float2*)&s_m2[(r0 + 8) * 132 + c0] =
                make_float2(silu_f(D[t][2] + b0), silu_f(D[t][3] + b1));
        }
    }
    __syncthreads();

    // ---- out[b] = (colsum t1) . Wn2 + 32*bn2 ----
    float part = 0.0f;
    if (tid < 128) {
        int c = tid;
        float s = 0.0f;
        #pragma unroll 1
        for (int i = 0; i < 32; i++) s += s_m2[i * 132 + c];
        part = s * Wn2[c];
    }
    #pragma unroll
    for (int off = 16; off > 0; off >>= 1)
        part += __shfl_down_sync(0xffffffffu, part, off);
    if (warp < 4 && lane == 0) s_red[warp] = part;
    __syncthreads();
    if (tid == 0)
        g_out[b] = s_red[0] + s_red[1] + s_red[2] + s_red[3] + 32.0f * bn2[0];
}

extern "C" void kernel_launch(void* const* d_in, const int* in_sizes, int n_in,
                              void* d_out, int out_size) {
    const float* g_h   = (const float*)d_in[0];
    const float* g_x   = (const float*)d_in[1];
    const float* W_in  = (const float*)d_in[3];
    const float* b_in  = (const float*)d_in[4];
    const float* We1   = (const float*)d_in[5];
    const float* be1   = (const float*)d_in[6];
    const float* We2   = (const float*)d_in[7];
    const float* be2   = (const float*)d_in[8];
    const float* Wh1   = (const float*)d_in[9];
    const float* bh1   = (const float*)d_in[10];
    const float* Wh2   = (const float*)d_in[11];
    const float* bh2   = (const float*)d_in[12];
    const float* W_out = (const float*)d_in[13];
    const float* b_out = (const float*)d_in[14];
    const float* Wn1   = (const float*)d_in[15];
    const float* bn1   = (const float*)d_in[16];
    const float* Wn2   = (const float*)d_in[17];
    const float* bn2   = (const float*)d_in[18];
    float* out = (float*)d_out;

    prep_kernel<<<dim3(32, 15), 256>>>(We1, We2, Wh1, Wh2, W_out, Wn1, W_in);

    const int smem_bytes = SM_WORDS * 4;
    cudaFuncSetAttribute(sake_kernel, cudaFuncAttributeMaxDynamicSharedMemorySize,
                         smem_bytes);
    sake_kernel<<<NB, NT, smem_bytes>>>(
        g_h, g_x, b_in, We1, be1, be2, bh1, bh2, b_out, bn1, Wn2, bn2, out);
}

// round 10
// speedup vs baseline: 1.7745x; 1.0323x over previous
#include <cuda_runtime.h>

// SAKE GNN fully fused, one CTA per graph (B=512, M=32, H=128, L=2).
// R10: 32 warps (1024 thr, 8/SMSP); aggregation via S-matrix MMA with
//      register accumulation across edge chunks (serial sweep removed);
//      2 barriers per edge chunk (S double-buffered).

#define NB 512
#define NT 1024
typedef unsigned int u32;
typedef unsigned short u16;

// global fragment buffer: 14 big Ws (16384 u32 each) + W_in (2048)
__device__ u32 g_wfrag[14 * 16384 + 2048];
#define WIN_BASE (14 * 16384)

// ---- shared memory layout (u32 word offsets) ----
#define O_HGH 0        // hg split: 32 x 68
#define O_HGL 2176
#define O_MIF 4352     // mi f32: 32 x 132
#define O_MJF 8576     // mj f32: 32 x 132
#define O_AGH 12800    // agg split: 32 x 68
#define O_AGL 14976
#define O_M1H 17152    // m1 / u / ho split: 32 x 68
#define O_M1L 19328
#define O_HTH 21504    // h input split: 32 x 8
#define O_HTL 21760
#define O_WF  22016    // W fragments: hi 8192 + lo 8192
#define O_M2TH 38400   // m2 B-frag hi: 128 cols x 20
#define O_M2TL 40960   // m2 B-frag lo
#define O_S   43520    // S selection: 2 bufs x (32 rows x 20)
#define O_D2  44800
#define O_EDGE 45824
#define O_WD  46848
#define O_BE2 46976
#define O_RMASK 47104
#define O_ROFF 47136
#define O_X   47168
#define O_RED 47264
#define O_NE  47280
#define SM_WORDS 47288

__device__ __forceinline__ float silu_f(float v) {
    return __fdividef(v, 1.0f + __expf(-v));
}
__device__ __forceinline__ u32 packbf(float x0, float x1) {
    u32 r;
    asm("cvt.rn.bf16x2.f32 %0, %1, %2;" : "=r"(r) : "f"(x1), "f"(x0));
    return r;
}
__device__ __forceinline__ void split2(float x0, float x1, u32& h, u32& l) {
    h = packbf(x0, x1);
    float r0 = x0 - __uint_as_float(h << 16);
    float r1 = x1 - __uint_as_float(h & 0xffff0000u);
    l = packbf(r0, r1);
}
__device__ __forceinline__ float2 ldpair(const u32* Xh, const u32* Xl, int idx) {
    u32 h = Xh[idx], l = Xl[idx];
    float2 v;
    v.x = __uint_as_float(h << 16) + __uint_as_float(l << 16);
    v.y = __uint_as_float(h & 0xffff0000u) + __uint_as_float(l & 0xffff0000u);
    return v;
}
__device__ __forceinline__ void stpair(u32* Xh, u32* Xl, int idx, float v0, float v1) {
    u32 h, l; split2(v0, v1, h, l);
    Xh[idx] = h; Xl[idx] = l;
}

__device__ __forceinline__ void mma4(float d[4], const u32 a[4], u32 b0, u32 b1) {
    asm volatile("mma.sync.aligned.m16n8k16.row.col.f32.bf16.bf16.f32 "
        "{%0,%1,%2,%3}, {%4,%5,%6,%7}, {%8,%9}, {%0,%1,%2,%3};"
        : "+f"(d[0]), "+f"(d[1]), "+f"(d[2]), "+f"(d[3])
        : "r"(a[0]), "r"(a[1]), "r"(a[2]), "r"(a[3]), "r"(b0), "r"(b1));
}

__device__ __forceinline__ void ldAf(const u32* X, int rs, int r0, int kt,
                                     int lane, u32 a[4]) {
    int gid = lane >> 2, tig = lane & 3;
    const u32* p = X + (r0 + gid) * rs + kt * 8 + tig;
    a[0] = p[0];
    a[2] = p[4];
    a[1] = p[8 * rs];
    a[3] = p[8 * rs + 4];
}

// 3-term GEMM, ONE n-tile per warp, kt range [kt0, kt1)
__device__ __forceinline__ void gemm_mma(const u32* Xh, const u32* Xl, int rs,
                                         const u32* sWF, int r0, int nt,
                                         int lane, int kt0, int kt1, float D[4]) {
    #pragma unroll 1
    for (int kt = kt0; kt < kt1; kt++) {
        u32 ah[4], al[4];
        ldAf(Xh, rs, r0, kt, lane, ah);
        ldAf(Xl, rs, r0, kt, lane, al);
        const u32* bp = sWF + ((kt * 16 + nt) * 32 + lane) * 2;
        u32 bh0 = bp[0], bh1 = bp[1];
        u32 bl0 = bp[8192], bl1 = bp[8193];
        mma4(D, ah, bh0, bh1);
        mma4(D, ah, bl0, bl1);
        mma4(D, al, bh0, bh1);
    }
}

__device__ __forceinline__ void cp16(unsigned saddr, const void* g) {
    asm volatile("cp.async.cg.shared.global [%0], [%1], 16;" :: "r"(saddr), "l"(g));
}
#define CP_COMMIT() asm volatile("cp.async.commit_group;")
#define CP_WAIT0()  asm volatile("cp.async.wait_group 0;" ::: "memory")
#define CP_WAIT1()  asm volatile("cp.async.wait_group 1;" ::: "memory")

__device__ __forceinline__ void stage_cp(const u32* __restrict__ g, u32* s,
                                         int nf4, int tid) {
    unsigned sa = (unsigned)__cvta_generic_to_shared(s);
    for (int v = tid; v < nf4; v += NT)
        cp16(sa + v * 16, g + v * 4);
}

__device__ __forceinline__ void stage_W_halves(const u32* __restrict__ F,
                                               u32* WF, int tid) {
    stage_cp(F, WF, 1024, tid);
    stage_cp(F + 8192, WF + 8192, 1024, tid);
    CP_COMMIT();
    stage_cp(F + 4096, WF + 4096, 1024, tid);
    stage_cp(F + 12288, WF + 12288, 1024, tid);
    CP_COMMIT();
}

// write one f32 value into the hi/lo B-fragment m2 buffers at (col c, edge r)
__device__ __forceinline__ void write_m2t(u32* M2TH, u32* M2TL, int c, int r, float v) {
    u32 hp = packbf(v, 0.0f);
    float hf = __uint_as_float(hp << 16);
    u32 lp = packbf(v - hf, 0.0f);
    int wi = (c * 20 + (r >> 1)) * 2 + (r & 1);
    ((u16*)M2TH)[wi] = (u16)hp;
    ((u16*)M2TL)[wi] = (u16)lp;
}

// ================= prep kernel: weights -> fragment hi/lo layout =============
__global__ void prep_kernel(const float* __restrict__ We1,
                            const float* __restrict__ We2,
                            const float* __restrict__ Wh1,
                            const float* __restrict__ Wh2,
                            const float* __restrict__ W_out,
                            const float* __restrict__ Wn1,
                            const float* __restrict__ W_in) {
    int y = blockIdx.y;
    int u = blockIdx.x * 256 + threadIdx.x;
    if (y < 14) {
        const float* src;
        if (y < 12) {
            int l = y / 6, w = y % 6;
            switch (w) {
                case 0: src = We1 + l * 257 * 128; break;
                case 1: src = We1 + l * 257 * 128 + 16384; break;
                case 2: src = We2 + l * 16384; break;
                case 3: src = Wh1 + l * 32768; break;
                case 4: src = Wh1 + l * 32768 + 16384; break;
                default: src = Wh2 + l * 16384; break;
            }
        } else {
            src = (y == 12) ? W_out : Wn1;
        }
        int p = u >> 7, c = u & 127;
        float w0 = src[(2 * p) * 128 + c];
        float w1 = src[(2 * p + 1) * 128 + c];
        int kt = p >> 3, pr = p & 7;
        int cpp = pr & 3, reg = pr >> 2;
        int lane = (c & 7) * 4 + cpp;
        int nt = c >> 3;
        int dst = y * 16384 + ((kt * 16 + nt) * 32 + lane) * 2 + reg;
        u32 h, l2; split2(w0, w1, h, l2);
        g_wfrag[dst] = h;
        g_wfrag[dst + 8192] = l2;
    } else {
        if (u >= 1024) return;
        int p = u >> 7, c = u & 127;
        float w0 = W_in[(2 * p) * 128 + c];
        float w1 = W_in[(2 * p + 1) * 128 + c];
        int cpp = p & 3, reg = p >> 2;
        int lane = (c & 7) * 4 + cpp;
        int nt = c >> 3;
        int dst = WIN_BASE + ((nt * 32 + lane) * 2 + reg);
        u32 h, l2; split2(w0, w1, h, l2);
        g_wfrag[dst] = h;
        g_wfrag[dst + 1024] = l2;
    }
}

// ================================ main kernel ================================
__global__ void __launch_bounds__(NT, 1)
sake_kernel(const float* __restrict__ g_h, const float* __restrict__ g_x,
            const float* __restrict__ b_in,
            const float* __restrict__ We1, const float* __restrict__ be1,
            const float* __restrict__ be2,
            const float* __restrict__ bh1, const float* __restrict__ bh2,
            const float* __restrict__ b_out,
            const float* __restrict__ bn1,
            const float* __restrict__ Wn2, const float* __restrict__ bn2,
            float* __restrict__ g_out)
{
    extern __shared__ u32 smu[];
    u32* HGH = smu + O_HGH;  u32* HGL = smu + O_HGL;
    float* miF = (float*)(smu + O_MIF);
    float* mjF = (float*)(smu + O_MJF);
    u32* AGH = smu + O_AGH;  u32* AGL = smu + O_AGL;
    u32* M1H = smu + O_M1H;  u32* M1L = smu + O_M1L;
    u32* HTH = smu + O_HTH;  u32* HTL = smu + O_HTL;
    u32* WF  = smu + O_WF;
    u32* M2TH = smu + O_M2TH;
    u32* M2TL = smu + O_M2TL;
    u32* Sbuf = smu + O_S;
    float* s_d2   = (float*)(smu + O_D2);
    int*   s_edge = (int*)(smu + O_EDGE);
    float* s_wd   = (float*)(smu + O_WD);
    float* s_be2  = (float*)(smu + O_BE2);
    u32*   s_rmask = smu + O_RMASK;
    int*   s_roff  = (int*)(smu + O_ROFF);
    float* s_x    = (float*)(smu + O_X);
    float* s_red  = (float*)(smu + O_RED);
    int*   s_ne   = (int*)(smu + O_NE);

    const int tid  = threadIdx.x;
    const int warp = tid >> 5;          // 0..31
    const int lane = tid & 31;
    const int gid  = lane >> 2;
    const int tig  = lane & 3;
    const int b    = blockIdx.x;
    const int rt   = warp & 1;          // row tile
    const int nt   = warp >> 1;         // single n-tile (0..15)
    const int r0   = rt * 16 + gid;
    const int c0   = nt * 8 + 2 * tig;
    const int cpi  = c0 >> 1;

    // ---- prologue: x, split h, stage W_in frags ----
    if (tid < 96) s_x[tid] = g_x[b * 96 + tid];
    if (tid < 256) {
        int r = tid >> 3, cp = tid & 7;
        float2 hv = *(const float2*)&g_h[b * 512 + r * 16 + cp * 2];
        u32 h, l; split2(hv.x, hv.y, h, l);
        HTH[r * 8 + cp] = h; HTL[r * 8 + cp] = l;
    }
    stage_cp(g_wfrag + WIN_BASE, WF, 256, tid);
    stage_cp(g_wfrag + WIN_BASE + 1024, WF + 8192, 256, tid);
    CP_COMMIT();
    __syncthreads();

    // ---- d2 ----
    for (int p = tid; p < 1024; p += NT) {
        int i = p >> 5, j = p & 31;
        float dx = s_x[i * 3 + 0] - s_x[j * 3 + 0];
        float dy = s_x[i * 3 + 1] - s_x[j * 3 + 1];
        float dz = s_x[i * 3 + 2] - s_x[j * 3 + 2];
        s_d2[p] = dx * dx + dy * dy + dz * dz;
    }
    __syncthreads();

    // ---- adjacency masks: warp w owns node w ----
    {
        bool adj = (s_d2[warp * 32 + lane] < 1.0f) && (lane != warp);
        unsigned m = __ballot_sync(0xffffffffu, adj);
        if (lane == 0) s_rmask[warp] = m;
    }
    CP_WAIT0();
    __syncthreads();

    // ---- hg = h @ W_in + b_in ----
    {
        float D[4] = {};
        gemm_mma(HTH, HTL, 8, WF, rt * 16, nt, lane, 0, 1, D);
        float b0 = b_in[c0], b1 = b_in[c0 + 1];
        stpair(HGH, HGL, r0 * 68 + cpi,       D[0] + b0, D[1] + b1);
        stpair(HGH, HGL, (r0 + 8) * 68 + cpi, D[2] + b0, D[3] + b1);
    }

    // ---- edge-list scan ----
    __syncthreads();
    if (warp == 0) {
        unsigned m = s_rmask[lane];
        int c = __popc(m);
        int inc = c;
        #pragma unroll
        for (int d = 1; d < 32; d <<= 1) {
            int n = __shfl_up_sync(0xffffffffu, inc, d);
            if (lane >= d) inc += n;
        }
        s_roff[lane] = inc - c;
        if (lane == 31) *s_ne = inc;
    }
    __syncthreads();
    {
        unsigned m = s_rmask[warp];
        if ((m >> lane) & 1u) {
            int pos = s_roff[warp] + __popc(m & ((1u << lane) - 1u));
            s_edge[pos] = (warp << 5) | lane;
        }
    }
    __syncthreads();
    const int nE = *s_ne;

    // ---- layers ----
    #pragma unroll 1
    for (int l = 0; l < 2; l++) {
        const u32* F_e1a = g_wfrag + (l * 6 + 0) * 16384;
        const u32* F_e1b = g_wfrag + (l * 6 + 1) * 16384;
        const u32* F_e2  = g_wfrag + (l * 6 + 2) * 16384;
        const u32* F_h1a = g_wfrag + (l * 6 + 3) * 16384;
        const u32* F_h1b = g_wfrag + (l * 6 + 4) * 16384;
        const u32* F_h2  = g_wfrag + (l * 6 + 5) * 16384;
        const float* We1l = We1 + l * (257 * 128);

        // mi = hg @ We1a + be1 -> miF
        stage_W_halves(F_e1a, WF, tid);
        CP_WAIT1(); __syncthreads();
        {
            float D[4] = {};
            gemm_mma(HGH, HGL, 68, WF, rt * 16, nt, lane, 0, 4, D);
            CP_WAIT0(); __syncthreads();
            gemm_mma(HGH, HGL, 68, WF, rt * 16, nt, lane, 4, 8, D);
            float b0 = be1[l * 128 + c0], b1 = be1[l * 128 + c0 + 1];
            *(float2*)&miF[r0 * 132 + c0]       = make_float2(D[0] + b0, D[1] + b1);
            *(float2*)&miF[(r0 + 8) * 132 + c0] = make_float2(D[2] + b0, D[3] + b1);
        }
        __syncthreads();

        // mj = hg @ We1b -> mjF
        stage_W_halves(F_e1b, WF, tid);
        CP_WAIT1(); __syncthreads();
        {
            float D[4] = {};
            gemm_mma(HGH, HGL, 68, WF, rt * 16, nt, lane, 0, 4, D);
            CP_WAIT0(); __syncthreads();
            gemm_mma(HGH, HGL, 68, WF, rt * 16, nt, lane, 4, 8, D);
            *(float2*)&mjF[r0 * 132 + c0]       = make_float2(D[0], D[1]);
            *(float2*)&mjF[(r0 + 8) * 132 + c0] = make_float2(D[2], D[3]);
        }
        __syncthreads();

        // stage We2; wd, be2
        stage_W_halves(F_e2, WF, tid);
        if (tid < 128) {
            s_wd[tid]  = We1l[256 * 128 + tid];
            s_be2[tid] = be2[l * 128 + tid];
        }
        CP_WAIT0();
        __syncthreads();

        // ---- pair phase: 32-edge chunks; agg accumulated in registers ----
        float Dagg[4] = { 0.f, 0.f, 0.f, 0.f };
        int sb = 0;
        for (int e0 = 0; e0 < nE; e0 += 32) {
            {   // build m1 (split): 32 threads per edge, 4 cols each
                int e = tid >> 5, cq = (tid & 31) * 4;
                int ee = e0 + e;
                int ij = s_edge[ee < nE ? ee : nE - 1];
                int i = ij >> 5, j = ij & 31;
                float dd = s_d2[ij];
                float4 a = *(const float4*)&miF[i * 132 + cq];
                float4 bb = *(const float4*)&mjF[j * 132 + cq];
                float4 w = *(const float4*)&s_wd[cq];
                float v0 = silu_f(a.x + bb.x + dd * w.x);
                float v1 = silu_f(a.y + bb.y + dd * w.y);
                float v2 = silu_f(a.z + bb.z + dd * w.z);
                float v3 = silu_f(a.w + bb.w + dd * w.w);
                u32 h0, l0, h1, l1;
                split2(v0, v1, h0, l0);
                split2(v2, v3, h1, l1);
                *(uint2*)&M1H[e * 68 + (cq >> 1)] = make_uint2(h0, h1);
                *(uint2*)&M1L[e * 68 + (cq >> 1)] = make_uint2(l0, l1);
            }
            if (tid < 512) {   // build S[sb]: rows=nodes, col-pairs=edge pairs
                int i = tid >> 4, ep = tid & 15;
                int ea = e0 + 2 * ep, eb = ea + 1;
                int ia = (ea < nE) ? (s_edge[ea] >> 5) : -1;
                int ib = (eb < nE) ? (s_edge[eb] >> 5) : -1;
                u32 val = (ia == i ? 0x00003F80u : 0u) | (ib == i ? 0x3F800000u : 0u);
                Sbuf[sb * 640 + i * 20 + ep] = val;
            }
            __syncthreads();   // B1
            {   // pair GEMM + silu -> m2T (B-fragment hi/lo)
                float D[4] = {};
                gemm_mma(M1H, M1L, 68, WF, rt * 16, nt, lane, 0, 8, D);
                float b0 = s_be2[c0], b1 = s_be2[c0 + 1];
                write_m2t(M2TH, M2TL, c0,     r0,     silu_f(D[0] + b0));
                write_m2t(M2TH, M2TL, c0 + 1, r0,     silu_f(D[1] + b1));
                write_m2t(M2TH, M2TL, c0,     r0 + 8, silu_f(D[2] + b0));
                write_m2t(M2TH, M2TL, c0 + 1, r0 + 8, silu_f(D[3] + b1));
            }
            __syncthreads();   // B2
            {   // agg += S @ (m2h + m2l)
                const u32* Sp = Sbuf + sb * 640;
                #pragma unroll
                for (int kt = 0; kt < 2; kt++) {
                    u32 a[4];
                    ldAf(Sp, 20, rt * 16, kt, lane, a);
                    int cB = nt * 8 + (lane >> 2);
                    const u32* bh = M2TH + cB * 20 + kt * 8 + (lane & 3);
                    const u32* bl = M2TL + cB * 20 + kt * 8 + (lane & 3);
                    mma4(Dagg, a, bh[0], bh[4]);
                    mma4(Dagg, a, bl[0], bl[4]);
                }
            }
            sb ^= 1;
        }
        // write agg registers -> AG split arrays; stage Wh1a
        stage_W_halves(F_h1a, WF, tid);
        stpair(AGH, AGL, r0 * 68 + cpi,       Dagg[0], Dagg[1]);
        stpair(AGH, AGL, (r0 + 8) * 68 + cpi, Dagg[2], Dagg[3]);
        CP_WAIT0();
        __syncthreads();

        // u = silu(hg @ Wh1a + agg @ Wh1b + bh1) -> M1 (split)
        float D[4] = {};
        gemm_mma(HGH, HGL, 68, WF, rt * 16, nt, lane, 0, 8, D);
        __syncthreads();
        stage_W_halves(F_h1b, WF, tid);
        CP_WAIT0();
        __syncthreads();
        gemm_mma(AGH, AGL, 68, WF, rt * 16, nt, lane, 0, 8, D);
        {
            float b0 = bh1[l * 128 + c0], b1 = bh1[l * 128 + c0 + 1];
            stpair(M1H, M1L, r0 * 68 + cpi,
                   silu_f(D[0] + b0), silu_f(D[1] + b1));
            stpair(M1H, M1L, (r0 + 8) * 68 + cpi,
                   silu_f(D[2] + b0), silu_f(D[3] + b1));
        }
        __syncthreads();

        // hg += u @ Wh2 + bh2
        stage_W_halves(F_h2, WF, tid);
        CP_WAIT1(); __syncthreads();
        {
            float D2[4] = {};
            gemm_mma(M1H, M1L, 68, WF, rt * 16, nt, lane, 0, 4, D2);
            CP_WAIT0(); __syncthreads();
            gemm_mma(M1H, M1L, 68, WF, rt * 16, nt, lane, 4, 8, D2);
            float b0 = bh2[l * 128 + c0], b1 = bh2[l * 128 + c0 + 1];
            float2 h0 = ldpair(HGH, HGL, r0 * 68 + cpi);
            stpair(HGH, HGL, r0 * 68 + cpi, h0.x + D2[0] + b0, h0.y + D2[1] + b1);
            float2 h1 = ldpair(HGH, HGL, (r0 + 8) * 68 + cpi);
            stpair(HGH, HGL, (r0 + 8) * 68 + cpi, h1.x + D2[2] + b0, h1.y + D2[3] + b1);
        }
        __syncthreads();
    }

    // ---- head: ho = hg @ W_out + b_out -> M1 (split) ----
    stage_W_halves(g_wfrag + 12 * 16384, WF, tid);
    CP_WAIT1(); __syncthreads();
    {
        float D[4] = {};
        gemm_mma(HGH, HGL, 68, WF, rt * 16, nt, lane, 0, 4, D);
        CP_WAIT0(); __syncthreads();
        gemm_mma(HGH, HGL, 68, WF, rt * 16, nt, lane, 4, 8, D);
        float b0 = b_out[c0], b1 = b_out[c0 + 1];
        stpair(M1H, M1L, r0 * 68 + cpi,       D[0] + b0, D[1] + b1);
        stpair(M1H, M1L, (r0 + 8) * 68 + cpi, D[2] + b0, D[3] + b1);
    }
    __syncthreads();

    // t1 = silu(ho @ Wn1 + bn1) -> miF (f32)
    stage_W_halves(g_wfrag + 13 * 16384, WF, tid);
    CP_WAIT1(); __syncthreads();
    {
        float D[4] = {};
        gemm_mma(M1H, M1L, 68, WF, rt * 16, nt, lane, 0, 4, D);
        CP_WAIT0(); __syncthreads();
        gemm_mma(M1H, M1L, 68, WF, rt * 16, nt, lane, 4, 8, D);
        float b0 = bn1[c0], b1 = bn1[c0 + 1];
        *(float2*)&miF[r0 * 132 + c0] =
            make_float2(silu_f(D[0] + b0), silu_f(D[1] + b1));
        *(float2*)&miF[(r0 + 8) * 132 + c0] =
            make_float2(silu_f(D[2] + b0), silu_f(D[3] + b1));
    }
    __syncthreads();

    // ---- out[b] = (colsum t1) . Wn2 + 32*bn2 ----
    float part = 0.0f;
    if (tid < 128) {
        int c = tid;
        float s = 0.0f;
        #pragma unroll 1
        for (int i = 0; i < 32; i++) s += miF[i * 132 + c];
        part = s * Wn2[c];
    }
    #pragma unroll
    for (int off = 16; off > 0; off >>= 1)
        part += __shfl_down_sync(0xffffffffu, part, off);
    if (warp < 4 && lane == 0) s_red[warp] = part;
    __syncthreads();
    if (tid == 0)
        g_out[b] = s_red[0] + s_red[1] + s_red[2] + s_red[3] + 32.0f * bn2[0];
}

extern "C" void kernel_launch(void* const* d_in, const int* in_sizes, int n_in,
                              void* d_out, int out_size) {
    const float* g_h   = (const float*)d_in[0];
    const float* g_x   = (const float*)d_in[1];
    const float* W_in  = (const float*)d_in[3];
    const float* b_in  = (const float*)d_in[4];
    const float* We1   = (const float*)d_in[5];
    const float* be1   = (const float*)d_in[6];
    const float* We2   = (const float*)d_in[7];
    const float* be2   = (const float*)d_in[8];
    const float* Wh1   = (const float*)d_in[9];
    const float* bh1   = (const float*)d_in[10];
    const float* Wh2   = (const float*)d_in[11];
    const float* bh2   = (const float*)d_in[12];
    const float* W_out = (const float*)d_in[13];
    const float* b_out = (const float*)d_in[14];
    const float* Wn1   = (const float*)d_in[15];
    const float* bn1   = (const float*)d_in[16];
    const float* Wn2   = (const float*)d_in[17];
    const float* bn2   = (const float*)d_in[18];
    float* out = (float*)d_out;

    prep_kernel<<<dim3(32, 15), 256>>>(We1, We2, Wh1, Wh2, W_out, Wn1, W_in);

    const int smem_bytes = SM_WORDS * 4;
    cudaFuncSetAttribute(sake_kernel, cudaFuncAttributeMaxDynamicSharedMemorySize,
                         smem_bytes);
    sake_kernel<<<NB, NT, smem_bytes>>>(
        g_h, g_x, b_in, We1, be1, be2, bh1, bh2, b_out, bn1, Wn2, bn2, out);
}

// round 11
// speedup vs baseline: 1.8215x; 1.0265x over previous
#include <cuda_runtime.h>

// SAKE GNN fully fused, one CTA per graph (B=512, M=32, H=128, L=2).
// R11: pair phase software-pipelined to ONE barrier/chunk — build(c+1),
//      agg(c-1) and pairGEMM(c) run concurrently per warp. M1/m2T double-
//      buffered, S triple-buffered.

#define NB 512
#define NT 1024
typedef unsigned int u32;
typedef unsigned short u16;

// global fragment buffer: 14 big Ws (16384 u32 each) + W_in (2048)
__device__ u32 g_wfrag[14 * 16384 + 2048];
#define WIN_BASE (14 * 16384)

// ---- shared memory layout (u32 word offsets) ----
#define O_HGH 0        // hg split: 32 x 68
#define O_HGL 2176
#define O_MIF 4352     // mi f32: 32 x 132
#define O_MJF 8576     // mj f32: 32 x 132
#define O_AGH 12800    // agg split: 32 x 68
#define O_AGL 14976
#define O_M1H 17152    // m1 split: 2 bufs x 32 x 68
#define O_M1L 21504
#define O_HTH 25856    // h input split: 32 x 8
#define O_HTL 26112
#define O_WF  26368    // W fragments: hi 8192 + lo 8192
#define O_M2TH 42752   // m2 B-frag hi: 2 bufs x (128 cols x 20)
#define O_M2TL 47872
#define O_S   52992    // S selection: 3 bufs x (32 rows x 20)
#define O_D2  54912
#define O_EDGE 55936
#define O_WD  56960
#define O_BE2 57088
#define O_RMASK 57216
#define O_ROFF 57248
#define O_X   57280
#define O_RED 57376
#define O_NE  57392
#define SM_WORDS 57396

__device__ __forceinline__ float silu_f(float v) {
    return __fdividef(v, 1.0f + __expf(-v));
}
__device__ __forceinline__ u32 packbf(float x0, float x1) {
    u32 r;
    asm("cvt.rn.bf16x2.f32 %0, %1, %2;" : "=r"(r) : "f"(x1), "f"(x0));
    return r;
}
__device__ __forceinline__ void split2(float x0, float x1, u32& h, u32& l) {
    h = packbf(x0, x1);
    float r0 = x0 - __uint_as_float(h << 16);
    float r1 = x1 - __uint_as_float(h & 0xffff0000u);
    l = packbf(r0, r1);
}
__device__ __forceinline__ float2 ldpair(const u32* Xh, const u32* Xl, int idx) {
    u32 h = Xh[idx], l = Xl[idx];
    float2 v;
    v.x = __uint_as_float(h << 16) + __uint_as_float(l << 16);
    v.y = __uint_as_float(h & 0xffff0000u) + __uint_as_float(l & 0xffff0000u);
    return v;
}
__device__ __forceinline__ void stpair(u32* Xh, u32* Xl, int idx, float v0, float v1) {
    u32 h, l; split2(v0, v1, h, l);
    Xh[idx] = h; Xl[idx] = l;
}

__device__ __forceinline__ void mma4(float d[4], const u32 a[4], u32 b0, u32 b1) {
    asm volatile("mma.sync.aligned.m16n8k16.row.col.f32.bf16.bf16.f32 "
        "{%0,%1,%2,%3}, {%4,%5,%6,%7}, {%8,%9}, {%0,%1,%2,%3};"
        : "+f"(d[0]), "+f"(d[1]), "+f"(d[2]), "+f"(d[3])
        : "r"(a[0]), "r"(a[1]), "r"(a[2]), "r"(a[3]), "r"(b0), "r"(b1));
}

__device__ __forceinline__ void ldAf(const u32* X, int rs, int r0, int kt,
                                     int lane, u32 a[4]) {
    int gid = lane >> 2, tig = lane & 3;
    const u32* p = X + (r0 + gid) * rs + kt * 8 + tig;
    a[0] = p[0];
    a[2] = p[4];
    a[1] = p[8 * rs];
    a[3] = p[8 * rs + 4];
}

// 3-term GEMM, ONE n-tile per warp, kt range [kt0, kt1)
__device__ __forceinline__ void gemm_mma(const u32* Xh, const u32* Xl, int rs,
                                         const u32* sWF, int r0, int nt,
                                         int lane, int kt0, int kt1, float D[4]) {
    #pragma unroll 1
    for (int kt = kt0; kt < kt1; kt++) {
        u32 ah[4], al[4];
        ldAf(Xh, rs, r0, kt, lane, ah);
        ldAf(Xl, rs, r0, kt, lane, al);
        const u32* bp = sWF + ((kt * 16 + nt) * 32 + lane) * 2;
        u32 bh0 = bp[0], bh1 = bp[1];
        u32 bl0 = bp[8192], bl1 = bp[8193];
        mma4(D, ah, bh0, bh1);
        mma4(D, ah, bl0, bl1);
        mma4(D, al, bh0, bh1);
    }
}

__device__ __forceinline__ void cp16(unsigned saddr, const void* g) {
    asm volatile("cp.async.cg.shared.global [%0], [%1], 16;" :: "r"(saddr), "l"(g));
}
#define CP_COMMIT() asm volatile("cp.async.commit_group;")
#define CP_WAIT0()  asm volatile("cp.async.wait_group 0;" ::: "memory")
#define CP_WAIT1()  asm volatile("cp.async.wait_group 1;" ::: "memory")

__device__ __forceinline__ void stage_cp(const u32* __restrict__ g, u32* s,
                                         int nf4, int tid) {
    unsigned sa = (unsigned)__cvta_generic_to_shared(s);
    for (int v = tid; v < nf4; v += NT)
        cp16(sa + v * 16, g + v * 4);
}

__device__ __forceinline__ void stage_W_halves(const u32* __restrict__ F,
                                               u32* WF, int tid) {
    stage_cp(F, WF, 1024, tid);
    stage_cp(F + 8192, WF + 8192, 1024, tid);
    CP_COMMIT();
    stage_cp(F + 4096, WF + 4096, 1024, tid);
    stage_cp(F + 12288, WF + 12288, 1024, tid);
    CP_COMMIT();
}

// write one f32 value into the hi/lo B-fragment m2 buffers at (col c, edge r)
__device__ __forceinline__ void write_m2t(u32* M2THb, u32* M2TLb, int c, int r, float v) {
    u32 hp = packbf(v, 0.0f);
    float hf = __uint_as_float(hp << 16);
    u32 lp = packbf(v - hf, 0.0f);
    int wi = (c * 20 + (r >> 1)) * 2 + (r & 1);
    ((u16*)M2THb)[wi] = (u16)hp;
    ((u16*)M2TLb)[wi] = (u16)lp;
}

// build one 32-edge chunk of m1 (split) — one warp per edge, 4 cols/lane
__device__ __forceinline__ void build_chunk(int e0, int nE, const int* s_edge,
                                            const float* s_d2, const float* miF,
                                            const float* mjF, const float* s_wd,
                                            u32* M1Hb, u32* M1Lb, int tid) {
    int e = tid >> 5, cq = (tid & 31) * 4;
    int ee = e0 + e;
    int ij = s_edge[ee < nE ? ee : nE - 1];
    int i = ij >> 5, j = ij & 31;
    float dd = s_d2[ij];
    float4 a = *(const float4*)&miF[i * 132 + cq];
    float4 bb = *(const float4*)&mjF[j * 132 + cq];
    float4 w = *(const float4*)&s_wd[cq];
    float v0 = silu_f(a.x + bb.x + dd * w.x);
    float v1 = silu_f(a.y + bb.y + dd * w.y);
    float v2 = silu_f(a.z + bb.z + dd * w.z);
    float v3 = silu_f(a.w + bb.w + dd * w.w);
    u32 h0, l0, h1, l1;
    split2(v0, v1, h0, l0);
    split2(v2, v3, h1, l1);
    *(uint2*)&M1Hb[e * 68 + (cq >> 1)] = make_uint2(h0, h1);
    *(uint2*)&M1Lb[e * 68 + (cq >> 1)] = make_uint2(l0, l1);
}

// build S selection matrix for one chunk
__device__ __forceinline__ void build_S(int e0, int nE, const int* s_edge,
                                        u32* Sb, int tid) {
    if (tid < 512) {
        int i = tid >> 4, ep = tid & 15;
        int ea = e0 + 2 * ep, eb = ea + 1;
        int ia = (ea < nE) ? (s_edge[ea] >> 5) : -1;
        int ib = (eb < nE) ? (s_edge[eb] >> 5) : -1;
        u32 val = (ia == i ? 0x00003F80u : 0u) | (ib == i ? 0x3F800000u : 0u);
        Sb[i * 20 + ep] = val;
    }
}

// agg += S @ (m2h + m2l)
__device__ __forceinline__ void agg_mma(const u32* Sp, const u32* m2h,
                                        const u32* m2l, int rt, int nt,
                                        int lane, float Dagg[4]) {
    #pragma unroll
    for (int kt = 0; kt < 2; kt++) {
        u32 a[4];
        ldAf(Sp, 20, rt * 16, kt, lane, a);
        int cB = nt * 8 + (lane >> 2);
        const u32* bh = m2h + cB * 20 + kt * 8 + (lane & 3);
        const u32* bl = m2l + cB * 20 + kt * 8 + (lane & 3);
        mma4(Dagg, a, bh[0], bh[4]);
        mma4(Dagg, a, bl[0], bl[4]);
    }
}

// ================= prep kernel: weights -> fragment hi/lo layout =============
__global__ void prep_kernel(const float* __restrict__ We1,
                            const float* __restrict__ We2,
                            const float* __restrict__ Wh1,
                            const float* __restrict__ Wh2,
                            const float* __restrict__ W_out,
                            const float* __restrict__ Wn1,
                            const float* __restrict__ W_in) {
    int y = blockIdx.y;
    int u = blockIdx.x * 256 + threadIdx.x;
    if (y < 14) {
        const float* src;
        if (y < 12) {
            int l = y / 6, w = y % 6;
            switch (w) {
                case 0: src = We1 + l * 257 * 128; break;
                case 1: src = We1 + l * 257 * 128 + 16384; break;
                case 2: src = We2 + l * 16384; break;
                case 3: src = Wh1 + l * 32768; break;
                case 4: src = Wh1 + l * 32768 + 16384; break;
                default: src = Wh2 + l * 16384; break;
            }
        } else {
            src = (y == 12) ? W_out : Wn1;
        }
        int p = u >> 7, c = u & 127;
        float w0 = src[(2 * p) * 128 + c];
        float w1 = src[(2 * p + 1) * 128 + c];
        int kt = p >> 3, pr = p & 7;
        int cpp = pr & 3, reg = pr >> 2;
        int lane = (c & 7) * 4 + cpp;
        int nt = c >> 3;
        int dst = y * 16384 + ((kt * 16 + nt) * 32 + lane) * 2 + reg;
        u32 h, l2; split2(w0, w1, h, l2);
        g_wfrag[dst] = h;
        g_wfrag[dst + 8192] = l2;
    } else {
        if (u >= 1024) return;
        int p = u >> 7, c = u & 127;
        float w0 = W_in[(2 * p) * 128 + c];
        float w1 = W_in[(2 * p + 1) * 128 + c];
        int cpp = p & 3, reg = p >> 2;
        int lane = (c & 7) * 4 + cpp;
        int nt = c >> 3;
        int dst = WIN_BASE + ((nt * 32 + lane) * 2 + reg);
        u32 h, l2; split2(w0, w1, h, l2);
        g_wfrag[dst] = h;
        g_wfrag[dst + 1024] = l2;
    }
}

// ================================ main kernel ================================
__global__ void __launch_bounds__(NT, 1)
sake_kernel(const float* __restrict__ g_h, const float* __restrict__ g_x,
            const float* __restrict__ b_in,
            const float* __restrict__ We1, const float* __restrict__ be1,
            const float* __restrict__ be2,
            const float* __restrict__ bh1, const float* __restrict__ bh2,
            const float* __restrict__ b_out,
            const float* __restrict__ bn1,
            const float* __restrict__ Wn2, const float* __restrict__ bn2,
            float* __restrict__ g_out)
{
    extern __shared__ u32 smu[];
    u32* HGH = smu + O_HGH;  u32* HGL = smu + O_HGL;
    float* miF = (float*)(smu + O_MIF);
    float* mjF = (float*)(smu + O_MJF);
    u32* AGH = smu + O_AGH;  u32* AGL = smu + O_AGL;
    u32* M1H = smu + O_M1H;  u32* M1L = smu + O_M1L;
    u32* HTH = smu + O_HTH;  u32* HTL = smu + O_HTL;
    u32* WF  = smu + O_WF;
    u32* M2TH = smu + O_M2TH;
    u32* M2TL = smu + O_M2TL;
    u32* Sbuf = smu + O_S;
    float* s_d2   = (float*)(smu + O_D2);
    int*   s_edge = (int*)(smu + O_EDGE);
    float* s_wd   = (float*)(smu + O_WD);
    float* s_be2  = (float*)(smu + O_BE2);
    u32*   s_rmask = smu + O_RMASK;
    int*   s_roff  = (int*)(smu + O_ROFF);
    float* s_x    = (float*)(smu + O_X);
    float* s_red  = (float*)(smu + O_RED);
    int*   s_ne   = (int*)(smu + O_NE);

    const int tid  = threadIdx.x;
    const int warp = tid >> 5;          // 0..31
    const int lane = tid & 31;
    const int gid  = lane >> 2;
    const int tig  = lane & 3;
    const int b    = blockIdx.x;
    const int rt   = warp & 1;          // row tile
    const int nt   = warp >> 1;         // single n-tile (0..15)
    const int r0   = rt * 16 + gid;
    const int c0   = nt * 8 + 2 * tig;
    const int cpi  = c0 >> 1;

    // ---- prologue: x, split h, stage W_in frags ----
    if (tid < 96) s_x[tid] = g_x[b * 96 + tid];
    if (tid < 256) {
        int r = tid >> 3, cp = tid & 7;
        float2 hv = *(const float2*)&g_h[b * 512 + r * 16 + cp * 2];
        u32 h, l; split2(hv.x, hv.y, h, l);
        HTH[r * 8 + cp] = h; HTL[r * 8 + cp] = l;
    }
    stage_cp(g_wfrag + WIN_BASE, WF, 256, tid);
    stage_cp(g_wfrag + WIN_BASE + 1024, WF + 8192, 256, tid);
    CP_COMMIT();
    __syncthreads();

    // ---- d2 ----
    for (int p = tid; p < 1024; p += NT) {
        int i = p >> 5, j = p & 31;
        float dx = s_x[i * 3 + 0] - s_x[j * 3 + 0];
        float dy = s_x[i * 3 + 1] - s_x[j * 3 + 1];
        float dz = s_x[i * 3 + 2] - s_x[j * 3 + 2];
        s_d2[p] = dx * dx + dy * dy + dz * dz;
    }
    __syncthreads();

    // ---- adjacency masks: warp w owns node w ----
    {
        bool adj = (s_d2[warp * 32 + lane] < 1.0f) && (lane != warp);
        unsigned m = __ballot_sync(0xffffffffu, adj);
        if (lane == 0) s_rmask[warp] = m;
    }
    CP_WAIT0();
    __syncthreads();

    // ---- hg = h @ W_in + b_in ----
    {
        float D[4] = {};
        gemm_mma(HTH, HTL, 8, WF, rt * 16, nt, lane, 0, 1, D);
        float b0 = b_in[c0], b1 = b_in[c0 + 1];
        stpair(HGH, HGL, r0 * 68 + cpi,       D[0] + b0, D[1] + b1);
        stpair(HGH, HGL, (r0 + 8) * 68 + cpi, D[2] + b0, D[3] + b1);
    }

    // ---- edge-list scan ----
    __syncthreads();
    if (warp == 0) {
        unsigned m = s_rmask[lane];
        int c = __popc(m);
        int inc = c;
        #pragma unroll
        for (int d = 1; d < 32; d <<= 1) {
            int n = __shfl_up_sync(0xffffffffu, inc, d);
            if (lane >= d) inc += n;
        }
        s_roff[lane] = inc - c;
        if (lane == 31) *s_ne = inc;
    }
    __syncthreads();
    {
        unsigned m = s_rmask[warp];
        if ((m >> lane) & 1u) {
            int pos = s_roff[warp] + __popc(m & ((1u << lane) - 1u));
            s_edge[pos] = (warp << 5) | lane;
        }
    }
    __syncthreads();
    const int nE = *s_ne;
    const int nCh = (nE + 31) >> 5;

    // ---- layers ----
    #pragma unroll 1
    for (int l = 0; l < 2; l++) {
        const u32* F_e1a = g_wfrag + (l * 6 + 0) * 16384;
        const u32* F_e1b = g_wfrag + (l * 6 + 1) * 16384;
        const u32* F_e2  = g_wfrag + (l * 6 + 2) * 16384;
        const u32* F_h1a = g_wfrag + (l * 6 + 3) * 16384;
        const u32* F_h1b = g_wfrag + (l * 6 + 4) * 16384;
        const u32* F_h2  = g_wfrag + (l * 6 + 5) * 16384;
        const float* We1l = We1 + l * (257 * 128);

        // mi = hg @ We1a + be1 -> miF
        stage_W_halves(F_e1a, WF, tid);
        CP_WAIT1(); __syncthreads();
        {
            float D[4] = {};
            gemm_mma(HGH, HGL, 68, WF, rt * 16, nt, lane, 0, 4, D);
            CP_WAIT0(); __syncthreads();
            gemm_mma(HGH, HGL, 68, WF, rt * 16, nt, lane, 4, 8, D);
            float b0 = be1[l * 128 + c0], b1 = be1[l * 128 + c0 + 1];
            *(float2*)&miF[r0 * 132 + c0]       = make_float2(D[0] + b0, D[1] + b1);
            *(float2*)&miF[(r0 + 8) * 132 + c0] = make_float2(D[2] + b0, D[3] + b1);
        }
        __syncthreads();

        // mj = hg @ We1b -> mjF
        stage_W_halves(F_e1b, WF, tid);
        CP_WAIT1(); __syncthreads();
        {
            float D[4] = {};
            gemm_mma(HGH, HGL, 68, WF, rt * 16, nt, lane, 0, 4, D);
            CP_WAIT0(); __syncthreads();
            gemm_mma(HGH, HGL, 68, WF, rt * 16, nt, lane, 4, 8, D);
            *(float2*)&mjF[r0 * 132 + c0]       = make_float2(D[0], D[1]);
            *(float2*)&mjF[(r0 + 8) * 132 + c0] = make_float2(D[2], D[3]);
        }
        __syncthreads();

        // stage We2; wd, be2
        stage_W_halves(F_e2, WF, tid);
        if (tid < 128) {
            s_wd[tid]  = We1l[256 * 128 + tid];
            s_be2[tid] = be2[l * 128 + tid];
        }
        CP_WAIT0();
        __syncthreads();

        // ---- pair phase: pipelined, ONE barrier per 32-edge chunk ----
        float Dagg[4] = { 0.f, 0.f, 0.f, 0.f };
        if (nE > 0) {
            build_chunk(0, nE, s_edge, s_d2, miF, mjF, s_wd, M1H, M1L, tid);
            build_S(0, nE, s_edge, Sbuf, tid);
        }
        __syncthreads();
        #pragma unroll 1
        for (int c = 0; c < nCh; c++) {
            const int cur = c & 1;
            // build chunk c+1 (independent of GEMM(c) and agg(c-1))
            if (c + 1 < nCh) {
                const int nx = cur ^ 1;
                build_chunk((c + 1) * 32, nE, s_edge, s_d2, miF, mjF, s_wd,
                            M1H + nx * 2176, M1L + nx * 2176, tid);
                build_S((c + 1) * 32, nE, s_edge, Sbuf + ((c + 1) % 3) * 640, tid);
            }
            // agg for chunk c-1
            if (c > 0) {
                const int pv = cur ^ 1;
                agg_mma(Sbuf + ((c - 1) % 3) * 640, M2TH + pv * 2560,
                        M2TL + pv * 2560, rt, nt, lane, Dagg);
            }
            // pair GEMM chunk c + silu -> m2T[cur]
            {
                float D[4] = {};
                gemm_mma(M1H + cur * 2176, M1L + cur * 2176, 68, WF,
                         rt * 16, nt, lane, 0, 8, D);
                float b0 = s_be2[c0], b1 = s_be2[c0 + 1];
                u32* m2h = M2TH + cur * 2560;
                u32* m2l = M2TL + cur * 2560;
                write_m2t(m2h, m2l, c0,     r0,     silu_f(D[0] + b0));
                write_m2t(m2h, m2l, c0 + 1, r0,     silu_f(D[1] + b1));
                write_m2t(m2h, m2l, c0,     r0 + 8, silu_f(D[2] + b0));
                write_m2t(m2h, m2l, c0 + 1, r0 + 8, silu_f(D[3] + b1));
            }
            __syncthreads();
        }
        if (nE > 0) {   // agg for the last chunk
            const int lc = nCh - 1, pv = lc & 1;
            agg_mma(Sbuf + (lc % 3) * 640, M2TH + pv * 2560, M2TL + pv * 2560,
                    rt, nt, lane, Dagg);
        }

        // write agg registers -> AG split arrays; stage Wh1a
        stage_W_halves(F_h1a, WF, tid);
        stpair(AGH, AGL, r0 * 68 + cpi,       Dagg[0], Dagg[1]);
        stpair(AGH, AGL, (r0 + 8) * 68 + cpi, Dagg[2], Dagg[3]);
        CP_WAIT0();
        __syncthreads();

        // u = silu(hg @ Wh1a + agg @ Wh1b + bh1) -> M1 (split, buf0)
        float D[4] = {};
        gemm_mma(HGH, HGL, 68, WF, rt * 16, nt, lane, 0, 8, D);
        __syncthreads();
        stage_W_halves(F_h1b, WF, tid);
        CP_WAIT0();
        __syncthreads();
        gemm_mma(AGH, AGL, 68, WF, rt * 16, nt, lane, 0, 8, D);
        {
            float b0 = bh1[l * 128 + c0], b1 = bh1[l * 128 + c0 + 1];
            stpair(M1H, M1L, r0 * 68 + cpi,
                   silu_f(D[0] + b0), silu_f(D[1] + b1));
            stpair(M1H, M1L, (r0 + 8) * 68 + cpi,
                   silu_f(D[2] + b0), silu_f(D[3] + b1));
        }
        __syncthreads();

        // hg += u @ Wh2 + bh2
        stage_W_halves(F_h2, WF, tid);
        CP_WAIT1(); __syncthreads();
        {
            float D2[4] = {};
            gemm_mma(M1H, M1L, 68, WF, rt * 16, nt, lane, 0, 4, D2);
            CP_WAIT0(); __syncthreads();
            gemm_mma(M1H, M1L, 68, WF, rt * 16, nt, lane, 4, 8, D2);
            float b0 = bh2[l * 128 + c0], b1 = bh2[l * 128 + c0 + 1];
            float2 h0 = ldpair(HGH, HGL, r0 * 68 + cpi);
            stpair(HGH, HGL, r0 * 68 + cpi, h0.x + D2[0] + b0, h0.y + D2[1] + b1);
            float2 h1 = ldpair(HGH, HGL, (r0 + 8) * 68 + cpi);
            stpair(HGH, HGL, (r0 + 8) * 68 + cpi, h1.x + D2[2] + b0, h1.y + D2[3] + b1);
        }
        __syncthreads();
    }

    // ---- head: ho = hg @ W_out + b_out -> M1 (split, buf0) ----
    stage_W_halves(g_wfrag + 12 * 16384, WF, tid);
    CP_WAIT1(); __syncthreads();
    {
        float D[4] = {};
        gemm_mma(HGH, HGL, 68, WF, rt * 16, nt, lane, 0, 4, D);
        CP_WAIT0(); __syncthreads();
        gemm_mma(HGH, HGL, 68, WF, rt * 16, nt, lane, 4, 8, D);
        float b0 = b_out[c0], b1 = b_out[c0 + 1];
        stpair(M1H, M1L, r0 * 68 + cpi,       D[0] + b0, D[1] + b1);
        stpair(M1H, M1L, (r0 + 8) * 68 + cpi, D[2] + b0, D[3] + b1);
    }
    __syncthreads();

    // t1 = silu(ho @ Wn1 + bn1) -> miF (f32)
    stage_W_halves(g_wfrag + 13 * 16384, WF, tid);
    CP_WAIT1(); __syncthreads();
    {
        float D[4] = {};
        gemm_mma(M1H, M1L, 68, WF, rt * 16, nt, lane, 0, 4, D);
        CP_WAIT0(); __syncthreads();
        gemm_mma(M1H, M1L, 68, WF, rt * 16, nt, lane, 4, 8, D);
        float b0 = bn1[c0], b1 = bn1[c0 + 1];
        *(float2*)&miF[r0 * 132 + c0] =
            make_float2(silu_f(D[0] + b0), silu_f(D[1] + b1));
        *(float2*)&miF[(r0 + 8) * 132 + c0] =
            make_float2(silu_f(D[2] + b0), silu_f(D[3] + b1));
    }
    __syncthreads();

    // ---- out[b] = (colsum t1) . Wn2 + 32*bn2 ----
    float part = 0.0f;
    if (tid < 128) {
        int c = tid;
        float s = 0.0f;
        #pragma unroll 1
        for (int i = 0; i < 32; i++) s += miF[i * 132 + c];
        part = s * Wn2[c];
    }
    #pragma unroll
    for (int off = 16; off > 0; off >>= 1)
        part += __shfl_down_sync(0xffffffffu, part, off);
    if (warp < 4 && lane == 0) s_red[warp] = part;
    __syncthreads();
    if (tid == 0)
        g_out[b] = s_red[0] + s_red[1] + s_red[2] + s_red[3] + 32.0f * bn2[0];
}

extern "C" void kernel_launch(void* const* d_in, const int* in_sizes, int n_in,
                              void* d_out, int out_size) {
    const float* g_h   = (const float*)d_in[0];
    const float* g_x   = (const float*)d_in[1];
    const float* W_in  = (const float*)d_in[3];
    const float* b_in  = (const float*)d_in[4];
    const float* We1   = (const float*)d_in[5];
    const float* be1   = (const float*)d_in[6];
    const float* We2   = (const float*)d_in[7];
    const float* be2   = (const float*)d_in[8];
    const float* Wh1   = (const float*)d_in[9];
    const float* bh1   = (const float*)d_in[10];
    const float* Wh2   = (const float*)d_in[11];
    const float* bh2   = (const float*)d_in[12];
    const float* W_out = (const float*)d_in[13];
    const float* b_out = (const float*)d_in[14];
    const float* Wn1   = (const float*)d_in[15];
    const float* bn1   = (const float*)d_in[16];
    const float* Wn2   = (const float*)d_in[17];
    const float* bn2   = (const float*)d_in[18];
    float* out = (float*)d_out;

    prep_kernel<<<dim3(32, 15), 256>>>(We1, We2, Wh1, Wh2, W_out, Wn1, W_in);

    const int smem_bytes = SM_WORDS * 4;
    cudaFuncSetAttribute(sake_kernel, cudaFuncAttributeMaxDynamicSharedMemorySize,
                         smem_bytes);
    sake_kernel<<<NB, NT, smem_bytes>>>(
        g_h, g_x, b_in, We1, be1, be2, bh1, bh2, b_out, bn1, Wn2, bn2, out);
}

// round 12
// speedup vs baseline: 1.8217x; 1.0001x over previous
#include <cuda_runtime.h>

// SAKE GNN fully fused, one CTA per graph (B=512, M=32, H=128, L=2).
// R12: ldmatrix.x4 for all A/S fragment loads (8 LDS -> 2 LDSM per kt),
//      LDS.64 for B hi/lo pairs — ~20% fewer issue slots at identical math.

#define NB 512
#define NT 1024
typedef unsigned int u32;
typedef unsigned short u16;

// global fragment buffer: 14 big Ws (16384 u32 each) + W_in (2048)
__device__ u32 g_wfrag[14 * 16384 + 2048];
#define WIN_BASE (14 * 16384)

// ---- shared memory layout (u32 word offsets) ----
#define O_HGH 0        // hg split: 32 x 68
#define O_HGL 2176
#define O_MIF 4352     // mi f32: 32 x 132
#define O_MJF 8576     // mj f32: 32 x 132
#define O_AGH 12800    // agg split: 32 x 68
#define O_AGL 14976
#define O_M1H 17152    // m1 split: 2 bufs x 32 x 68
#define O_M1L 21504
#define O_HTH 25856    // h input split: 32 x 8
#define O_HTL 26112
#define O_WF  26368    // W fragments: hi 8192 + lo 8192
#define O_M2TH 42752   // m2 B-frag hi: 2 bufs x (128 cols x 20)
#define O_M2TL 47872
#define O_S   52992    // S selection: 3 bufs x (32 rows x 20)
#define O_D2  54912
#define O_EDGE 55936
#define O_WD  56960
#define O_BE2 57088
#define O_RMASK 57216
#define O_ROFF 57248
#define O_X   57280
#define O_RED 57376
#define O_NE  57392
#define SM_WORDS 57396

__device__ __forceinline__ float silu_f(float v) {
    return __fdividef(v, 1.0f + __expf(-v));
}
__device__ __forceinline__ u32 packbf(float x0, float x1) {
    u32 r;
    asm("cvt.rn.bf16x2.f32 %0, %1, %2;" : "=r"(r) : "f"(x1), "f"(x0));
    return r;
}
__device__ __forceinline__ void split2(float x0, float x1, u32& h, u32& l) {
    h = packbf(x0, x1);
    float r0 = x0 - __uint_as_float(h << 16);
    float r1 = x1 - __uint_as_float(h & 0xffff0000u);
    l = packbf(r0, r1);
}
__device__ __forceinline__ float2 ldpair(const u32* Xh, const u32* Xl, int idx) {
    u32 h = Xh[idx], l = Xl[idx];
    float2 v;
    v.x = __uint_as_float(h << 16) + __uint_as_float(l << 16);
    v.y = __uint_as_float(h & 0xffff0000u) + __uint_as_float(l & 0xffff0000u);
    return v;
}
__device__ __forceinline__ void stpair(u32* Xh, u32* Xl, int idx, float v0, float v1) {
    u32 h, l; split2(v0, v1, h, l);
    Xh[idx] = h; Xl[idx] = l;
}

__device__ __forceinline__ void mma4(float d[4], const u32 a[4], u32 b0, u32 b1) {
    asm volatile("mma.sync.aligned.m16n8k16.row.col.f32.bf16.bf16.f32 "
        "{%0,%1,%2,%3}, {%4,%5,%6,%7}, {%8,%9}, {%0,%1,%2,%3};"
        : "+f"(d[0]), "+f"(d[1]), "+f"(d[2]), "+f"(d[3])
        : "r"(a[0]), "r"(a[1]), "r"(a[2]), "r"(a[3]), "r"(b0), "r"(b1));
}

__device__ __forceinline__ u32 smaddr(const void* p) {
    return (u32)__cvta_generic_to_shared(p);
}
#define LDSM4(d, a) \
    asm volatile("ldmatrix.sync.aligned.m8n8.x4.shared.b16 {%0,%1,%2,%3}, [%4];" \
        : "=r"((d)[0]), "=r"((d)[1]), "=r"((d)[2]), "=r"((d)[3]) : "r"(a))

// 3-term GEMM, ONE n-tile per warp, kt range [kt0, kt1); A via ldmatrix.
// Lane address for tile t (t = lane>>3): row = r0 + (t&1)*8 + (lane&7),
// col-offset (t>>1)*4 u32; advances 32 bytes per kt.
__device__ __forceinline__ void gemm_mma(const u32* Xh, const u32* Xl, int rs,
                                         const u32* sWF, int r0, int nt,
                                         int lane, int kt0, int kt1, float D[4]) {
    int t = lane >> 3, rowin = lane & 7;
    int off = (r0 + ((t & 1) << 3) + rowin) * rs + ((t >> 1) << 2);
    u32 baseH = smaddr(Xh + off);
    u32 baseL = smaddr(Xl + off);
    #pragma unroll 1
    for (int kt = kt0; kt < kt1; kt++) {
        u32 ah[4], al[4];
        LDSM4(ah, baseH + kt * 32);
        LDSM4(al, baseL + kt * 32);
        const u32* bp = sWF + ((kt * 16 + nt) * 32 + lane) * 2;
        uint2 bh = *(const uint2*)bp;
        uint2 bl = *(const uint2*)(bp + 8192);
        mma4(D, ah, bh.x, bh.y);
        mma4(D, ah, bl.x, bl.y);
        mma4(D, al, bh.x, bh.y);
    }
}

__device__ __forceinline__ void cp16(unsigned saddr, const void* g) {
    asm volatile("cp.async.cg.shared.global [%0], [%1], 16;" :: "r"(saddr), "l"(g));
}
#define CP_COMMIT() asm volatile("cp.async.commit_group;")
#define CP_WAIT0()  asm volatile("cp.async.wait_group 0;" ::: "memory")
#define CP_WAIT1()  asm volatile("cp.async.wait_group 1;" ::: "memory")

__device__ __forceinline__ void stage_cp(const u32* __restrict__ g, u32* s,
                                         int nf4, int tid) {
    unsigned sa = (unsigned)__cvta_generic_to_shared(s);
    for (int v = tid; v < nf4; v += NT)
        cp16(sa + v * 16, g + v * 4);
}

__device__ __forceinline__ void stage_W_halves(const u32* __restrict__ F,
                                               u32* WF, int tid) {
    stage_cp(F, WF, 1024, tid);
    stage_cp(F + 8192, WF + 8192, 1024, tid);
    CP_COMMIT();
    stage_cp(F + 4096, WF + 4096, 1024, tid);
    stage_cp(F + 12288, WF + 12288, 1024, tid);
    CP_COMMIT();
}

// write one f32 value into the hi/lo B-fragment m2 buffers at (col c, edge r)
__device__ __forceinline__ void write_m2t(u32* M2THb, u32* M2TLb, int c, int r, float v) {
    u32 hp = packbf(v, 0.0f);
    float hf = __uint_as_float(hp << 16);
    u32 lp = packbf(v - hf, 0.0f);
    int wi = (c * 20 + (r >> 1)) * 2 + (r & 1);
    ((u16*)M2THb)[wi] = (u16)hp;
    ((u16*)M2TLb)[wi] = (u16)lp;
}

// build one 32-edge chunk of m1 (split) — one warp per edge, 4 cols/lane
__device__ __forceinline__ void build_chunk(int e0, int nE, const int* s_edge,
                                            const float* s_d2, const float* miF,
                                            const float* mjF, const float* s_wd,
                                            u32* M1Hb, u32* M1Lb, int tid) {
    int e = tid >> 5, cq = (tid & 31) * 4;
    int ee = e0 + e;
    int ij = s_edge[ee < nE ? ee : nE - 1];
    int i = ij >> 5, j = ij & 31;
    float dd = s_d2[ij];
    float4 a = *(const float4*)&miF[i * 132 + cq];
    float4 bb = *(const float4*)&mjF[j * 132 + cq];
    float4 w = *(const float4*)&s_wd[cq];
    float v0 = silu_f(a.x + bb.x + dd * w.x);
    float v1 = silu_f(a.y + bb.y + dd * w.y);
    float v2 = silu_f(a.z + bb.z + dd * w.z);
    float v3 = silu_f(a.w + bb.w + dd * w.w);
    u32 h0, l0, h1, l1;
    split2(v0, v1, h0, l0);
    split2(v2, v3, h1, l1);
    *(uint2*)&M1Hb[e * 68 + (cq >> 1)] = make_uint2(h0, h1);
    *(uint2*)&M1Lb[e * 68 + (cq >> 1)] = make_uint2(l0, l1);
}

// build S selection matrix for one chunk
__device__ __forceinline__ void build_S(int e0, int nE, const int* s_edge,
                                        u32* Sb, int tid) {
    if (tid < 512) {
        int i = tid >> 4, ep = tid & 15;
        int ea = e0 + 2 * ep, eb = ea + 1;
        int ia = (ea < nE) ? (s_edge[ea] >> 5) : -1;
        int ib = (eb < nE) ? (s_edge[eb] >> 5) : -1;
        u32 val = (ia == i ? 0x00003F80u : 0u) | (ib == i ? 0x3F800000u : 0u);
        Sb[i * 20 + ep] = val;
    }
}

// agg += S @ (m2h + m2l); S via ldmatrix
__device__ __forceinline__ void agg_mma(const u32* Sp, const u32* m2h,
                                        const u32* m2l, int rt, int nt,
                                        int lane, float Dagg[4]) {
    int t = lane >> 3, rowin = lane & 7;
    u32 baseS = smaddr(Sp + (rt * 16 + ((t & 1) << 3) + rowin) * 20 + ((t >> 1) << 2));
    #pragma unroll
    for (int kt = 0; kt < 2; kt++) {
        u32 a[4];
        LDSM4(a, baseS + kt * 32);
        int cB = nt * 8 + (lane >> 2);
        const u32* bh = m2h + cB * 20 + kt * 8 + (lane & 3);
        const u32* bl = m2l + cB * 20 + kt * 8 + (lane & 3);
        mma4(Dagg, a, bh[0], bh[4]);
        mma4(Dagg, a, bl[0], bl[4]);
    }
}

// ================= prep kernel: weights -> fragment hi/lo layout =============
__global__ void prep_kernel(const float* __restrict__ We1,
                            const float* __restrict__ We2,
                            const float* __restrict__ Wh1,
                            const float* __restrict__ Wh2,
                            const float* __restrict__ W_out,
                            const float* __restrict__ Wn1,
                            const float* __restrict__ W_in) {
    int y = blockIdx.y;
    int u = blockIdx.x * 256 + threadIdx.x;
    if (y < 14) {
        const float* src;
        if (y < 12) {
            int l = y / 6, w = y % 6;
            switch (w) {
                case 0: src = We1 + l * 257 * 128; break;
                case 1: src = We1 + l * 257 * 128 + 16384; break;
                case 2: src = We2 + l * 16384; break;
                case 3: src = Wh1 + l * 32768; break;
                case 4: src = Wh1 + l * 32768 + 16384; break;
                default: src = Wh2 + l * 16384; break;
            }
        } else {
            src = (y == 12) ? W_out : Wn1;
        }
        int p = u >> 7, c = u & 127;
        float w0 = src[(2 * p) * 128 + c];
        float w1 = src[(2 * p + 1) * 128 + c];
        int kt = p >> 3, pr = p & 7;
        int cpp = pr & 3, reg = pr >> 2;
        int lane = (c & 7) * 4 + cpp;
        int nt = c >> 3;
        int dst = y * 16384 + ((kt * 16 + nt) * 32 + lane) * 2 + reg;
        u32 h, l2; split2(w0, w1, h, l2);
        g_wfrag[dst] = h;
        g_wfrag[dst + 8192] = l2;
    } else {
        if (u >= 1024) return;
        int p = u >> 7, c = u & 127;
        float w0 = W_in[(2 * p) * 128 + c];
        float w1 = W_in[(2 * p + 1) * 128 + c];
        int cpp = p & 3, reg = p >> 2;
        int lane = (c & 7) * 4 + cpp;
        int nt = c >> 3;
        int dst = WIN_BASE + ((nt * 32 + lane) * 2 + reg);
        u32 h, l2; split2(w0, w1, h, l2);
        g_wfrag[dst] = h;
        g_wfrag[dst + 1024] = l2;
    }
}

// ================================ main kernel ================================
__global__ void __launch_bounds__(NT, 1)
sake_kernel(const float* __restrict__ g_h, const float* __restrict__ g_x,
            const float* __restrict__ b_in,
            const float* __restrict__ We1, const float* __restrict__ be1,
            const float* __restrict__ be2,
            const float* __restrict__ bh1, const float* __restrict__ bh2,
            const float* __restrict__ b_out,
            const float* __restrict__ bn1,
            const float* __restrict__ Wn2, const float* __restrict__ bn2,
            float* __restrict__ g_out)
{
    extern __shared__ u32 smu[];
    u32* HGH = smu + O_HGH;  u32* HGL = smu + O_HGL;
    float* miF = (float*)(smu + O_MIF);
    float* mjF = (float*)(smu + O_MJF);
    u32* AGH = smu + O_AGH;  u32* AGL = smu + O_AGL;
    u32* M1H = smu + O_M1H;  u32* M1L = smu + O_M1L;
    u32* HTH = smu + O_HTH;  u32* HTL = smu + O_HTL;
    u32* WF  = smu + O_WF;
    u32* M2TH = smu + O_M2TH;
    u32* M2TL = smu + O_M2TL;
    u32* Sbuf = smu + O_S;
    float* s_d2   = (float*)(smu + O_D2);
    int*   s_edge = (int*)(smu + O_EDGE);
    float* s_wd   = (float*)(smu + O_WD);
    float* s_be2  = (float*)(smu + O_BE2);
    u32*   s_rmask = smu + O_RMASK;
    int*   s_roff  = (int*)(smu + O_ROFF);
    float* s_x    = (float*)(smu + O_X);
    float* s_red  = (float*)(smu + O_RED);
    int*   s_ne   = (int*)(smu + O_NE);

    const int tid  = threadIdx.x;
    const int warp = tid >> 5;          // 0..31
    const int lane = tid & 31;
    const int gid  = lane >> 2;
    const int tig  = lane & 3;
    const int b    = blockIdx.x;
    const int rt   = warp & 1;          // row tile
    const int nt   = warp >> 1;         // single n-tile (0..15)
    const int r0   = rt * 16 + gid;
    const int c0   = nt * 8 + 2 * tig;
    const int cpi  = c0 >> 1;

    // ---- prologue: x, split h, stage W_in frags ----
    if (tid < 96) s_x[tid] = g_x[b * 96 + tid];
    if (tid < 256) {
        int r = tid >> 3, cp = tid & 7;
        float2 hv = *(const float2*)&g_h[b * 512 + r * 16 + cp * 2];
        u32 h, l; split2(hv.x, hv.y, h, l);
        HTH[r * 8 + cp] = h; HTL[r * 8 + cp] = l;
    }
    stage_cp(g_wfrag + WIN_BASE, WF, 256, tid);
    stage_cp(g_wfrag + WIN_BASE + 1024, WF + 8192, 256, tid);
    CP_COMMIT();
    __syncthreads();

    // ---- d2 ----
    for (int p = tid; p < 1024; p += NT) {
        int i = p >> 5, j = p & 31;
        float dx = s_x[i * 3 + 0] - s_x[j * 3 + 0];
        float dy = s_x[i * 3 + 1] - s_x[j * 3 + 1];
        float dz = s_x[i * 3 + 2] - s_x[j * 3 + 2];
        s_d2[p] = dx * dx + dy * dy + dz * dz;
    }
    __syncthreads();

    // ---- adjacency masks: warp w owns node w ----
    {
        bool adj = (s_d2[warp * 32 + lane] < 1.0f) && (lane != warp);
        unsigned m = __ballot_sync(0xffffffffu, adj);
        if (lane == 0) s_rmask[warp] = m;
    }
    CP_WAIT0();
    __syncthreads();

    // ---- hg = h @ W_in + b_in ----
    {
        float D[4] = {};
        gemm_mma(HTH, HTL, 8, WF, rt * 16, nt, lane, 0, 1, D);
        float b0 = b_in[c0], b1 = b_in[c0 + 1];
        stpair(HGH, HGL, r0 * 68 + cpi,       D[0] + b0, D[1] + b1);
        stpair(HGH, HGL, (r0 + 8) * 68 + cpi, D[2] + b0, D[3] + b1);
    }

    // ---- edge-list scan ----
    __syncthreads();
    if (warp == 0) {
        unsigned m = s_rmask[lane];
        int c = __popc(m);
        int inc = c;
        #pragma unroll
        for (int d = 1; d < 32; d <<= 1) {
            int n = __shfl_up_sync(0xffffffffu, inc, d);
            if (lane >= d) inc += n;
        }
        s_roff[lane] = inc - c;
        if (lane == 31) *s_ne = inc;
    }
    __syncthreads();
    {
        unsigned m = s_rmask[warp];
        if ((m >> lane) & 1u) {
            int pos = s_roff[warp] + __popc(m & ((1u << lane) - 1u));
            s_edge[pos] = (warp << 5) | lane;
        }
    }
    __syncthreads();
    const int nE = *s_ne;
    const int nCh = (nE + 31) >> 5;

    // ---- layers ----
    #pragma unroll 1
    for (int l = 0; l < 2; l++) {
        const u32* F_e1a = g_wfrag + (l * 6 + 0) * 16384;
        const u32* F_e1b = g_wfrag + (l * 6 + 1) * 16384;
        const u32* F_e2  = g_wfrag + (l * 6 + 2) * 16384;
        const u32* F_h1a = g_wfrag + (l * 6 + 3) * 16384;
        const u32* F_h1b = g_wfrag + (l * 6 + 4) * 16384;
        const u32* F_h2  = g_wfrag + (l * 6 + 5) * 16384;
        const float* We1l = We1 + l * (257 * 128);

        // mi = hg @ We1a + be1 -> miF
        stage_W_halves(F_e1a, WF, tid);
        CP_WAIT1(); __syncthreads();
        {
            float D[4] = {};
            gemm_mma(HGH, HGL, 68, WF, rt * 16, nt, lane, 0, 4, D);
            CP_WAIT0(); __syncthreads();
            gemm_mma(HGH, HGL, 68, WF, rt * 16, nt, lane, 4, 8, D);
            float b0 = be1[l * 128 + c0], b1 = be1[l * 128 + c0 + 1];
            *(float2*)&miF[r0 * 132 + c0]       = make_float2(D[0] + b0, D[1] + b1);
            *(float2*)&miF[(r0 + 8) * 132 + c0] = make_float2(D[2] + b0, D[3] + b1);
        }
        __syncthreads();

        // mj = hg @ We1b -> mjF
        stage_W_halves(F_e1b, WF, tid);
        CP_WAIT1(); __syncthreads();
        {
            float D[4] = {};
            gemm_mma(HGH, HGL, 68, WF, rt * 16, nt, lane, 0, 4, D);
            CP_WAIT0(); __syncthreads();
            gemm_mma(HGH, HGL, 68, WF, rt * 16, nt, lane, 4, 8, D);
            *(float2*)&mjF[r0 * 132 + c0]       = make_float2(D[0], D[1]);
            *(float2*)&mjF[(r0 + 8) * 132 + c0] = make_float2(D[2], D[3]);
        }
        __syncthreads();

        // stage We2; wd, be2
        stage_W_halves(F_e2, WF, tid);
        if (tid < 128) {
            s_wd[tid]  = We1l[256 * 128 + tid];
            s_be2[tid] = be2[l * 128 + tid];
        }
        CP_WAIT0();
        __syncthreads();

        // ---- pair phase: pipelined, ONE barrier per 32-edge chunk ----
        float Dagg[4] = { 0.f, 0.f, 0.f, 0.f };
        if (nE > 0) {
            build_chunk(0, nE, s_edge, s_d2, miF, mjF, s_wd, M1H, M1L, tid);
            build_S(0, nE, s_edge, Sbuf, tid);
        }
        __syncthreads();
        #pragma unroll 1
        for (int c = 0; c < nCh; c++) {
            const int cur = c & 1;
            // build chunk c+1 (independent of GEMM(c) and agg(c-1))
            if (c + 1 < nCh) {
                const int nx = cur ^ 1;
                build_chunk((c + 1) * 32, nE, s_edge, s_d2, miF, mjF, s_wd,
                            M1H + nx * 2176, M1L + nx * 2176, tid);
                build_S((c + 1) * 32, nE, s_edge, Sbuf + ((c + 1) % 3) * 640, tid);
            }
            // agg for chunk c-1
            if (c > 0) {
                const int pv = cur ^ 1;
                agg_mma(Sbuf + ((c - 1) % 3) * 640, M2TH + pv * 2560,
                        M2TL + pv * 2560, rt, nt, lane, Dagg);
            }
            // pair GEMM chunk c + silu -> m2T[cur]
            {
                float D[4] = {};
                gemm_mma(M1H + cur * 2176, M1L + cur * 2176, 68, WF,
                         rt * 16, nt, lane, 0, 8, D);
                float b0 = s_be2[c0], b1 = s_be2[c0 + 1];
                u32* m2h = M2TH + cur * 2560;
                u32* m2l = M2TL + cur * 2560;
                write_m2t(m2h, m2l, c0,     r0,     silu_f(D[0] + b0));
                write_m2t(m2h, m2l, c0 + 1, r0,     silu_f(D[1] + b1));
                write_m2t(m2h, m2l, c0,     r0 + 8, silu_f(D[2] + b0));
                write_m2t(m2h, m2l, c0 + 1, r0 + 8, silu_f(D[3] + b1));
            }
            __syncthreads();
        }
        if (nE > 0) {   // agg for the last chunk
            const int lc = nCh - 1, pv = lc & 1;
            agg_mma(Sbuf + (lc % 3) * 640, M2TH + pv * 2560, M2TL + pv * 2560,
                    rt, nt, lane, Dagg);
        }

        // write agg registers -> AG split arrays; stage Wh1a
        stage_W_halves(F_h1a, WF, tid);
        stpair(AGH, AGL, r0 * 68 + cpi,       Dagg[0], Dagg[1]);
        stpair(AGH, AGL, (r0 + 8) * 68 + cpi, Dagg[2], Dagg[3]);
        CP_WAIT0();
        __syncthreads();

        // u = silu(hg @ Wh1a + agg @ Wh1b + bh1) -> M1 (split, buf0)
        float D[4] = {};
        gemm_mma(HGH, HGL, 68, WF, rt * 16, nt, lane, 0, 8, D);
        __syncthreads();
        stage_W_halves(F_h1b, WF, tid);
        CP_WAIT0();
        __syncthreads();
        gemm_mma(AGH, AGL, 68, WF, rt * 16, nt, lane, 0, 8, D);
        {
            float b0 = bh1[l * 128 + c0], b1 = bh1[l * 128 + c0 + 1];
            stpair(M1H, M1L, r0 * 68 + cpi,
                   silu_f(D[0] + b0), silu_f(D[1] + b1));
            stpair(M1H, M1L, (r0 + 8) * 68 + cpi,
                   silu_f(D[2] + b0), silu_f(D[3] + b1));
        }
        __syncthreads();

        // hg += u @ Wh2 + bh2
        stage_W_halves(F_h2, WF, tid);
        CP_WAIT1(); __syncthreads();
        {
            float D2[4] = {};
            gemm_mma(M1H, M1L, 68, WF, rt * 16, nt, lane, 0, 4, D2);
            CP_WAIT0(); __syncthreads();
            gemm_mma(M1H, M1L, 68, WF, rt * 16, nt, lane, 4, 8, D2);
            float b0 = bh2[l * 128 + c0], b1 = bh2[l * 128 + c0 + 1];
            float2 h0 = ldpair(HGH, HGL, r0 * 68 + cpi);
            stpair(HGH, HGL, r0 * 68 + cpi, h0.x + D2[0] + b0, h0.y + D2[1] + b1);
            float2 h1 = ldpair(HGH, HGL, (r0 + 8) * 68 + cpi);
            stpair(HGH, HGL, (r0 + 8) * 68 + cpi, h1.x + D2[2] + b0, h1.y + D2[3] + b1);
        }
        __syncthreads();
    }

    // ---- head: ho = hg @ W_out + b_out -> M1 (split, buf0) ----
    stage_W_halves(g_wfrag + 12 * 16384, WF, tid);
    CP_WAIT1(); __syncthreads();
    {
        float D[4] = {};
        gemm_mma(HGH, HGL, 68, WF, rt * 16, nt, lane, 0, 4, D);
        CP_WAIT0(); __syncthreads();
        gemm_mma(HGH, HGL, 68, WF, rt * 16, nt, lane, 4, 8, D);
        float b0 = b_out[c0], b1 = b_out[c0 + 1];
        stpair(M1H, M1L, r0 * 68 + cpi,       D[0] + b0, D[1] + b1);
        stpair(M1H, M1L, (r0 + 8) * 68 + cpi, D[2] + b0, D[3] + b1);
    }
    __syncthreads();

    // t1 = silu(ho @ Wn1 + bn1) -> miF (f32)
    stage_W_halves(g_wfrag + 13 * 16384, WF, tid);
    CP_WAIT1(); __syncthreads();
    {
        float D[4] = {};
        gemm_mma(M1H, M1L, 68, WF, rt * 16, nt, lane, 0, 4, D);
        CP_WAIT0(); __syncthreads();
        gemm_mma(M1H, M1L, 68, WF, rt * 16, nt, lane, 4, 8, D);
        float b0 = bn1[c0], b1 = bn1[c0 + 1];
        *(float2*)&miF[r0 * 132 + c0] =
            make_float2(silu_f(D[0] + b0), silu_f(D[1] + b1));
        *(float2*)&miF[(r0 + 8) * 132 + c0] =
            make_float2(silu_f(D[2] + b0), silu_f(D[3] + b1));
    }
    __syncthreads();

    // ---- out[b] = (colsum t1) . Wn2 + 32*bn2 ----
    float part = 0.0f;
    if (tid < 128) {
        int c = tid;
        float s = 0.0f;
        #pragma unroll 1
        for (int i = 0; i < 32; i++) s += miF[i * 132 + c];
        part = s * Wn2[c];
    }
    #pragma unroll
    for (int off = 16; off > 0; off >>= 1)
        part += __shfl_down_sync(0xffffffffu, part, off);
    if (warp < 4 && lane == 0) s_red[warp] = part;
    __syncthreads();
    if (tid == 0)
        g_out[b] = s_red[0] + s_red[1] + s_red[2] + s_red[3] + 32.0f * bn2[0];
}

extern "C" void kernel_launch(void* const* d_in, const int* in_sizes, int n_in,
                              void* d_out, int out_size) {
    const float* g_h   = (const float*)d_in[0];
    const float* g_x   = (const float*)d_in[1];
    const float* W_in  = (const float*)d_in[3];
    const float* b_in  = (const float*)d_in[4];
    const float* We1   = (const float*)d_in[5];
    const float* be1   = (const float*)d_in[6];
    const float* We2   = (const float*)d_in[7];
    const float* be2   = (const float*)d_in[8];
    const float* Wh1   = (const float*)d_in[9];
    const float* bh1   = (const float*)d_in[10];
    const float* Wh2   = (const float*)d_in[11];
    const float* bh2   = (const float*)d_in[12];
    const float* W_out = (const float*)d_in[13];
    const float* b_out = (const float*)d_in[14];
    const float* Wn1   = (const float*)d_in[15];
    const float* bn1   = (const float*)d_in[16];
    const float* Wn2   = (const float*)d_in[17];
    const float* bn2   = (const float*)d_in[18];
    float* out = (float*)d_out;

    prep_kernel<<<dim3(32, 15), 256>>>(We1, We2, Wh1, Wh2, W_out, Wn1, W_in);

    const int smem_bytes = SM_WORDS * 4;
    cudaFuncSetAttribute(sake_kernel, cudaFuncAttributeMaxDynamicSharedMemorySize,
                         smem_bytes);
    sake_kernel<<<NB, NT, smem_bytes>>>(
        g_h, g_x, b_in, We1, be1, be2, bh1, bh2, b_out, bn1, Wn2, bn2, out);
}

// round 13
// speedup vs baseline: 1.9335x; 1.0613x over previous
#include <cuda_runtime.h>

// SAKE GNN fully fused, one CTA per graph (B=512, M=32, H=128, L=2).
// R13: warp-specialized pair phase — 16 producer warps build m1/S chunks,
//      16 consumer warps (2 n-tiles each) run pair GEMM + agg; named-barrier
//      double-buffer handoff. Halves A-fragment smem traffic and overlaps
//      build with MMA.

#define NB 512
#define NT 1024
typedef unsigned int u32;
typedef unsigned short u16;

// global fragment buffer: 14 big Ws (16384 u32 each) + W_in (2048)
__device__ u32 g_wfrag[14 * 16384 + 2048];
#define WIN_BASE (14 * 16384)

// ---- shared memory layout (u32 word offsets) ----
#define O_HGH 0        // hg split: 32 x 68
#define O_HGL 2176
#define O_MIF 4352     // mi f32: 32 x 132
#define O_MJF 8576     // mj f32: 32 x 132
#define O_AGH 12800    // agg split: 32 x 68
#define O_AGL 14976
#define O_M1H 17152    // m1 split: 2 bufs x 32 x 68
#define O_M1L 21504
#define O_HTH 25856    // h input split: 32 x 8
#define O_HTL 26112
#define O_WF  26368    // W fragments: hi 8192 + lo 8192
#define O_M2TH 42752   // m2 B-frag hi: 2 bufs x (128 cols x 20)
#define O_M2TL 47872
#define O_S   52992    // S selection: 2 bufs x (32 rows x 20)
#define O_D2  54912
#define O_EDGE 55936
#define O_WD  56960
#define O_BE2 57088
#define O_RMASK 57216
#define O_ROFF 57248
#define O_X   57280
#define O_RED 57376
#define O_NE  57392
#define SM_WORDS 57396

// named barrier ids
#define BFULL0 1
#define BFULL1 2
#define BEMPTY0 3
#define BEMPTY1 4
#define BCONS  5

#define BAR_SYNC(id, n)   asm volatile("bar.sync %0, %1;"   :: "r"(id), "r"(n) : "memory")
#define BAR_ARRIVE(id, n) asm volatile("bar.arrive %0, %1;" :: "r"(id), "r"(n) : "memory")

__device__ __forceinline__ float silu_f(float v) {
    return __fdividef(v, 1.0f + __expf(-v));
}
__device__ __forceinline__ u32 packbf(float x0, float x1) {
    u32 r;
    asm("cvt.rn.bf16x2.f32 %0, %1, %2;" : "=r"(r) : "f"(x1), "f"(x0));
    return r;
}
__device__ __forceinline__ void split2(float x0, float x1, u32& h, u32& l) {
    h = packbf(x0, x1);
    float r0 = x0 - __uint_as_float(h << 16);
    float r1 = x1 - __uint_as_float(h & 0xffff0000u);
    l = packbf(r0, r1);
}
__device__ __forceinline__ float2 ldpair(const u32* Xh, const u32* Xl, int idx) {
    u32 h = Xh[idx], l = Xl[idx];
    float2 v;
    v.x = __uint_as_float(h << 16) + __uint_as_float(l << 16);
    v.y = __uint_as_float(h & 0xffff0000u) + __uint_as_float(l & 0xffff0000u);
    return v;
}
__device__ __forceinline__ void stpair(u32* Xh, u32* Xl, int idx, float v0, float v1) {
    u32 h, l; split2(v0, v1, h, l);
    Xh[idx] = h; Xl[idx] = l;
}

__device__ __forceinline__ void mma4(float d[4], const u32 a[4], u32 b0, u32 b1) {
    asm volatile("mma.sync.aligned.m16n8k16.row.col.f32.bf16.bf16.f32 "
        "{%0,%1,%2,%3}, {%4,%5,%6,%7}, {%8,%9}, {%0,%1,%2,%3};"
        : "+f"(d[0]), "+f"(d[1]), "+f"(d[2]), "+f"(d[3])
        : "r"(a[0]), "r"(a[1]), "r"(a[2]), "r"(a[3]), "r"(b0), "r"(b1));
}

__device__ __forceinline__ u32 smaddr(const void* p) {
    return (u32)__cvta_generic_to_shared(p);
}
#define LDSM4(d, a) \
    asm volatile("ldmatrix.sync.aligned.m8n8.x4.shared.b16 {%0,%1,%2,%3}, [%4];" \
        : "=r"((d)[0]), "=r"((d)[1]), "=r"((d)[2]), "=r"((d)[3]) : "r"(a))

// 3-term GEMM, ONE n-tile per warp, kt range [kt0, kt1); A via ldmatrix.
__device__ __forceinline__ void gemm_mma(const u32* Xh, const u32* Xl, int rs,
                                         const u32* sWF, int r0, int nt,
                                         int lane, int kt0, int kt1, float D[4]) {
    int t = lane >> 3, rowin = lane & 7;
    int off = (r0 + ((t & 1) << 3) + rowin) * rs + ((t >> 1) << 2);
    u32 baseH = smaddr(Xh + off);
    u32 baseL = smaddr(Xl + off);
    #pragma unroll 1
    for (int kt = kt0; kt < kt1; kt++) {
        u32 ah[4], al[4];
        LDSM4(ah, baseH + kt * 32);
        LDSM4(al, baseL + kt * 32);
        const u32* bp = sWF + ((kt * 16 + nt) * 32 + lane) * 2;
        uint2 bh = *(const uint2*)bp;
        uint2 bl = *(const uint2*)(bp + 8192);
        mma4(D, ah, bh.x, bh.y);
        mma4(D, ah, bl.x, bl.y);
        mma4(D, al, bh.x, bh.y);
    }
}

// consumer pair GEMM: TWO n-tiles per warp, all 8 kt
__device__ __forceinline__ void gemm_mma2(const u32* Xh, const u32* Xl,
                                          const u32* sWF, int r0, int ntb,
                                          int lane, float D[2][4]) {
    int t = lane >> 3, rowin = lane & 7;
    int off = (r0 + ((t & 1) << 3) + rowin) * 68 + ((t >> 1) << 2);
    u32 baseH = smaddr(Xh + off);
    u32 baseL = smaddr(Xl + off);
    #pragma unroll 1
    for (int kt = 0; kt < 8; kt++) {
        u32 ah[4], al[4];
        LDSM4(ah, baseH + kt * 32);
        LDSM4(al, baseL + kt * 32);
        #pragma unroll
        for (int t2 = 0; t2 < 2; t2++) {
            const u32* bp = sWF + ((kt * 16 + ntb + t2) * 32 + lane) * 2;
            uint2 bh = *(const uint2*)bp;
            uint2 bl = *(const uint2*)(bp + 8192);
            mma4(D[t2], ah, bh.x, bh.y);
            mma4(D[t2], ah, bl.x, bl.y);
            mma4(D[t2], al, bh.x, bh.y);
        }
    }
}

__device__ __forceinline__ void cp16(unsigned saddr, const void* g) {
    asm volatile("cp.async.cg.shared.global [%0], [%1], 16;" :: "r"(saddr), "l"(g));
}
#define CP_COMMIT() asm volatile("cp.async.commit_group;")
#define CP_WAIT0()  asm volatile("cp.async.wait_group 0;" ::: "memory")
#define CP_WAIT1()  asm volatile("cp.async.wait_group 1;" ::: "memory")

__device__ __forceinline__ void stage_cp(const u32* __restrict__ g, u32* s,
                                         int nf4, int tid) {
    unsigned sa = (unsigned)__cvta_generic_to_shared(s);
    for (int v = tid; v < nf4; v += NT)
        cp16(sa + v * 16, g + v * 4);
}

__device__ __forceinline__ void stage_W_halves(const u32* __restrict__ F,
                                               u32* WF, int tid) {
    stage_cp(F, WF, 1024, tid);
    stage_cp(F + 8192, WF + 8192, 1024, tid);
    CP_COMMIT();
    stage_cp(F + 4096, WF + 4096, 1024, tid);
    stage_cp(F + 12288, WF + 12288, 1024, tid);
    CP_COMMIT();
}

// write one f32 value into the hi/lo B-fragment m2 buffers at (col c, edge r)
__device__ __forceinline__ void write_m2t(u32* M2THb, u32* M2TLb, int c, int r, float v) {
    u32 hp = packbf(v, 0.0f);
    float hf = __uint_as_float(hp << 16);
    u32 lp = packbf(v - hf, 0.0f);
    int wi = (c * 20 + (r >> 1)) * 2 + (r & 1);
    ((u16*)M2THb)[wi] = (u16)hp;
    ((u16*)M2TLb)[wi] = (u16)lp;
}

// producer build: 512 threads, 16 threads/edge, 8 cols each
__device__ __forceinline__ void build_chunk_p(int e0, int nE, const int* s_edge,
                                              const float* s_d2, const float* miF,
                                              const float* mjF, const float* s_wd,
                                              u32* M1Hb, u32* M1Lb, int tid) {
    int e = tid >> 4;            // 0..31
    int cq = (tid & 15) * 8;     // 8 cols
    int ee = e0 + e;
    int ij = s_edge[ee < nE ? ee : nE - 1];
    int i = ij >> 5, j = ij & 31;
    float dd = s_d2[ij];
    u32 hb[4], lb[4];
    #pragma unroll
    for (int q = 0; q < 2; q++) {
        float4 a = *(const float4*)&miF[i * 132 + cq + 4 * q];
        float4 bb = *(const float4*)&mjF[j * 132 + cq + 4 * q];
        float4 w = *(const float4*)&s_wd[cq + 4 * q];
        float v0 = silu_f(a.x + bb.x + dd * w.x);
        float v1 = silu_f(a.y + bb.y + dd * w.y);
        float v2 = silu_f(a.z + bb.z + dd * w.z);
        float v3 = silu_f(a.w + bb.w + dd * w.w);
        split2(v0, v1, hb[2 * q], lb[2 * q]);
        split2(v2, v3, hb[2 * q + 1], lb[2 * q + 1]);
    }
    *(uint4*)&M1Hb[e * 68 + (cq >> 1)] = make_uint4(hb[0], hb[1], hb[2], hb[3]);
    *(uint4*)&M1Lb[e * 68 + (cq >> 1)] = make_uint4(lb[0], lb[1], lb[2], lb[3]);
}

// build S selection matrix for one chunk (producer tids 0..511)
__device__ __forceinline__ void build_S(int e0, int nE, const int* s_edge,
                                        u32* Sb, int tid) {
    int i = tid >> 4, ep = tid & 15;
    int ea = e0 + 2 * ep, eb = ea + 1;
    int ia = (ea < nE) ? (s_edge[ea] >> 5) : -1;
    int ib = (eb < nE) ? (s_edge[eb] >> 5) : -1;
    u32 val = (ia == i ? 0x00003F80u : 0u) | (ib == i ? 0x3F800000u : 0u);
    Sb[i * 20 + ep] = val;
}

// consumer agg: Dagg[2][4] += S @ (m2h + m2l), 2 n-tiles
__device__ __forceinline__ void agg_mma2(const u32* Sp, const u32* m2h,
                                         const u32* m2l, int rt, int ntb,
                                         int lane, float Dagg[2][4]) {
    int t = lane >> 3, rowin = lane & 7;
    u32 baseS = smaddr(Sp + (rt * 16 + ((t & 1) << 3) + rowin) * 20 + ((t >> 1) << 2));
    #pragma unroll
    for (int kt = 0; kt < 2; kt++) {
        u32 a[4];
        LDSM4(a, baseS + kt * 32);
        #pragma unroll
        for (int t2 = 0; t2 < 2; t2++) {
            int cB = (ntb + t2) * 8 + (lane >> 2);
            const u32* bh = m2h + cB * 20 + kt * 8 + (lane & 3);
            const u32* bl = m2l + cB * 20 + kt * 8 + (lane & 3);
            mma4(Dagg[t2], a, bh[0], bh[4]);
            mma4(Dagg[t2], a, bl[0], bl[4]);
        }
    }
}

// ================= prep kernel: weights -> fragment hi/lo layout =============
__global__ void prep_kernel(const float* __restrict__ We1,
                            const float* __restrict__ We2,
                            const float* __restrict__ Wh1,
                            const float* __restrict__ Wh2,
                            const float* __restrict__ W_out,
                            const float* __restrict__ Wn1,
                            const float* __restrict__ W_in) {
    int y = blockIdx.y;
    int u = blockIdx.x * 256 + threadIdx.x;
    if (y < 14) {
        const float* src;
        if (y < 12) {
            int l = y / 6, w = y % 6;
            switch (w) {
                case 0: src = We1 + l * 257 * 128; break;
                case 1: src = We1 + l * 257 * 128 + 16384; break;
                case 2: src = We2 + l * 16384; break;
                case 3: src = Wh1 + l * 32768; break;
                case 4: src = Wh1 + l * 32768 + 16384; break;
                default: src = Wh2 + l * 16384; break;
            }
        } else {
            src = (y == 12) ? W_out : Wn1;
        }
        int p = u >> 7, c = u & 127;
        float w0 = src[(2 * p) * 128 + c];
        float w1 = src[(2 * p + 1) * 128 + c];
        int kt = p >> 3, pr = p & 7;
        int cpp = pr & 3, reg = pr >> 2;
        int lane = (c & 7) * 4 + cpp;
        int nt = c >> 3;
        int dst = y * 16384 + ((kt * 16 + nt) * 32 + lane) * 2 + reg;
        u32 h, l2; split2(w0, w1, h, l2);
        g_wfrag[dst] = h;
        g_wfrag[dst + 8192] = l2;
    } else {
        if (u >= 1024) return;
        int p = u >> 7, c = u & 127;
        float w0 = W_in[(2 * p) * 128 + c];
        float w1 = W_in[(2 * p + 1) * 128 + c];
        int cpp = p & 3, reg = p >> 2;
        int lane = (c & 7) * 4 + cpp;
        int nt = c >> 3;
        int dst = WIN_BASE + ((nt * 32 + lane) * 2 + reg);
        u32 h, l2; split2(w0, w1, h, l2);
        g_wfrag[dst] = h;
        g_wfrag[dst + 1024] = l2;
    }
}

// ================================ main kernel ================================
__global__ void __launch_bounds__(NT, 1)
sake_kernel(const float* __restrict__ g_h, const float* __restrict__ g_x,
            const float* __restrict__ b_in,
            const float* __restrict__ We1, const float* __restrict__ be1,
            const float* __restrict__ be2,
            const float* __restrict__ bh1, const float* __restrict__ bh2,
            const float* __restrict__ b_out,
            const float* __restrict__ bn1,
            const float* __restrict__ Wn2, const float* __restrict__ bn2,
            float* __restrict__ g_out)
{
    extern __shared__ u32 smu[];
    u32* HGH = smu + O_HGH;  u32* HGL = smu + O_HGL;
    float* miF = (float*)(smu + O_MIF);
    float* mjF = (float*)(smu + O_MJF);
    u32* AGH = smu + O_AGH;  u32* AGL = smu + O_AGL;
    u32* M1H = smu + O_M1H;  u32* M1L = smu + O_M1L;
    u32* HTH = smu + O_HTH;  u32* HTL = smu + O_HTL;
    u32* WF  = smu + O_WF;
    u32* M2TH = smu + O_M2TH;
    u32* M2TL = smu + O_M2TL;
    u32* Sbuf = smu + O_S;
    float* s_d2   = (float*)(smu + O_D2);
    int*   s_edge = (int*)(smu + O_EDGE);
    float* s_wd   = (float*)(smu + O_WD);
    float* s_be2  = (float*)(smu + O_BE2);
    u32*   s_rmask = smu + O_RMASK;
    int*   s_roff  = (int*)(smu + O_ROFF);
    float* s_x    = (float*)(smu + O_X);
    float* s_red  = (float*)(smu + O_RED);
    int*   s_ne   = (int*)(smu + O_NE);

    const int tid  = threadIdx.x;
    const int warp = tid >> 5;          // 0..31
    const int lane = tid & 31;
    const int gid  = lane >> 2;
    const int tig  = lane & 3;
    const int b    = blockIdx.x;
    const int rt   = warp & 1;          // row tile (node GEMMs)
    const int nt   = warp >> 1;         // single n-tile (node GEMMs)
    const int r0   = rt * 16 + gid;
    const int c0   = nt * 8 + 2 * tig;
    const int cpi  = c0 >> 1;

    // ---- prologue: x, split h, stage W_in frags ----
    if (tid < 96) s_x[tid] = g_x[b * 96 + tid];
    if (tid < 256) {
        int r = tid >> 3, cp = tid & 7;
        float2 hv = *(const float2*)&g_h[b * 512 + r * 16 + cp * 2];
        u32 h, l; split2(hv.x, hv.y, h, l);
        HTH[r * 8 + cp] = h; HTL[r * 8 + cp] = l;
    }
    stage_cp(g_wfrag + WIN_BASE, WF, 256, tid);
    stage_cp(g_wfrag + WIN_BASE + 1024, WF + 8192, 256, tid);
    CP_COMMIT();
    __syncthreads();

    // ---- d2 ----
    for (int p = tid; p < 1024; p += NT) {
        int i = p >> 5, j = p & 31;
        float dx = s_x[i * 3 + 0] - s_x[j * 3 + 0];
        float dy = s_x[i * 3 + 1] - s_x[j * 3 + 1];
        float dz = s_x[i * 3 + 2] - s_x[j * 3 + 2];
        s_d2[p] = dx * dx + dy * dy + dz * dz;
    }
    __syncthreads();

    // ---- adjacency masks: warp w owns node w ----
    {
        bool adj = (s_d2[warp * 32 + lane] < 1.0f) && (lane != warp);
        unsigned m = __ballot_sync(0xffffffffu, adj);
        if (lane == 0) s_rmask[warp] = m;
    }
    CP_WAIT0();
    __syncthreads();

    // ---- hg = h @ W_in + b_in ----
    {
        float D[4] = {};
        gemm_mma(HTH, HTL, 8, WF, rt * 16, nt, lane, 0, 1, D);
        float b0 = b_in[c0], b1 = b_in[c0 + 1];
        stpair(HGH, HGL, r0 * 68 + cpi,       D[0] + b0, D[1] + b1);
        stpair(HGH, HGL, (r0 + 8) * 68 + cpi, D[2] + b0, D[3] + b1);
    }

    // ---- edge-list scan ----
    __syncthreads();
    if (warp == 0) {
        unsigned m = s_rmask[lane];
        int c = __popc(m);
        int inc = c;
        #pragma unroll
        for (int d = 1; d < 32; d <<= 1) {
            int n = __shfl_up_sync(0xffffffffu, inc, d);
            if (lane >= d) inc += n;
        }
        s_roff[lane] = inc - c;
        if (lane == 31) *s_ne = inc;
    }
    __syncthreads();
    {
        unsigned m = s_rmask[warp];
        if ((m >> lane) & 1u) {
            int pos = s_roff[warp] + __popc(m & ((1u << lane) - 1u));
            s_edge[pos] = (warp << 5) | lane;
        }
    }
    __syncthreads();
    const int nE = *s_ne;
    const int nCh = (nE + 31) >> 5;

    // ---- layers ----
    #pragma unroll 1
    for (int l = 0; l < 2; l++) {
        const u32* F_e1a = g_wfrag + (l * 6 + 0) * 16384;
        const u32* F_e1b = g_wfrag + (l * 6 + 1) * 16384;
        const u32* F_e2  = g_wfrag + (l * 6 + 2) * 16384;
        const u32* F_h1a = g_wfrag + (l * 6 + 3) * 16384;
        const u32* F_h1b = g_wfrag + (l * 6 + 4) * 16384;
        const u32* F_h2  = g_wfrag + (l * 6 + 5) * 16384;
        const float* We1l = We1 + l * (257 * 128);

        // mi = hg @ We1a + be1 -> miF
        stage_W_halves(F_e1a, WF, tid);
        CP_WAIT1(); __syncthreads();
        {
            float D[4] = {};
            gemm_mma(HGH, HGL, 68, WF, rt * 16, nt, lane, 0, 4, D);
            CP_WAIT0(); __syncthreads();
            gemm_mma(HGH, HGL, 68, WF, rt * 16, nt, lane, 4, 8, D);
            float b0 = be1[l * 128 + c0], b1 = be1[l * 128 + c0 + 1];
            *(float2*)&miF[r0 * 132 + c0]       = make_float2(D[0] + b0, D[1] + b1);
            *(float2*)&miF[(r0 + 8) * 132 + c0] = make_float2(D[2] + b0, D[3] + b1);
        }
        __syncthreads();

        // mj = hg @ We1b -> mjF
        stage_W_halves(F_e1b, WF, tid);
        CP_WAIT1(); __syncthreads();
        {
            float D[4] = {};
            gemm_mma(HGH, HGL, 68, WF, rt * 16, nt, lane, 0, 4, D);
            CP_WAIT0(); __syncthreads();
            gemm_mma(HGH, HGL, 68, WF, rt * 16, nt, lane, 4, 8, D);
            *(float2*)&mjF[r0 * 132 + c0]       = make_float2(D[0], D[1]);
            *(float2*)&mjF[(r0 + 8) * 132 + c0] = make_float2(D[2], D[3]);
        }
        __syncthreads();

        // stage We2; wd, be2
        stage_W_halves(F_e2, WF, tid);
        if (tid < 128) {
            s_wd[tid]  = We1l[256 * 128 + tid];
            s_be2[tid] = be2[l * 128 + tid];
        }
        CP_WAIT0();
        __syncthreads();

        // ---- pair phase: warp-specialized producer/consumer pipeline ----
        float Dagg[2][4] = {};
        if (nCh > 0) {
            if (warp < 16) {
                // PRODUCERS: build m1 + S chunks
                #pragma unroll 1
                for (int c = 0; c < nCh; c++) {
                    const int buf = c & 1;
                    if (c >= 2) BAR_SYNC(BEMPTY0 + buf, 1024);
                    build_chunk_p(c * 32, nE, s_edge, s_d2, miF, mjF, s_wd,
                                  M1H + buf * 2176, M1L + buf * 2176, tid);
                    build_S(c * 32, nE, s_edge, Sbuf + buf * 640, tid);
                    BAR_ARRIVE(BFULL0 + buf, 1024);
                }
            } else {
                // CONSUMERS: pair GEMM (2 n-tiles) + agg
                const int cw   = warp - 16;
                const int crt  = cw & 1;
                const int cntb = (cw >> 1) * 2;
                const int cr0  = crt * 16 + gid;
                #pragma unroll 1
                for (int c = 0; c < nCh; c++) {
                    const int buf = c & 1;
                    BAR_SYNC(BFULL0 + buf, 1024);
                    float D[2][4] = {};
                    gemm_mma2(M1H + buf * 2176, M1L + buf * 2176, WF,
                              crt * 16, cntb, lane, D);
                    u32* m2h = M2TH + buf * 2560;
                    u32* m2l = M2TL + buf * 2560;
                    #pragma unroll
                    for (int t2 = 0; t2 < 2; t2++) {
                        int cc = (cntb + t2) * 8 + 2 * tig;
                        float b0 = s_be2[cc], b1 = s_be2[cc + 1];
                        write_m2t(m2h, m2l, cc,     cr0,     silu_f(D[t2][0] + b0));
                        write_m2t(m2h, m2l, cc + 1, cr0,     silu_f(D[t2][1] + b1));
                        write_m2t(m2h, m2l, cc,     cr0 + 8, silu_f(D[t2][2] + b0));
                        write_m2t(m2h, m2l, cc + 1, cr0 + 8, silu_f(D[t2][3] + b1));
                    }
                    BAR_SYNC(BCONS, 512);
                    agg_mma2(Sbuf + buf * 640, m2h, m2l, crt, cntb, lane, Dagg);
                    if (c < nCh - 2) BAR_ARRIVE(BEMPTY0 + buf, 1024);
                }
            }
        }
        __syncthreads();

        // consumers write agg registers -> AG split arrays; stage Wh1a (all)
        stage_W_halves(F_h1a, WF, tid);
        if (warp >= 16) {
            const int cw   = warp - 16;
            const int crt  = cw & 1;
            const int cntb = (cw >> 1) * 2;
            const int cr0  = crt * 16 + gid;
            #pragma unroll
            for (int t2 = 0; t2 < 2; t2++) {
                int cc = (cntb + t2) * 8 + 2 * tig;
                stpair(AGH, AGL, cr0 * 68 + (cc >> 1),       Dagg[t2][0], Dagg[t2][1]);
                stpair(AGH, AGL, (cr0 + 8) * 68 + (cc >> 1), Dagg[t2][2], Dagg[t2][3]);
            }
        }
        CP_WAIT0();
        __syncthreads();

        // u = silu(hg @ Wh1a + agg @ Wh1b + bh1) -> M1 (split, buf0)
        float D[4] = {};
        gemm_mma(HGH, HGL, 68, WF, rt * 16, nt, lane, 0, 8, D);
        __syncthreads();
        stage_W_halves(F_h1b, WF, tid);
        CP_WAIT0();
        __syncthreads();
        gemm_mma(AGH, AGL, 68, WF, rt * 16, nt, lane, 0, 8, D);
        {
            float b0 = bh1[l * 128 + c0], b1 = bh1[l * 128 + c0 + 1];
            stpair(M1H, M1L, r0 * 68 + cpi,
                   silu_f(D[0] + b0), silu_f(D[1] + b1));
            stpair(M1H, M1L, (r0 + 8) * 68 + cpi,
                   silu_f(D[2] + b0), silu_f(D[3] + b1));
        }
        __syncthreads();

        // hg += u @ Wh2 + bh2
        stage_W_halves(F_h2, WF, tid);
        CP_WAIT1(); __syncthreads();
        {
            float D2[4] = {};
            gemm_mma(M1H, M1L, 68, WF, rt * 16, nt, lane, 0, 4, D2);
            CP_WAIT0(); __syncthreads();
            gemm_mma(M1H, M1L, 68, WF, rt * 16, nt, lane, 4, 8, D2);
            float b0 = bh2[l * 128 + c0], b1 = bh2[l * 128 + c0 + 1];
            float2 h0 = ldpair(HGH, HGL, r0 * 68 + cpi);
            stpair(HGH, HGL, r0 * 68 + cpi, h0.x + D2[0] + b0, h0.y + D2[1] + b1);
            float2 h1 = ldpair(HGH, HGL, (r0 + 8) * 68 + cpi);
            stpair(HGH, HGL, (r0 + 8) * 68 + cpi, h1.x + D2[2] + b0, h1.y + D2[3] + b1);
        }
        __syncthreads();
    }

    // ---- head: ho = hg @ W_out + b_out -> M1 (split, buf0) ----
    stage_W_halves(g_wfrag + 12 * 16384, WF, tid);
    CP_WAIT1(); __syncthreads();
    {
        float D[4] = {};
        gemm_mma(HGH, HGL, 68, WF, rt * 16, nt, lane, 0, 4, D);
        CP_WAIT0(); __syncthreads();
        gemm_mma(HGH, HGL, 68, WF, rt * 16, nt, lane, 4, 8, D);
        float b0 = b_out[c0], b1 = b_out[c0 + 1];
        stpair(M1H, M1L, r0 * 68 + cpi,       D[0] + b0, D[1] + b1);
        stpair(M1H, M1L, (r0 + 8) * 68 + cpi, D[2] + b0, D[3] + b1);
    }
    __syncthreads();

    // t1 = silu(ho @ Wn1 + bn1) -> miF (f32)
    stage_W_halves(g_wfrag + 13 * 16384, WF, tid);
    CP_WAIT1(); __syncthreads();
    {
        float D[4] = {};
        gemm_mma(M1H, M1L, 68, WF, rt * 16, nt, lane, 0, 4, D);
        CP_WAIT0(); __syncthreads();
        gemm_mma(M1H, M1L, 68, WF, rt * 16, nt, lane, 4, 8, D);
        float b0 = bn1[c0], b1 = bn1[c0 + 1];
        *(float2*)&miF[r0 * 132 + c0] =
            make_float2(silu_f(D[0] + b0), silu_f(D[1] + b1));
        *(float2*)&miF[(r0 + 8) * 132 + c0] =
            make_float2(silu_f(D[2] + b0), silu_f(D[3] + b1));
    }
    __syncthreads();

    // ---- out[b] = (colsum t1) . Wn2 + 32*bn2 ----
    float part = 0.0f;
    if (tid < 128) {
        int c = tid;
        float s = 0.0f;
        #pragma unroll 1
        for (int i = 0; i < 32; i++) s += miF[i * 132 + c];
        part = s * Wn2[c];
    }
    #pragma unroll
    for (int off = 16; off > 0; off >>= 1)
        part += __shfl_down_sync(0xffffffffu, part, off);
    if (warp < 4 && lane == 0) s_red[warp] = part;
    __syncthreads();
    if (tid == 0)
        g_out[b] = s_red[0] + s_red[1] + s_red[2] + s_red[3] + 32.0f * bn2[0];
}

extern "C" void kernel_launch(void* const* d_in, const int* in_sizes, int n_in,
                              void* d_out, int out_size) {
    const float* g_h   = (const float*)d_in[0];
    const float* g_x   = (const float*)d_in[1];
    const float* W_in  = (const float*)d_in[3];
    const float* b_in  = (const float*)d_in[4];
    const float* We1   = (const float*)d_in[5];
    const float* be1   = (const float*)d_in[6];
    const float* We2   = (const float*)d_in[7];
    const float* be2   = (const float*)d_in[8];
    const float* Wh1   = (const float*)d_in[9];
    const float* bh1   = (const float*)d_in[10];
    const float* Wh2   = (const float*)d_in[11];
    const float* bh2   = (const float*)d_in[12];
    const float* W_out = (const float*)d_in[13];
    const float* b_out = (const float*)d_in[14];
    const float* Wn1   = (const float*)d_in[15];
    const float* bn1   = (const float*)d_in[16];
    const float* Wn2   = (const float*)d_in[17];
    const float* bn2   = (const float*)d_in[18];
    float* out = (float*)d_out;

    prep_kernel<<<dim3(32, 15), 256>>>(We1, We2, Wh1, Wh2, W_out, Wn1, W_in);

    const int smem_bytes = SM_WORDS * 4;
    cudaFuncSetAttribute(sake_kernel, cudaFuncAttributeMaxDynamicSharedMemorySize,
                         smem_bytes);
    sake_kernel<<<NB, NT, smem_bytes>>>(
        g_h, g_x, b_in, We1, be1, be2, bh1, bh2, b_out, bn1, Wn2, bn2, out);
}

// round 14
// speedup vs baseline: 1.9779x; 1.0230x over previous
#include <cuda_runtime.h>

// SAKE GNN fully fused, one CTA per graph (B=512, M=32, H=128, L=2).
// R14: node GEMMs K-split — warps = (kh, rt, ntpair) 2x2x8, each 2 n-tiles
//      x 4 kt; halves A-fragment smem traffic (the measured L1 wall).
//      kh-halves combined via scratch reduction. Pair phase = R13 pipeline.

#define NB 512
#define NT 1024
typedef unsigned int u32;
typedef unsigned short u16;

// global fragment buffer: 14 big Ws (16384 u32 each) + W_in (2048)
__device__ u32 g_wfrag[14 * 16384 + 2048];
#define WIN_BASE (14 * 16384)

// ---- shared memory layout (u32 word offsets) ----
#define O_HGH 0        // hg split: 32 x 68
#define O_HGL 2176
#define O_MIF 4352     // mi f32: 32 x 132
#define O_MJF 8576     // mj f32: 32 x 132
#define O_AGH 12800    // agg split: 32 x 68
#define O_AGL 14976
#define O_M1H 17152    // m1 split: 2 bufs x 32 x 68
#define O_M1L 21504
#define O_HTH 25856    // h input split: 32 x 8
#define O_HTL 26112
#define O_WF  26368    // W fragments: hi 8192 + lo 8192
#define O_M2TH 42752   // m2 B-frag hi: 2 bufs x (128 cols x 20); also kh scratch
#define O_M2TL 47872
#define O_S   52992    // S selection: 2 bufs x (32 rows x 20)
#define O_D2  54912
#define O_EDGE 55936
#define O_WD  56960
#define O_BE2 57088
#define O_RMASK 57216
#define O_ROFF 57248
#define O_X   57280
#define O_RED 57376
#define O_NE  57392
#define SM_WORDS 57396

// named barrier ids
#define BFULL0 1
#define BFULL1 2
#define BEMPTY0 3
#define BEMPTY1 4
#define BCONS  5

#define BAR_SYNC(id, n)   asm volatile("bar.sync %0, %1;"   :: "r"(id), "r"(n) : "memory")
#define BAR_ARRIVE(id, n) asm volatile("bar.arrive %0, %1;" :: "r"(id), "r"(n) : "memory")

__device__ __forceinline__ float silu_f(float v) {
    return __fdividef(v, 1.0f + __expf(-v));
}
__device__ __forceinline__ u32 packbf(float x0, float x1) {
    u32 r;
    asm("cvt.rn.bf16x2.f32 %0, %1, %2;" : "=r"(r) : "f"(x1), "f"(x0));
    return r;
}
__device__ __forceinline__ void split2(float x0, float x1, u32& h, u32& l) {
    h = packbf(x0, x1);
    float r0 = x0 - __uint_as_float(h << 16);
    float r1 = x1 - __uint_as_float(h & 0xffff0000u);
    l = packbf(r0, r1);
}
__device__ __forceinline__ float2 ldpair(const u32* Xh, const u32* Xl, int idx) {
    u32 h = Xh[idx], l = Xl[idx];
    float2 v;
    v.x = __uint_as_float(h << 16) + __uint_as_float(l << 16);
    v.y = __uint_as_float(h & 0xffff0000u) + __uint_as_float(l & 0xffff0000u);
    return v;
}
__device__ __forceinline__ void stpair(u32* Xh, u32* Xl, int idx, float v0, float v1) {
    u32 h, l; split2(v0, v1, h, l);
    Xh[idx] = h; Xl[idx] = l;
}

__device__ __forceinline__ void mma4(float d[4], const u32 a[4], u32 b0, u32 b1) {
    asm volatile("mma.sync.aligned.m16n8k16.row.col.f32.bf16.bf16.f32 "
        "{%0,%1,%2,%3}, {%4,%5,%6,%7}, {%8,%9}, {%0,%1,%2,%3};"
        : "+f"(d[0]), "+f"(d[1]), "+f"(d[2]), "+f"(d[3])
        : "r"(a[0]), "r"(a[1]), "r"(a[2]), "r"(a[3]), "r"(b0), "r"(b1));
}

__device__ __forceinline__ u32 smaddr(const void* p) {
    return (u32)__cvta_generic_to_shared(p);
}
#define LDSM4(d, a) \
    asm volatile("ldmatrix.sync.aligned.m8n8.x4.shared.b16 {%0,%1,%2,%3}, [%4];" \
        : "=r"((d)[0]), "=r"((d)[1]), "=r"((d)[2]), "=r"((d)[3]) : "r"(a))

// 3-term GEMM, TWO n-tiles per warp, kt range [kt0, kt1); A via ldmatrix.
__device__ __forceinline__ void gemm_mma2n(const u32* Xh, const u32* Xl, int rs,
                                           const u32* sWF, int r0, int ntb,
                                           int lane, int kt0, int kt1,
                                           float D[2][4]) {
    int t = lane >> 3, rowin = lane & 7;
    int off = (r0 + ((t & 1) << 3) + rowin) * rs + ((t >> 1) << 2);
    u32 baseH = smaddr(Xh + off);
    u32 baseL = smaddr(Xl + off);
    #pragma unroll 1
    for (int kt = kt0; kt < kt1; kt++) {
        u32 ah[4], al[4];
        LDSM4(ah, baseH + kt * 32);
        LDSM4(al, baseL + kt * 32);
        #pragma unroll
        for (int t2 = 0; t2 < 2; t2++) {
            const u32* bp = sWF + ((kt * 16 + ntb + t2) * 32 + lane) * 2;
            uint2 bh = *(const uint2*)bp;
            uint2 bl = *(const uint2*)(bp + 8192);
            mma4(D[t2], ah, bh.x, bh.y);
            mma4(D[t2], ah, bl.x, bl.y);
            mma4(D[t2], al, bh.x, bh.y);
        }
    }
}

// combine kh halves via smem scratch; returns true if this warp owns epilogue.
// MUST be called by all threads (contains __syncthreads).
__device__ __forceinline__ bool reduce_kh(float D[2][4], float* scr,
                                          int kh, int rtn, int ntp, int lane) {
    int base = (((rtn << 3) + ntp) * 32 + lane) * 8;
    if (kh) {
        *(float4*)&scr[base]     = make_float4(D[0][0], D[0][1], D[0][2], D[0][3]);
        *(float4*)&scr[base + 4] = make_float4(D[1][0], D[1][1], D[1][2], D[1][3]);
    }
    __syncthreads();
    if (!kh) {
        float4 p0 = *(const float4*)&scr[base];
        float4 p1 = *(const float4*)&scr[base + 4];
        D[0][0] += p0.x; D[0][1] += p0.y; D[0][2] += p0.z; D[0][3] += p0.w;
        D[1][0] += p1.x; D[1][1] += p1.y; D[1][2] += p1.z; D[1][3] += p1.w;
    }
    return !kh;
}

__device__ __forceinline__ void cp16(unsigned saddr, const void* g) {
    asm volatile("cp.async.cg.shared.global [%0], [%1], 16;" :: "r"(saddr), "l"(g));
}
#define CP_COMMIT() asm volatile("cp.async.commit_group;")
#define CP_WAIT0()  asm volatile("cp.async.wait_group 0;" ::: "memory")

__device__ __forceinline__ void stage_cp(const u32* __restrict__ g, u32* s,
                                         int nf4, int tid) {
    unsigned sa = (unsigned)__cvta_generic_to_shared(s);
    for (int v = tid; v < nf4; v += NT)
        cp16(sa + v * 16, g + v * 4);
}

__device__ __forceinline__ void stage_W(const u32* __restrict__ F, u32* WF, int tid) {
    stage_cp(F, WF, 2048, tid);           // hi
    stage_cp(F + 8192, WF + 8192, 2048, tid);  // lo
    CP_COMMIT();
}

// write one f32 value into the hi/lo B-fragment m2 buffers at (col c, edge r)
__device__ __forceinline__ void write_m2t(u32* M2THb, u32* M2TLb, int c, int r, float v) {
    u32 hp = packbf(v, 0.0f);
    float hf = __uint_as_float(hp << 16);
    u32 lp = packbf(v - hf, 0.0f);
    int wi = (c * 20 + (r >> 1)) * 2 + (r & 1);
    ((u16*)M2THb)[wi] = (u16)hp;
    ((u16*)M2TLb)[wi] = (u16)lp;
}

// consumer pair GEMM: TWO n-tiles per warp, all 8 kt (rs = 68)
__device__ __forceinline__ void gemm_mma2(const u32* Xh, const u32* Xl,
                                          const u32* sWF, int r0, int ntb,
                                          int lane, float D[2][4]) {
    gemm_mma2n(Xh, Xl, 68, sWF, r0, ntb, lane, 0, 8, D);
}

// producer build: 512 threads, 16 threads/edge, 8 cols each
__device__ __forceinline__ void build_chunk_p(int e0, int nE, const int* s_edge,
                                              const float* s_d2, const float* miF,
                                              const float* mjF, const float* s_wd,
                                              u32* M1Hb, u32* M1Lb, int tid) {
    int e = tid >> 4;            // 0..31
    int cq = (tid & 15) * 8;     // 8 cols
    int ee = e0 + e;
    int ij = s_edge[ee < nE ? ee : nE - 1];
    int i = ij >> 5, j = ij & 31;
    float dd = s_d2[ij];
    u32 hb[4], lb[4];
    #pragma unroll
    for (int q = 0; q < 2; q++) {
        float4 a = *(const float4*)&miF[i * 132 + cq + 4 * q];
        float4 bb = *(const float4*)&mjF[j * 132 + cq + 4 * q];
        float4 w = *(const float4*)&s_wd[cq + 4 * q];
        float v0 = silu_f(a.x + bb.x + dd * w.x);
        float v1 = silu_f(a.y + bb.y + dd * w.y);
        float v2 = silu_f(a.z + bb.z + dd * w.z);
        float v3 = silu_f(a.w + bb.w + dd * w.w);
        split2(v0, v1, hb[2 * q], lb[2 * q]);
        split2(v2, v3, hb[2 * q + 1], lb[2 * q + 1]);
    }
    *(uint4*)&M1Hb[e * 68 + (cq >> 1)] = make_uint4(hb[0], hb[1], hb[2], hb[3]);
    *(uint4*)&M1Lb[e * 68 + (cq >> 1)] = make_uint4(lb[0], lb[1], lb[2], lb[3]);
}

// build S selection matrix for one chunk (producer tids 0..511)
__device__ __forceinline__ void build_S(int e0, int nE, const int* s_edge,
                                        u32* Sb, int tid) {
    int i = tid >> 4, ep = tid & 15;
    int ea = e0 + 2 * ep, eb = ea + 1;
    int ia = (ea < nE) ? (s_edge[ea] >> 5) : -1;
    int ib = (eb < nE) ? (s_edge[eb] >> 5) : -1;
    u32 val = (ia == i ? 0x00003F80u : 0u) | (ib == i ? 0x3F800000u : 0u);
    Sb[i * 20 + ep] = val;
}

// consumer agg: Dagg[2][4] += S @ (m2h + m2l), 2 n-tiles
__device__ __forceinline__ void agg_mma2(const u32* Sp, const u32* m2h,
                                         const u32* m2l, int rt, int ntb,
                                         int lane, float Dagg[2][4]) {
    int t = lane >> 3, rowin = lane & 7;
    u32 baseS = smaddr(Sp + (rt * 16 + ((t & 1) << 3) + rowin) * 20 + ((t >> 1) << 2));
    #pragma unroll
    for (int kt = 0; kt < 2; kt++) {
        u32 a[4];
        LDSM4(a, baseS + kt * 32);
        #pragma unroll
        for (int t2 = 0; t2 < 2; t2++) {
            int cB = (ntb + t2) * 8 + (lane >> 2);
            const u32* bh = m2h + cB * 20 + kt * 8 + (lane & 3);
            const u32* bl = m2l + cB * 20 + kt * 8 + (lane & 3);
            mma4(Dagg[t2], a, bh[0], bh[4]);
            mma4(Dagg[t2], a, bl[0], bl[4]);
        }
    }
}

// ================= prep kernel: weights -> fragment hi/lo layout =============
__global__ void prep_kernel(const float* __restrict__ We1,
                            const float* __restrict__ We2,
                            const float* __restrict__ Wh1,
                            const float* __restrict__ Wh2,
                            const float* __restrict__ W_out,
                            const float* __restrict__ Wn1,
                            const float* __restrict__ W_in) {
    int y = blockIdx.y;
    int u = blockIdx.x * 256 + threadIdx.x;
    if (y < 14) {
        const float* src;
        if (y < 12) {
            int l = y / 6, w = y % 6;
            switch (w) {
                case 0: src = We1 + l * 257 * 128; break;
                case 1: src = We1 + l * 257 * 128 + 16384; break;
                case 2: src = We2 + l * 16384; break;
                case 3: src = Wh1 + l * 32768; break;
                case 4: src = Wh1 + l * 32768 + 16384; break;
                default: src = Wh2 + l * 16384; break;
            }
        } else {
            src = (y == 12) ? W_out : Wn1;
        }
        int p = u >> 7, c = u & 127;
        float w0 = src[(2 * p) * 128 + c];
        float w1 = src[(2 * p + 1) * 128 + c];
        int kt = p >> 3, pr = p & 7;
        int cpp = pr & 3, reg = pr >> 2;
        int lane = (c & 7) * 4 + cpp;
        int nt = c >> 3;
        int dst = y * 16384 + ((kt * 16 + nt) * 32 + lane) * 2 + reg;
        u32 h, l2; split2(w0, w1, h, l2);
        g_wfrag[dst] = h;
        g_wfrag[dst + 8192] = l2;
    } else {
        if (u >= 1024) return;
        int p = u >> 7, c = u & 127;
        float w0 = W_in[(2 * p) * 128 + c];
        float w1 = W_in[(2 * p + 1) * 128 + c];
        int cpp = p & 3, reg = p >> 2;
        int lane = (c & 7) * 4 + cpp;
        int nt = c >> 3;
        int dst = WIN_BASE + ((nt * 32 + lane) * 2 + reg);
        u32 h, l2; split2(w0, w1, h, l2);
        g_wfrag[dst] = h;
        g_wfrag[dst + 1024] = l2;
    }
}

// ================================ main kernel ================================
__global__ void __launch_bounds__(NT, 1)
sake_kernel(const float* __restrict__ g_h, const float* __restrict__ g_x,
            const float* __restrict__ b_in,
            const float* __restrict__ We1, const float* __restrict__ be1,
            const float* __restrict__ be2,
            const float* __restrict__ bh1, const float* __restrict__ bh2,
            const float* __restrict__ b_out,
            const float* __restrict__ bn1,
            const float* __restrict__ Wn2, const float* __restrict__ bn2,
            float* __restrict__ g_out)
{
    extern __shared__ u32 smu[];
    u32* HGH = smu + O_HGH;  u32* HGL = smu + O_HGL;
    float* miF = (float*)(smu + O_MIF);
    float* mjF = (float*)(smu + O_MJF);
    u32* AGH = smu + O_AGH;  u32* AGL = smu + O_AGL;
    u32* M1H = smu + O_M1H;  u32* M1L = smu + O_M1L;
    u32* HTH = smu + O_HTH;  u32* HTL = smu + O_HTL;
    u32* WF  = smu + O_WF;
    u32* M2TH = smu + O_M2TH;
    u32* M2TL = smu + O_M2TL;
    float* scrF = (float*)(smu + O_M2TH);   // kh reduction scratch (node GEMMs)
    u32* Sbuf = smu + O_S;
    float* s_d2   = (float*)(smu + O_D2);
    int*   s_edge = (int*)(smu + O_EDGE);
    float* s_wd   = (float*)(smu + O_WD);
    float* s_be2  = (float*)(smu + O_BE2);
    u32*   s_rmask = smu + O_RMASK;
    int*   s_roff  = (int*)(smu + O_ROFF);
    float* s_x    = (float*)(smu + O_X);
    float* s_red  = (float*)(smu + O_RED);
    int*   s_ne   = (int*)(smu + O_NE);

    const int tid  = threadIdx.x;
    const int warp = tid >> 5;          // 0..31
    const int lane = tid & 31;
    const int gid  = lane >> 2;
    const int tig  = lane & 3;
    const int b    = blockIdx.x;
    // node-GEMM mapping: (kh, rtn, ntp)
    const int kh   = warp & 1;
    const int rtn  = (warp >> 1) & 1;
    const int ntp  = warp >> 2;         // 0..7
    const int ntbN = ntp * 2;
    const int rr0  = rtn * 16 + gid;
    const int kt0  = kh ? 4 : 0;
    const int kt1  = kh ? 8 : 4;

    // ---- prologue: x, split h, stage W_in frags ----
    if (tid < 96) s_x[tid] = g_x[b * 96 + tid];
    if (tid < 256) {
        int r = tid >> 3, cp = tid & 7;
        float2 hv = *(const float2*)&g_h[b * 512 + r * 16 + cp * 2];
        u32 h, l; split2(hv.x, hv.y, h, l);
        HTH[r * 8 + cp] = h; HTL[r * 8 + cp] = l;
    }
    stage_cp(g_wfrag + WIN_BASE, WF, 256, tid);
    stage_cp(g_wfrag + WIN_BASE + 1024, WF + 8192, 256, tid);
    CP_COMMIT();
    __syncthreads();

    // ---- d2 ----
    for (int p = tid; p < 1024; p += NT) {
        int i = p >> 5, j = p & 31;
        float dx = s_x[i * 3 + 0] - s_x[j * 3 + 0];
        float dy = s_x[i * 3 + 1] - s_x[j * 3 + 1];
        float dz = s_x[i * 3 + 2] - s_x[j * 3 + 2];
        s_d2[p] = dx * dx + dy * dy + dz * dz;
    }
    __syncthreads();

    // ---- adjacency masks: warp w owns node w ----
    {
        bool adj = (s_d2[warp * 32 + lane] < 1.0f) && (lane != warp);
        unsigned m = __ballot_sync(0xffffffffu, adj);
        if (lane == 0) s_rmask[warp] = m;
    }
    CP_WAIT0();
    __syncthreads();

    // ---- hg = h @ W_in + b_in (kh0 warps only; 1 kt) ----
    if (!kh) {
        float D[2][4] = {};
        gemm_mma2n(HTH, HTL, 8, WF, rtn * 16, ntbN, lane, 0, 1, D);
        #pragma unroll
        for (int t2 = 0; t2 < 2; t2++) {
            int cc = (ntbN + t2) * 8 + 2 * tig;
            float b0 = b_in[cc], b1 = b_in[cc + 1];
            stpair(HGH, HGL, rr0 * 68 + (cc >> 1),       D[t2][0] + b0, D[t2][1] + b1);
            stpair(HGH, HGL, (rr0 + 8) * 68 + (cc >> 1), D[t2][2] + b0, D[t2][3] + b1);
        }
    }

    // ---- edge-list scan ----
    __syncthreads();
    if (warp == 0) {
        unsigned m = s_rmask[lane];
        int c = __popc(m);
        int inc = c;
        #pragma unroll
        for (int d = 1; d < 32; d <<= 1) {
            int n = __shfl_up_sync(0xffffffffu, inc, d);
            if (lane >= d) inc += n;
        }
        s_roff[lane] = inc - c;
        if (lane == 31) *s_ne = inc;
    }
    __syncthreads();
    {
        unsigned m = s_rmask[warp];
        if ((m >> lane) & 1u) {
            int pos = s_roff[warp] + __popc(m & ((1u << lane) - 1u));
            s_edge[pos] = (warp << 5) | lane;
        }
    }
    __syncthreads();
    const int nE = *s_ne;
    const int nCh = (nE + 31) >> 5;

    // ---- layers ----
    #pragma unroll 1
    for (int l = 0; l < 2; l++) {
        const u32* F_e1a = g_wfrag + (l * 6 + 0) * 16384;
        const u32* F_e1b = g_wfrag + (l * 6 + 1) * 16384;
        const u32* F_e2  = g_wfrag + (l * 6 + 2) * 16384;
        const u32* F_h1a = g_wfrag + (l * 6 + 3) * 16384;
        const u32* F_h1b = g_wfrag + (l * 6 + 4) * 16384;
        const u32* F_h2  = g_wfrag + (l * 6 + 5) * 16384;
        const float* We1l = We1 + l * (257 * 128);

        // mi = hg @ We1a + be1 -> miF
        stage_W(F_e1a, WF, tid); CP_WAIT0(); __syncthreads();
        {
            float D[2][4] = {};
            gemm_mma2n(HGH, HGL, 68, WF, rtn * 16, ntbN, lane, kt0, kt1, D);
            if (reduce_kh(D, scrF, kh, rtn, ntp, lane)) {
                #pragma unroll
                for (int t2 = 0; t2 < 2; t2++) {
                    int cc = (ntbN + t2) * 8 + 2 * tig;
                    float b0 = be1[l * 128 + cc], b1 = be1[l * 128 + cc + 1];
                    *(float2*)&miF[rr0 * 132 + cc]       = make_float2(D[t2][0] + b0, D[t2][1] + b1);
                    *(float2*)&miF[(rr0 + 8) * 132 + cc] = make_float2(D[t2][2] + b0, D[t2][3] + b1);
                }
            }
        }
        __syncthreads();

        // mj = hg @ We1b -> mjF
        stage_W(F_e1b, WF, tid); CP_WAIT0(); __syncthreads();
        {
            float D[2][4] = {};
            gemm_mma2n(HGH, HGL, 68, WF, rtn * 16, ntbN, lane, kt0, kt1, D);
            if (reduce_kh(D, scrF, kh, rtn, ntp, lane)) {
                #pragma unroll
                for (int t2 = 0; t2 < 2; t2++) {
                    int cc = (ntbN + t2) * 8 + 2 * tig;
                    *(float2*)&mjF[rr0 * 132 + cc]       = make_float2(D[t2][0], D[t2][1]);
                    *(float2*)&mjF[(rr0 + 8) * 132 + cc] = make_float2(D[t2][2], D[t2][3]);
                }
            }
        }
        __syncthreads();

        // stage We2; wd, be2
        stage_W(F_e2, WF, tid);
        if (tid < 128) {
            s_wd[tid]  = We1l[256 * 128 + tid];
            s_be2[tid] = be2[l * 128 + tid];
        }
        CP_WAIT0();
        __syncthreads();

        // ---- pair phase: warp-specialized producer/consumer pipeline ----
        float Dagg[2][4] = {};
        if (nCh > 0) {
            if (warp < 16) {
                // PRODUCERS: build m1 + S chunks
                #pragma unroll 1
                for (int c = 0; c < nCh; c++) {
                    const int buf = c & 1;
                    if (c >= 2) BAR_SYNC(BEMPTY0 + buf, 1024);
                    build_chunk_p(c * 32, nE, s_edge, s_d2, miF, mjF, s_wd,
                                  M1H + buf * 2176, M1L + buf * 2176, tid);
                    build_S(c * 32, nE, s_edge, Sbuf + buf * 640, tid);
                    BAR_ARRIVE(BFULL0 + buf, 1024);
                }
            } else {
                // CONSUMERS: pair GEMM (2 n-tiles) + agg
                const int cw   = warp - 16;
                const int crt  = cw & 1;
                const int cntb = (cw >> 1) * 2;
                const int cr0  = crt * 16 + gid;
                #pragma unroll 1
                for (int c = 0; c < nCh; c++) {
                    const int buf = c & 1;
                    BAR_SYNC(BFULL0 + buf, 1024);
                    float D[2][4] = {};
                    gemm_mma2(M1H + buf * 2176, M1L + buf * 2176, WF,
                              crt * 16, cntb, lane, D);
                    u32* m2h = M2TH + buf * 2560;
                    u32* m2l = M2TL + buf * 2560;
                    #pragma unroll
                    for (int t2 = 0; t2 < 2; t2++) {
                        int cc = (cntb + t2) * 8 + 2 * tig;
                        float b0 = s_be2[cc], b1 = s_be2[cc + 1];
                        write_m2t(m2h, m2l, cc,     cr0,     silu_f(D[t2][0] + b0));
                        write_m2t(m2h, m2l, cc + 1, cr0,     silu_f(D[t2][1] + b1));
                        write_m2t(m2h, m2l, cc,     cr0 + 8, silu_f(D[t2][2] + b0));
                        write_m2t(m2h, m2l, cc + 1, cr0 + 8, silu_f(D[t2][3] + b1));
                    }
                    BAR_SYNC(BCONS, 512);
                    agg_mma2(Sbuf + buf * 640, m2h, m2l, crt, cntb, lane, Dagg);
                    if (c < nCh - 2) BAR_ARRIVE(BEMPTY0 + buf, 1024);
                }
            }
        }
        __syncthreads();

        // consumers write agg registers -> AG split arrays; stage Wh1a (all)
        stage_W(F_h1a, WF, tid);
        if (warp >= 16) {
            const int cw   = warp - 16;
            const int crt  = cw & 1;
            const int cntb = (cw >> 1) * 2;
            const int cr0  = crt * 16 + gid;
            #pragma unroll
            for (int t2 = 0; t2 < 2; t2++) {
                int cc = (cntb + t2) * 8 + 2 * tig;
                stpair(AGH, AGL, cr0 * 68 + (cc >> 1),       Dagg[t2][0], Dagg[t2][1]);
                stpair(AGH, AGL, (cr0 + 8) * 68 + (cc >> 1), Dagg[t2][2], Dagg[t2][3]);
            }
        }
        CP_WAIT0();
        __syncthreads();

        // u = silu(hg @ Wh1a + agg @ Wh1b + bh1) -> M1 (split, buf0)
        {
            float D[2][4] = {};
            gemm_mma2n(HGH, HGL, 68, WF, rtn * 16, ntbN, lane, kt0, kt1, D);
            __syncthreads();
            stage_W(F_h1b, WF, tid);
            CP_WAIT0();
            __syncthreads();
            gemm_mma2n(AGH, AGL, 68, WF, rtn * 16, ntbN, lane, kt0, kt1, D);
            if (reduce_kh(D, scrF, kh, rtn, ntp, lane)) {
                #pragma unroll
                for (int t2 = 0; t2 < 2; t2++) {
                    int cc = (ntbN + t2) * 8 + 2 * tig;
                    float b0 = bh1[l * 128 + cc], b1 = bh1[l * 128 + cc + 1];
                    stpair(M1H, M1L, rr0 * 68 + (cc >> 1),
                           silu_f(D[t2][0] + b0), silu_f(D[t2][1] + b1));
                    stpair(M1H, M1L, (rr0 + 8) * 68 + (cc >> 1),
                           silu_f(D[t2][2] + b0), silu_f(D[t2][3] + b1));
                }
            }
        }
        __syncthreads();

        // hg += u @ Wh2 + bh2
        stage_W(F_h2, WF, tid); CP_WAIT0(); __syncthreads();
        {
            float D[2][4] = {};
            gemm_mma2n(M1H, M1L, 68, WF, rtn * 16, ntbN, lane, kt0, kt1, D);
            if (reduce_kh(D, scrF, kh, rtn, ntp, lane)) {
                #pragma unroll
                for (int t2 = 0; t2 < 2; t2++) {
                    int cc = (ntbN + t2) * 8 + 2 * tig;
                    float b0 = bh2[l * 128 + cc], b1 = bh2[l * 128 + cc + 1];
                    float2 h0 = ldpair(HGH, HGL, rr0 * 68 + (cc >> 1));
                    stpair(HGH, HGL, rr0 * 68 + (cc >> 1),
                           h0.x + D[t2][0] + b0, h0.y + D[t2][1] + b1);
                    float2 h1 = ldpair(HGH, HGL, (rr0 + 8) * 68 + (cc >> 1));
                    stpair(HGH, HGL, (rr0 + 8) * 68 + (cc >> 1),
                           h1.x + D[t2][2] + b0, h1.y + D[t2][3] + b1);
                }
            }
        }
        __syncthreads();
    }

    // ---- head: ho = hg @ W_out + b_out -> M1 (split, buf0) ----
    stage_W(g_wfrag + 12 * 16384, WF, tid); CP_WAIT0(); __syncthreads();
    {
        float D[2][4] = {};
        gemm_mma2n(HGH, HGL, 68, WF, rtn * 16, ntbN, lane, kt0, kt1, D);
        if (reduce_kh(D, scrF, kh, rtn, ntp, lane)) {
            #pragma unroll
            for (int t2 = 0; t2 < 2; t2++) {
                int cc = (ntbN + t2) * 8 + 2 * tig;
                float b0 = b_out[cc], b1 = b_out[cc + 1];
                stpair(M1H, M1L, rr0 * 68 + (cc >> 1),       D[t2][0] + b0, D[t2][1] + b1);
                stpair(M1H, M1L, (rr0 + 8) * 68 + (cc >> 1), D[t2][2] + b0, D[t2][3] + b1);
            }
        }
    }
    __syncthreads();

    // t1 = silu(ho @ Wn1 + bn1) -> miF (f32)
    stage_W(g_wfrag + 13 * 16384, WF, tid); CP_WAIT0(); __syncthreads();
    {
        float D[2][4] = {};
        gemm_mma2n(M1H, M1L, 68, WF, rtn * 16, ntbN, lane, kt0, kt1, D);
        if (reduce_kh(D, scrF, kh, rtn, ntp, lane)) {
            #pragma unroll
            for (int t2 = 0; t2 < 2; t2++) {
                int cc = (ntbN + t2) * 8 + 2 * tig;
                float b0 = bn1[cc], b1 = bn1[cc + 1];
                *(float2*)&miF[rr0 * 132 + cc] =
                    make_float2(silu_f(D[t2][0] + b0), silu_f(D[t2][1] + b1));
                *(float2*)&miF[(rr0 + 8) * 132 + cc] =
                    make_float2(silu_f(D[t2][2] + b0), silu_f(D[t2][3] + b1));
            }
        }
    }
    __syncthreads();

    // ---- out[b] = (colsum t1) . Wn2 + 32*bn2 ----
    float part = 0.0f;
    if (tid < 128) {
        int c = tid;
        float s = 0.0f;
        #pragma unroll 1
        for (int i = 0; i < 32; i++) s += miF[i * 132 + c];
        part = s * Wn2[c];
    }
    #pragma unroll
    for (int off = 16; off > 0; off >>= 1)
        part += __shfl_down_sync(0xffffffffu, part, off);
    if (warp < 4 && lane == 0) s_red[warp] = part;
    __syncthreads();
    if (tid == 0)
        g_out[b] = s_red[0] + s_red[1] + s_red[2] + s_red[3] + 32.0f * bn2[0];
}

extern "C" void kernel_launch(void* const* d_in, const int* in_sizes, int n_in,
                              void* d_out, int out_size) {
    const float* g_h   = (const float*)d_in[0];
    const float* g_x   = (const float*)d_in[1];
    const float* W_in  = (const float*)d_in[3];
    const float* b_in  = (const float*)d_in[4];
    const float* We1   = (const float*)d_in[5];
    const float* be1   = (const float*)d_in[6];
    const float* We2   = (const float*)d_in[7];
    const float* be2   = (const float*)d_in[8];
    const float* Wh1   = (const float*)d_in[9];
    const float* bh1   = (const float*)d_in[10];
    const float* Wh2   = (const float*)d_in[11];
    const float* bh2   = (const float*)d_in[12];
    const float* W_out = (const float*)d_in[13];
    const float* b_out = (const float*)d_in[14];
    const float* Wn1   = (const float*)d_in[15];
    const float* bn1   = (const float*)d_in[16];
    const float* Wn2   = (const float*)d_in[17];
    const float* bn2   = (const float*)d_in[18];
    float* out = (float*)d_out;

    prep_kernel<<<dim3(32, 15), 256>>>(We1, We2, Wh1, Wh2, W_out, Wn1, W_in);

    const int smem_bytes = SM_WORDS * 4;
    cudaFuncSetAttribute(sake_kernel, cudaFuncAttributeMaxDynamicSharedMemorySize,
                         smem_bytes);
    sake_kernel<<<NB, NT, smem_bytes>>>(
        g_h, g_x, b_in, We1, be1, be2, bh1, bh2, b_out, bn1, Wn2, bn2, out);
}